// round 1
// baseline (speedup 1.0000x reference)
#include <cuda_runtime.h>
#include <cstdint>

#define N_NODES 20000
#define N_EDGES 320000
#define NEG_INF __int_as_float(0xff800000)

// ---------------- scratch (device globals; no allocation allowed) ----------
__device__ float g_xl[N_NODES * 1024];    // x @ W (per-head features), reused both layers
__device__ float g_h1[N_NODES * 1024];    // layer1 output (residual + aggregated)
__device__ float g_agg[N_NODES * 1024];   // layer2 aggregation buffer
__device__ float g_h2[N_NODES * 256];     // layer2 output
__device__ float g_fc1[N_NODES * 256];
__device__ float g_fc2[N_NODES * 256];
__device__ float g_asrc[N_NODES * 4];
__device__ float g_adst[N_NODES * 4];
__device__ float g_e[N_EDGES * 4];        // edge logits, then exp values
__device__ float g_emax[N_NODES * 4];
__device__ float g_denom[N_NODES * 4];

// ---------------- helpers ---------------------------------------------------
__device__ __forceinline__ void redAdd4(float* addr, float4 v) {
    asm volatile("red.global.add.v4.f32 [%0], {%1, %2, %3, %4};"
                 :: "l"(addr), "f"(v.x), "f"(v.y), "f"(v.z), "f"(v.w) : "memory");
}

__device__ __forceinline__ void atomicMaxFloat(float* addr, float v) {
    if (v >= 0.0f) {
        atomicMax((int*)addr, __float_as_int(v));
    } else {
        atomicMin((unsigned int*)addr, (unsigned int)__float_as_int(v));
    }
}

// ---------------- SGEMM: C[M,N] = A[M,K] @ B[K,N] (+bias, +act) -------------
// BM=128 BN=128 BK=8, 256 threads, 8x8 per thread. N,K multiples of 128/8; M guarded.
#define BM 128
#define BN 128
#define BK 8
#define TM 8
#define TN 8

template <int ACT>  // 0: none, 1: leaky_relu(0.01)
__global__ __launch_bounds__(256) void sgemm_kernel(
    const float* __restrict__ A, const float* __restrict__ B,
    const float* __restrict__ bias, float* __restrict__ C,
    int M, int N, int K)
{
    __shared__ float As[BK][BM];
    __shared__ float Bs[BK][BN];

    const int tid = threadIdx.x;
    const int bm = blockIdx.y, bn = blockIdx.x;

    const int rowA = tid >> 1;            // 0..127
    const int colA = (tid & 1) * 4;       // 0 or 4
    const int rowB = tid >> 5;            // 0..7
    const int colB = (tid & 31) * 4;      // 0..124
    const int tx = tid & 15, ty = tid >> 4;

    float acc[TM][TN];
    #pragma unroll
    for (int i = 0; i < TM; i++)
        #pragma unroll
        for (int j = 0; j < TN; j++) acc[i][j] = 0.0f;

    const bool aval = (bm * BM + rowA) < M;
    const float* Aptr = A + (size_t)(bm * BM + rowA) * K + colA;
    const float* Bptr = B + (size_t)rowB * N + bn * BN + colB;

    for (int k0 = 0; k0 < K; k0 += BK) {
        float4 av = aval ? *(const float4*)(Aptr + k0) : make_float4(0.f, 0.f, 0.f, 0.f);
        As[colA + 0][rowA] = av.x;
        As[colA + 1][rowA] = av.y;
        As[colA + 2][rowA] = av.z;
        As[colA + 3][rowA] = av.w;
        *(float4*)&Bs[rowB][colB] = *(const float4*)(Bptr + (size_t)k0 * N);
        __syncthreads();

        #pragma unroll
        for (int kk = 0; kk < BK; kk++) {
            float4 a0 = *(const float4*)&As[kk][ty * TM];
            float4 a1 = *(const float4*)&As[kk][ty * TM + 4];
            float4 b0 = *(const float4*)&Bs[kk][tx * TN];
            float4 b1 = *(const float4*)&Bs[kk][tx * TN + 4];
            float ra[TM] = {a0.x, a0.y, a0.z, a0.w, a1.x, a1.y, a1.z, a1.w};
            float rb[TN] = {b0.x, b0.y, b0.z, b0.w, b1.x, b1.y, b1.z, b1.w};
            #pragma unroll
            for (int i = 0; i < TM; i++)
                #pragma unroll
                for (int j = 0; j < TN; j++) acc[i][j] += ra[i] * rb[j];
        }
        __syncthreads();
    }

    float bv[TN];
    #pragma unroll
    for (int j = 0; j < TN; j++)
        bv[j] = bias ? bias[bn * BN + tx * TN + j] : 0.0f;

    #pragma unroll
    for (int i = 0; i < TM; i++) {
        int row = bm * BM + ty * TM + i;
        if (row >= M) continue;
        float* Crow = C + (size_t)row * N + bn * BN + tx * TN;
        #pragma unroll
        for (int j0 = 0; j0 < TN; j0 += 4) {
            float4 v;
            v.x = acc[i][j0 + 0] + bv[j0 + 0];
            v.y = acc[i][j0 + 1] + bv[j0 + 1];
            v.z = acc[i][j0 + 2] + bv[j0 + 2];
            v.w = acc[i][j0 + 3] + bv[j0 + 3];
            if (ACT == 1) {
                v.x = v.x > 0.f ? v.x : 0.01f * v.x;
                v.y = v.y > 0.f ? v.y : 0.01f * v.y;
                v.z = v.z > 0.f ? v.z : 0.01f * v.z;
                v.w = v.w > 0.f ? v.w : 0.01f * v.w;
            }
            *(float4*)(Crow + j0) = v;
        }
    }
}

// ---------------- attention scores: a_src/a_dst [N,4] ------------------------
// one warp per (node, head); lane covers 8 contiguous channels
__global__ __launch_bounds__(256) void attn_scores_kernel(
    const float* __restrict__ xl,
    const float* __restrict__ att_src, const float* __restrict__ att_dst,
    float* __restrict__ asrc, float* __restrict__ adst)
{
    int task = blockIdx.x * 8 + (threadIdx.x >> 5);
    if (task >= N_NODES * 4) return;
    int lane = threadIdx.x & 31;
    int n = task >> 2, h = task & 3;

    const float* xp = xl + (size_t)n * 1024 + h * 256 + lane * 8;
    const float* sp = att_src + h * 256 + lane * 8;
    const float* dp = att_dst + h * 256 + lane * 8;

    float s1 = 0.f, s2 = 0.f;
    #pragma unroll
    for (int q = 0; q < 8; q += 4) {
        float4 v = *(const float4*)(xp + q);
        float4 a = *(const float4*)(sp + q);
        float4 b = *(const float4*)(dp + q);
        s1 += v.x * a.x + v.y * a.y + v.z * a.z + v.w * a.w;
        s2 += v.x * b.x + v.y * b.y + v.z * b.z + v.w * b.w;
    }
    #pragma unroll
    for (int off = 16; off > 0; off >>= 1) {
        s1 += __shfl_xor_sync(0xffffffffu, s1, off);
        s2 += __shfl_xor_sync(0xffffffffu, s2, off);
    }
    if (lane == 0) {
        asrc[task] = s1;
        adst[task] = s2;
    }
}

// ---------------- segment-softmax init --------------------------------------
__global__ void seg_init_kernel(float* __restrict__ emax, float* __restrict__ denom) {
    int i = blockIdx.x * blockDim.x + threadIdx.x;
    if (i < N_NODES * 4) {
        emax[i] = NEG_INF;
        denom[i] = 0.0f;
    }
}

// ---------------- pass A: edge logits + segment max -------------------------
__global__ __launch_bounds__(256) void edge_logits_kernel(
    const int* __restrict__ src, const int* __restrict__ dst,
    const float* __restrict__ asrc, const float* __restrict__ adst,
    float* __restrict__ e, float* __restrict__ emax)
{
    int i = blockIdx.x * blockDim.x + threadIdx.x;
    if (i >= N_EDGES) return;
    int s = src[i], d = dst[i];
    float4 as = *(const float4*)(asrc + s * 4);
    float4 ad = *(const float4*)(adst + d * 4);
    float4 ev;
    ev.x = as.x + ad.x; ev.x = ev.x > 0.f ? ev.x : 0.2f * ev.x;
    ev.y = as.y + ad.y; ev.y = ev.y > 0.f ? ev.y : 0.2f * ev.y;
    ev.z = as.z + ad.z; ev.z = ev.z > 0.f ? ev.z : 0.2f * ev.z;
    ev.w = as.w + ad.w; ev.w = ev.w > 0.f ? ev.w : 0.2f * ev.w;
    *(float4*)(e + (size_t)i * 4) = ev;
    atomicMaxFloat(&emax[d * 4 + 0], ev.x);
    atomicMaxFloat(&emax[d * 4 + 1], ev.y);
    atomicMaxFloat(&emax[d * 4 + 2], ev.z);
    atomicMaxFloat(&emax[d * 4 + 3], ev.w);
}

// ---------------- pass B: exp + segment sum ---------------------------------
__global__ __launch_bounds__(256) void edge_exp_kernel(
    const int* __restrict__ dst,
    float* __restrict__ e, const float* __restrict__ emax,
    float* __restrict__ denom)
{
    int i = blockIdx.x * blockDim.x + threadIdx.x;
    if (i >= N_EDGES) return;
    int d = dst[i];
    float4 ev = *(const float4*)(e + (size_t)i * 4);
    float4 mx = *(const float4*)(emax + d * 4);
    float4 ex;
    ex.x = __expf(ev.x - mx.x);
    ex.y = __expf(ev.y - mx.y);
    ex.z = __expf(ev.z - mx.z);
    ex.w = __expf(ev.w - mx.w);
    *(float4*)(e + (size_t)i * 4) = ex;
    redAdd4(denom + d * 4, ex);
}

// ---------------- pass C: weighted message scatter --------------------------
// one warp per (edge, head); lane handles 8 contiguous channels (2 x float4)
__global__ __launch_bounds__(256) void edge_aggregate_kernel(
    const int* __restrict__ src, const int* __restrict__ dst,
    const float* __restrict__ xl, const float* __restrict__ ex,
    const float* __restrict__ denom, float* __restrict__ out)
{
    long long task = (long long)blockIdx.x * 8 + (threadIdx.x >> 5);
    if (task >= (long long)N_EDGES * 4) return;
    int lane = threadIdx.x & 31;
    int e = (int)(task >> 2), h = (int)(task & 3);
    int s = src[e], d = dst[e];
    float alpha = ex[e * 4 + h] / (denom[d * 4 + h] + 1e-16f);

    const float* sp = xl + (size_t)s * 1024 + h * 256 + lane * 8;
    float* dp = out + (size_t)d * 1024 + h * 256 + lane * 8;
    float4 v0 = *(const float4*)(sp);
    float4 v1 = *(const float4*)(sp + 4);
    v0.x *= alpha; v0.y *= alpha; v0.z *= alpha; v0.w *= alpha;
    v1.x *= alpha; v1.y *= alpha; v1.z *= alpha; v1.w *= alpha;
    redAdd4(dp, v0);
    redAdd4(dp + 4, v1);
}

// ---------------- zero buffer ------------------------------------------------
__global__ void zero_kernel(float4* __restrict__ p, int n4) {
    int i = blockIdx.x * blockDim.x + threadIdx.x;
    if (i < n4) p[i] = make_float4(0.f, 0.f, 0.f, 0.f);
}

// ---------------- layer2 head-mean combine ----------------------------------
__global__ void mean_combine_kernel(const float* __restrict__ agg, float* __restrict__ h2) {
    int idx = blockIdx.x * blockDim.x + threadIdx.x;
    if (idx >= N_NODES * 256) return;
    int n = idx >> 8, c = idx & 255;
    const float* a = agg + (size_t)n * 1024 + c;
    h2[idx] += 0.25f * (a[0] + a[256] + a[512] + a[768]);
}

// ---------------- output heads ----------------------------------------------
// one warp per node; 7 outputs (2 depression + 5 severity)
__global__ __launch_bounds__(256) void heads_kernel(
    const float* __restrict__ fc,
    const float* __restrict__ Wb, const float* __restrict__ bb,
    const float* __restrict__ Ws, const float* __restrict__ bs,
    float* __restrict__ out)
{
    int n = blockIdx.x * 8 + (threadIdx.x >> 5);
    if (n >= N_NODES) return;
    int lane = threadIdx.x & 31;

    float acc[7] = {0.f, 0.f, 0.f, 0.f, 0.f, 0.f, 0.f};
    #pragma unroll
    for (int i = 0; i < 8; i++) {
        int k = i * 32 + lane;
        float v = fc[(size_t)n * 256 + k];
        acc[0] += v * Wb[k * 2 + 0];
        acc[1] += v * Wb[k * 2 + 1];
        #pragma unroll
        for (int j = 0; j < 5; j++) acc[2 + j] += v * Ws[k * 5 + j];
    }
    #pragma unroll
    for (int off = 16; off > 0; off >>= 1) {
        #pragma unroll
        for (int j = 0; j < 7; j++) acc[j] += __shfl_xor_sync(0xffffffffu, acc[j], off);
    }
    if (lane == 0) {
        out[(size_t)n * 2 + 0] = acc[0] + bb[0];
        out[(size_t)n * 2 + 1] = acc[1] + bb[1];
        float* sev = out + (size_t)N_NODES * 2 + (size_t)n * 5;
        #pragma unroll
        for (int j = 0; j < 5; j++) sev[j] = acc[2 + j] + bs[j];
    }
}

// ---------------- launch ------------------------------------------------------
static inline void run_gat_layer(
    const float* feat_in, int in_dim,
    const float* W, const float* att_src, const float* att_dst,
    const int* src, const int* dst,
    float* xl, float* out_accum)
{
    // xl = feat_in @ W  [N, 1024]
    {
        dim3 grid(1024 / BN, (N_NODES + BM - 1) / BM);
        sgemm_kernel<0><<<grid, 256>>>(feat_in, W, nullptr, xl, N_NODES, 1024, in_dim);
    }
    attn_scores_kernel<<<(N_NODES * 4 + 7) / 8, 256>>>(xl, att_src, att_dst, g_asrc, g_adst);
    seg_init_kernel<<<(N_NODES * 4 + 255) / 256, 256>>>(g_emax, g_denom);
    edge_logits_kernel<<<(N_EDGES + 255) / 256, 256>>>(src, dst, g_asrc, g_adst, g_e, g_emax);
    edge_exp_kernel<<<(N_EDGES + 255) / 256, 256>>>(dst, g_e, g_emax, g_denom);
    edge_aggregate_kernel<<<(N_EDGES * 4 + 7) / 8, 256>>>(src, dst, xl, g_e, g_denom, out_accum);
}

extern "C" void kernel_launch(void* const* d_in, const int* in_sizes, int n_in,
                              void* d_out, int out_size)
{
    const float* x        = (const float*)d_in[0];
    const int*   ei       = (const int*)d_in[1];
    const float* W1       = (const float*)d_in[2];
    const float* att_src1 = (const float*)d_in[3];
    const float* att_dst1 = (const float*)d_in[4];
    const float* Wres1    = (const float*)d_in[5];
    const float* b1       = (const float*)d_in[6];
    const float* W2       = (const float*)d_in[7];
    const float* att_src2 = (const float*)d_in[8];
    const float* att_dst2 = (const float*)d_in[9];
    const float* Wres2    = (const float*)d_in[10];
    const float* b2       = (const float*)d_in[11];
    const float* Wfc      = (const float*)d_in[12];
    const float* bfc      = (const float*)d_in[13];
    const float* Wb       = (const float*)d_in[14];
    const float* bb       = (const float*)d_in[15];
    const float* Ws       = (const float*)d_in[16];
    const float* bs       = (const float*)d_in[17];
    float* out = (float*)d_out;

    const int* src = ei;
    const int* dst = ei + N_EDGES;

    float *xl, *h1, *agg, *h2, *fc1, *fc2;
    cudaGetSymbolAddress((void**)&xl,  g_xl);
    cudaGetSymbolAddress((void**)&h1,  g_h1);
    cudaGetSymbolAddress((void**)&agg, g_agg);
    cudaGetSymbolAddress((void**)&h2,  g_h2);
    cudaGetSymbolAddress((void**)&fc1, g_fc1);
    cudaGetSymbolAddress((void**)&fc2, g_fc2);

    const int mRows = (N_NODES + BM - 1) / BM;

    // ===== layer 1 (concat=true): h1 = agg + x@Wres1 + b1 =====
    {
        dim3 grid(1024 / BN, mRows);
        sgemm_kernel<0><<<grid, 256>>>(x, Wres1, b1, h1, N_NODES, 1024, 768);
    }
    run_gat_layer(x, 768, W1, att_src1, att_dst1, src, dst, xl, h1);

    // ===== layer 2 (concat=false): h2 = mean_heads(agg) + h1@Wres2 + b2 =====
    {
        dim3 grid(256 / BN, mRows);
        sgemm_kernel<0><<<grid, 256>>>(h1, Wres2, b2, h2, N_NODES, 256, 1024);
    }
    zero_kernel<<<(N_NODES * 1024 / 4 + 255) / 256, 256>>>((float4*)agg, N_NODES * 1024 / 4);
    run_gat_layer(h1, 1024, W2, att_src2, att_dst2, src, dst, xl, agg);
    mean_combine_kernel<<<(N_NODES * 256 + 255) / 256, 256>>>(agg, h2);

    // ===== shared FC twice =====
    {
        dim3 grid(256 / BN, mRows);
        sgemm_kernel<1><<<grid, 256>>>(h2, Wfc, bfc, fc1, N_NODES, 256, 256);
        sgemm_kernel<0><<<grid, 256>>>(fc1, Wfc, bfc, fc2, N_NODES, 256, 256);
    }

    // ===== heads =====
    heads_kernel<<<(N_NODES + 7) / 8, 256>>>(fc2, Wb, bb, Ws, bs, out);
}

// round 2
// speedup vs baseline: 1.5473x; 1.5473x over previous
#include <cuda_runtime.h>
#include <cstdint>

#define N_NODES 20000
#define N_EDGES 320000
#define NEG_INF __int_as_float(0xff800000)

// ---------------- scratch (device globals; no allocation allowed) ----------
__device__ float g_xl[N_NODES * 1024];
__device__ float g_h1[N_NODES * 1024];
__device__ float g_agg[N_NODES * 1024];
__device__ float g_h2[N_NODES * 256];
__device__ float g_fc1[N_NODES * 256];
__device__ float g_fc2[N_NODES * 256];
__device__ float g_asrc[N_NODES * 4];
__device__ float g_adst[N_NODES * 4];
__device__ float g_e[N_EDGES * 4];
__device__ float g_emax[N_NODES * 4];
__device__ float g_denom[N_NODES * 4];

// ---------------- helpers ---------------------------------------------------
__device__ __forceinline__ void redAdd4(float* addr, float4 v) {
    asm volatile("red.global.add.v4.f32 [%0], {%1, %2, %3, %4};"
                 :: "l"(addr), "f"(v.x), "f"(v.y), "f"(v.z), "f"(v.w) : "memory");
}

__device__ __forceinline__ void atomicMaxFloat(float* addr, float v) {
    if (v >= 0.0f) {
        atomicMax((int*)addr, __float_as_int(v));
    } else {
        atomicMin((unsigned int*)addr, (unsigned int)__float_as_int(v));
    }
}

__device__ __forceinline__ unsigned f2tf32(float x) {
    unsigned r;
    asm("cvt.rna.tf32.f32 %0, %1;" : "=r"(r) : "f"(x));
    return r;
}

__device__ __forceinline__ void mma_tf32(float* d, const unsigned* a, const unsigned* b) {
    asm volatile(
        "mma.sync.aligned.m16n8k8.row.col.f32.tf32.tf32.f32 "
        "{%0,%1,%2,%3}, {%4,%5,%6,%7}, {%8,%9}, {%0,%1,%2,%3};"
        : "+f"(d[0]), "+f"(d[1]), "+f"(d[2]), "+f"(d[3])
        : "r"(a[0]), "r"(a[1]), "r"(a[2]), "r"(a[3]), "r"(b[0]), "r"(b[1]));
}

// ---------------- tf32 tensor-core GEMM -------------------------------------
// C[M,N] = A[M,K] @ B[K,N] (+bias, +act). BM=BN=128, BK=16.
// 128 threads, 4 warps in 2x2, warp tile 64x64 (4 m-tiles x 8 n-tiles of m16n8k8).
// Requires N % 128 == 0, K % 16 == 0; M guarded.
#define GBM 128
#define GBN 128
#define GBK 16
#define ASTR (GBK + 4)    // 20 floats  -> conflict-free A fragment reads
#define BSTR (GBN + 8)    // 136 floats -> conflict-free B fragment reads

template <int ACT>  // 0: none, 1: leaky_relu(0.01)
__global__ __launch_bounds__(128) void mma_gemm_kernel(
    const float* __restrict__ A, const float* __restrict__ B,
    const float* __restrict__ bias, float* __restrict__ C,
    int M, int N, int K)
{
    __shared__ unsigned As[GBM * ASTR];
    __shared__ unsigned Bs[GBK * BSTR];

    const int tid = threadIdx.x;
    const int warp = tid >> 5, lane = tid & 31;
    const int g = lane >> 2, tg = lane & 3;
    const int wr = (warp >> 1) * 64;   // warp row base within tile
    const int wc = (warp & 1) * 64;    // warp col base within tile

    const int bm = blockIdx.y, bn = blockIdx.x;

    // A staging: thread t owns row t of the 128x16 tile (4 x float4)
    const int rowA = bm * GBM + tid;
    const bool avalid = rowA < M;
    const float* Ap = A + (size_t)rowA * K;

    // B staging: kb = tid>>3 (0..15), jb = tid&7; 4 chunks of 32 cols
    const int kb = tid >> 3, jb = tid & 7;
    const float* Bp = B + (size_t)kb * N + bn * GBN + jb * 4;

    float acc[4][8][4];
    #pragma unroll
    for (int mt = 0; mt < 4; mt++)
        #pragma unroll
        for (int nt = 0; nt < 8; nt++)
            #pragma unroll
            for (int i = 0; i < 4; i++) acc[mt][nt][i] = 0.0f;

    float4 aReg[4];
    float4 bReg[4];

    // prologue: stage tile k0=0
    #pragma unroll
    for (int q = 0; q < 4; q++)
        aReg[q] = avalid ? *(const float4*)(Ap + q * 4) : make_float4(0.f, 0.f, 0.f, 0.f);
    #pragma unroll
    for (int it = 0; it < 4; it++)
        bReg[it] = *(const float4*)(Bp + it * 32);

    for (int k0 = 0; k0 < K; k0 += GBK) {
        __syncthreads();  // previous compute done reading smem

        // store staged tile (tf32-converted) to smem
        #pragma unroll
        for (int q = 0; q < 4; q++) {
            uint4 u;
            u.x = f2tf32(aReg[q].x); u.y = f2tf32(aReg[q].y);
            u.z = f2tf32(aReg[q].z); u.w = f2tf32(aReg[q].w);
            *(uint4*)&As[tid * ASTR + q * 4] = u;
        }
        #pragma unroll
        for (int it = 0; it < 4; it++) {
            uint4 u;
            u.x = f2tf32(bReg[it].x); u.y = f2tf32(bReg[it].y);
            u.z = f2tf32(bReg[it].z); u.w = f2tf32(bReg[it].w);
            *(uint4*)&Bs[kb * BSTR + jb * 4 + it * 32] = u;
        }
        __syncthreads();

        // stage next tile (overlaps with MMA below)
        int kn = k0 + GBK;
        if (kn < K) {
            #pragma unroll
            for (int q = 0; q < 4; q++)
                aReg[q] = avalid ? *(const float4*)(Ap + kn + q * 4)
                                 : make_float4(0.f, 0.f, 0.f, 0.f);
            #pragma unroll
            for (int it = 0; it < 4; it++)
                bReg[it] = *(const float4*)(Bp + (size_t)kn * N + it * 32);
        }

        // compute: 2 k-steps of 8
        #pragma unroll
        for (int kk = 0; kk < 2; kk++) {
            unsigned af[4][4];
            unsigned bf[8][2];
            #pragma unroll
            for (int mt = 0; mt < 4; mt++) {
                int r0 = wr + mt * 16 + g;
                af[mt][0] = As[(r0    ) * ASTR + kk * 8 + tg];
                af[mt][1] = As[(r0 + 8) * ASTR + kk * 8 + tg];
                af[mt][2] = As[(r0    ) * ASTR + kk * 8 + tg + 4];
                af[mt][3] = As[(r0 + 8) * ASTR + kk * 8 + tg + 4];
            }
            #pragma unroll
            for (int nt = 0; nt < 8; nt++) {
                bf[nt][0] = Bs[(kk * 8 + tg    ) * BSTR + wc + nt * 8 + g];
                bf[nt][1] = Bs[(kk * 8 + tg + 4) * BSTR + wc + nt * 8 + g];
            }
            #pragma unroll
            for (int mt = 0; mt < 4; mt++)
                #pragma unroll
                for (int nt = 0; nt < 8; nt++)
                    mma_tf32(acc[mt][nt], af[mt], bf[nt]);
        }
    }

    // epilogue
    float bv[8][2];
    #pragma unroll
    for (int nt = 0; nt < 8; nt++) {
        int col = bn * GBN + wc + nt * 8 + 2 * tg;
        bv[nt][0] = bias ? bias[col] : 0.0f;
        bv[nt][1] = bias ? bias[col + 1] : 0.0f;
    }

    #pragma unroll
    for (int mt = 0; mt < 4; mt++) {
        #pragma unroll
        for (int i = 0; i < 2; i++) {
            int row = bm * GBM + wr + mt * 16 + g + i * 8;
            if (row >= M) continue;
            float* Crow = C + (size_t)row * N + bn * GBN + wc;
            #pragma unroll
            for (int nt = 0; nt < 8; nt++) {
                float2 v;
                v.x = acc[mt][nt][i * 2 + 0] + bv[nt][0];
                v.y = acc[mt][nt][i * 2 + 1] + bv[nt][1];
                if (ACT == 1) {
                    v.x = v.x > 0.f ? v.x : 0.01f * v.x;
                    v.y = v.y > 0.f ? v.y : 0.01f * v.y;
                }
                *(float2*)(Crow + nt * 8 + 2 * tg) = v;
            }
        }
    }
}

// ---------------- attention scores: a_src/a_dst [N,4] ------------------------
__global__ __launch_bounds__(256) void attn_scores_kernel(
    const float* __restrict__ xl,
    const float* __restrict__ att_src, const float* __restrict__ att_dst,
    float* __restrict__ asrc, float* __restrict__ adst)
{
    int task = blockIdx.x * 8 + (threadIdx.x >> 5);
    if (task >= N_NODES * 4) return;
    int lane = threadIdx.x & 31;
    int n = task >> 2, h = task & 3;

    const float* xp = xl + (size_t)n * 1024 + h * 256 + lane * 8;
    const float* sp = att_src + h * 256 + lane * 8;
    const float* dp = att_dst + h * 256 + lane * 8;

    float s1 = 0.f, s2 = 0.f;
    #pragma unroll
    for (int q = 0; q < 8; q += 4) {
        float4 v = *(const float4*)(xp + q);
        float4 a = *(const float4*)(sp + q);
        float4 b = *(const float4*)(dp + q);
        s1 += v.x * a.x + v.y * a.y + v.z * a.z + v.w * a.w;
        s2 += v.x * b.x + v.y * b.y + v.z * b.z + v.w * b.w;
    }
    #pragma unroll
    for (int off = 16; off > 0; off >>= 1) {
        s1 += __shfl_xor_sync(0xffffffffu, s1, off);
        s2 += __shfl_xor_sync(0xffffffffu, s2, off);
    }
    if (lane == 0) {
        asrc[task] = s1;
        adst[task] = s2;
    }
}

// ---------------- segment-softmax init --------------------------------------
__global__ void seg_init_kernel(float* __restrict__ emax, float* __restrict__ denom) {
    int i = blockIdx.x * blockDim.x + threadIdx.x;
    if (i < N_NODES * 4) {
        emax[i] = NEG_INF;
        denom[i] = 0.0f;
    }
}

// ---------------- pass A: edge logits + segment max -------------------------
__global__ __launch_bounds__(256) void edge_logits_kernel(
    const int* __restrict__ src, const int* __restrict__ dst,
    const float* __restrict__ asrc, const float* __restrict__ adst,
    float* __restrict__ e, float* __restrict__ emax)
{
    int i = blockIdx.x * blockDim.x + threadIdx.x;
    if (i >= N_EDGES) return;
    int s = src[i], d = dst[i];
    float4 as = *(const float4*)(asrc + s * 4);
    float4 ad = *(const float4*)(adst + d * 4);
    float4 ev;
    ev.x = as.x + ad.x; ev.x = ev.x > 0.f ? ev.x : 0.2f * ev.x;
    ev.y = as.y + ad.y; ev.y = ev.y > 0.f ? ev.y : 0.2f * ev.y;
    ev.z = as.z + ad.z; ev.z = ev.z > 0.f ? ev.z : 0.2f * ev.z;
    ev.w = as.w + ad.w; ev.w = ev.w > 0.f ? ev.w : 0.2f * ev.w;
    *(float4*)(e + (size_t)i * 4) = ev;
    atomicMaxFloat(&emax[d * 4 + 0], ev.x);
    atomicMaxFloat(&emax[d * 4 + 1], ev.y);
    atomicMaxFloat(&emax[d * 4 + 2], ev.z);
    atomicMaxFloat(&emax[d * 4 + 3], ev.w);
}

// ---------------- pass B: exp + segment sum ---------------------------------
__global__ __launch_bounds__(256) void edge_exp_kernel(
    const int* __restrict__ dst,
    float* __restrict__ e, const float* __restrict__ emax,
    float* __restrict__ denom)
{
    int i = blockIdx.x * blockDim.x + threadIdx.x;
    if (i >= N_EDGES) return;
    int d = dst[i];
    float4 ev = *(const float4*)(e + (size_t)i * 4);
    float4 mx = *(const float4*)(emax + d * 4);
    float4 ex;
    ex.x = __expf(ev.x - mx.x);
    ex.y = __expf(ev.y - mx.y);
    ex.z = __expf(ev.z - mx.z);
    ex.w = __expf(ev.w - mx.w);
    *(float4*)(e + (size_t)i * 4) = ex;
    redAdd4(denom + d * 4, ex);
}

// ---------------- pass C: weighted message scatter --------------------------
__global__ __launch_bounds__(256) void edge_aggregate_kernel(
    const int* __restrict__ src, const int* __restrict__ dst,
    const float* __restrict__ xl, const float* __restrict__ ex,
    const float* __restrict__ denom, float* __restrict__ out)
{
    long long task = (long long)blockIdx.x * 8 + (threadIdx.x >> 5);
    if (task >= (long long)N_EDGES * 4) return;
    int lane = threadIdx.x & 31;
    int e = (int)(task >> 2), h = (int)(task & 3);
    int s = src[e], d = dst[e];
    float alpha = ex[e * 4 + h] / (denom[d * 4 + h] + 1e-16f);

    const float* sp = xl + (size_t)s * 1024 + h * 256 + lane * 8;
    float* dp = out + (size_t)d * 1024 + h * 256 + lane * 8;
    float4 v0 = *(const float4*)(sp);
    float4 v1 = *(const float4*)(sp + 4);
    v0.x *= alpha; v0.y *= alpha; v0.z *= alpha; v0.w *= alpha;
    v1.x *= alpha; v1.y *= alpha; v1.z *= alpha; v1.w *= alpha;
    redAdd4(dp, v0);
    redAdd4(dp + 4, v1);
}

// ---------------- zero buffer ------------------------------------------------
__global__ void zero_kernel(float4* __restrict__ p, int n4) {
    int i = blockIdx.x * blockDim.x + threadIdx.x;
    if (i < n4) p[i] = make_float4(0.f, 0.f, 0.f, 0.f);
}

// ---------------- layer2 head-mean combine ----------------------------------
__global__ void mean_combine_kernel(const float* __restrict__ agg, float* __restrict__ h2) {
    int idx = blockIdx.x * blockDim.x + threadIdx.x;
    if (idx >= N_NODES * 256) return;
    int n = idx >> 8, c = idx & 255;
    const float* a = agg + (size_t)n * 1024 + c;
    h2[idx] += 0.25f * (a[0] + a[256] + a[512] + a[768]);
}

// ---------------- output heads ----------------------------------------------
__global__ __launch_bounds__(256) void heads_kernel(
    const float* __restrict__ fc,
    const float* __restrict__ Wb, const float* __restrict__ bb,
    const float* __restrict__ Ws, const float* __restrict__ bs,
    float* __restrict__ out)
{
    int n = blockIdx.x * 8 + (threadIdx.x >> 5);
    if (n >= N_NODES) return;
    int lane = threadIdx.x & 31;

    float acc[7] = {0.f, 0.f, 0.f, 0.f, 0.f, 0.f, 0.f};
    #pragma unroll
    for (int i = 0; i < 8; i++) {
        int k = i * 32 + lane;
        float v = fc[(size_t)n * 256 + k];
        acc[0] += v * Wb[k * 2 + 0];
        acc[1] += v * Wb[k * 2 + 1];
        #pragma unroll
        for (int j = 0; j < 5; j++) acc[2 + j] += v * Ws[k * 5 + j];
    }
    #pragma unroll
    for (int off = 16; off > 0; off >>= 1) {
        #pragma unroll
        for (int j = 0; j < 7; j++) acc[j] += __shfl_xor_sync(0xffffffffu, acc[j], off);
    }
    if (lane == 0) {
        out[(size_t)n * 2 + 0] = acc[0] + bb[0];
        out[(size_t)n * 2 + 1] = acc[1] + bb[1];
        float* sev = out + (size_t)N_NODES * 2 + (size_t)n * 5;
        #pragma unroll
        for (int j = 0; j < 5; j++) sev[j] = acc[2 + j] + bs[j];
    }
}

// ---------------- launch ------------------------------------------------------
static inline void run_gat_layer(
    const float* feat_in, int in_dim,
    const float* W, const float* att_src, const float* att_dst,
    const int* src, const int* dst,
    float* xl, float* out_accum)
{
    {
        dim3 grid(1024 / GBN, (N_NODES + GBM - 1) / GBM);
        mma_gemm_kernel<0><<<grid, 128>>>(feat_in, W, nullptr, xl, N_NODES, 1024, in_dim);
    }
    attn_scores_kernel<<<(N_NODES * 4 + 7) / 8, 256>>>(xl, att_src, att_dst, g_asrc, g_adst);
    seg_init_kernel<<<(N_NODES * 4 + 255) / 256, 256>>>(g_emax, g_denom);
    edge_logits_kernel<<<(N_EDGES + 255) / 256, 256>>>(src, dst, g_asrc, g_adst, g_e, g_emax);
    edge_exp_kernel<<<(N_EDGES + 255) / 256, 256>>>(dst, g_e, g_emax, g_denom);
    edge_aggregate_kernel<<<(N_EDGES * 4 + 7) / 8, 256>>>(src, dst, xl, g_e, g_denom, out_accum);
}

extern "C" void kernel_launch(void* const* d_in, const int* in_sizes, int n_in,
                              void* d_out, int out_size)
{
    const float* x        = (const float*)d_in[0];
    const int*   ei       = (const int*)d_in[1];
    const float* W1       = (const float*)d_in[2];
    const float* att_src1 = (const float*)d_in[3];
    const float* att_dst1 = (const float*)d_in[4];
    const float* Wres1    = (const float*)d_in[5];
    const float* b1       = (const float*)d_in[6];
    const float* W2       = (const float*)d_in[7];
    const float* att_src2 = (const float*)d_in[8];
    const float* att_dst2 = (const float*)d_in[9];
    const float* Wres2    = (const float*)d_in[10];
    const float* b2       = (const float*)d_in[11];
    const float* Wfc      = (const float*)d_in[12];
    const float* bfc      = (const float*)d_in[13];
    const float* Wb       = (const float*)d_in[14];
    const float* bb       = (const float*)d_in[15];
    const float* Ws       = (const float*)d_in[16];
    const float* bs       = (const float*)d_in[17];
    float* out = (float*)d_out;

    const int* src = ei;
    const int* dst = ei + N_EDGES;

    float *xl, *h1, *agg, *h2, *fc1, *fc2;
    cudaGetSymbolAddress((void**)&xl,  g_xl);
    cudaGetSymbolAddress((void**)&h1,  g_h1);
    cudaGetSymbolAddress((void**)&agg, g_agg);
    cudaGetSymbolAddress((void**)&h2,  g_h2);
    cudaGetSymbolAddress((void**)&fc1, g_fc1);
    cudaGetSymbolAddress((void**)&fc2, g_fc2);

    const int mRows = (N_NODES + GBM - 1) / GBM;

    // ===== layer 1 (concat=true): h1 = agg + x@Wres1 + b1 =====
    {
        dim3 grid(1024 / GBN, mRows);
        mma_gemm_kernel<0><<<grid, 128>>>(x, Wres1, b1, h1, N_NODES, 1024, 768);
    }
    run_gat_layer(x, 768, W1, att_src1, att_dst1, src, dst, xl, h1);

    // ===== layer 2 (concat=false): h2 = mean_heads(agg) + h1@Wres2 + b2 =====
    {
        dim3 grid(256 / GBN, mRows);
        mma_gemm_kernel<0><<<grid, 128>>>(h1, Wres2, b2, h2, N_NODES, 256, 1024);
    }
    zero_kernel<<<(N_NODES * 1024 / 4 + 255) / 256, 256>>>((float4*)agg, N_NODES * 1024 / 4);
    run_gat_layer(h1, 1024, W2, att_src2, att_dst2, src, dst, xl, agg);
    mean_combine_kernel<<<(N_NODES * 256 + 255) / 256, 256>>>(agg, h2);

    // ===== shared FC twice =====
    {
        dim3 grid(256 / GBN, mRows);
        mma_gemm_kernel<1><<<grid, 128>>>(h2, Wfc, bfc, fc1, N_NODES, 256, 256);
        mma_gemm_kernel<0><<<grid, 128>>>(fc1, Wfc, bfc, fc2, N_NODES, 256, 256);
    }

    // ===== heads =====
    heads_kernel<<<(N_NODES + 7) / 8, 256>>>(fc2, Wb, bb, Ws, bs, out);
}

// round 3
// speedup vs baseline: 3.0659x; 1.9814x over previous
#include <cuda_runtime.h>
#include <cstdint>

#define N_NODES 20000
#define N_EDGES 320000
#define NEG_INF __int_as_float(0xff800000)

// ---------------- scratch (device globals; no allocation allowed) ----------
__device__ float g_xl[N_NODES * 1024];
__device__ float g_h1[N_NODES * 1024];
__device__ float g_h2[N_NODES * 256];
__device__ float g_fc1[N_NODES * 256];
__device__ float g_fc2[N_NODES * 256];
__device__ float g_asrc[N_NODES * 4];
__device__ float g_adst[N_NODES * 4];
__device__ float g_e[N_EDGES * 4];
__device__ float g_emax[N_NODES * 4];
__device__ float g_denom[N_NODES * 4];

// ---------------- helpers ---------------------------------------------------
__device__ __forceinline__ void redAdd4(float* addr, float4 v) {
    asm volatile("red.global.add.v4.f32 [%0], {%1, %2, %3, %4};"
                 :: "l"(addr), "f"(v.x), "f"(v.y), "f"(v.z), "f"(v.w) : "memory");
}

__device__ __forceinline__ void atomicMaxFloat(float* addr, float v) {
    if (v >= 0.0f) {
        atomicMax((int*)addr, __float_as_int(v));
    } else {
        atomicMin((unsigned int*)addr, (unsigned int)__float_as_int(v));
    }
}

__device__ __forceinline__ unsigned f2tf32(float x) {
    unsigned r;
    asm("cvt.rna.tf32.f32 %0, %1;" : "=r"(r) : "f"(x));
    return r;
}

__device__ __forceinline__ void mma_tf32(float* d, const unsigned* a, const unsigned* b) {
    asm volatile(
        "mma.sync.aligned.m16n8k8.row.col.f32.tf32.tf32.f32 "
        "{%0,%1,%2,%3}, {%4,%5,%6,%7}, {%8,%9}, {%0,%1,%2,%3};"
        : "+f"(d[0]), "+f"(d[1]), "+f"(d[2]), "+f"(d[3])
        : "r"(a[0]), "r"(a[1]), "r"(a[2]), "r"(a[3]), "r"(b[0]), "r"(b[1]));
}

// ---------------- tf32 tensor-core GEMM -------------------------------------
// C[M,N] = A[M,K] @ B[K,N] (+bias, +act). CTA tile 128x128, BK=16.
// 256 threads = 8 warps in 2x4, warp tile 64x32. Double-buffered smem.
// Requires N % 128 == 0, K % 16 == 0; M guarded.
#define GBM 128
#define GBN 128
#define GBK 16
#define ASTR (GBK + 4)    // 20 -> conflict-free A fragment reads
#define BSTR (GBN + 8)    // 136 -> conflict-free B fragment reads

template <int ACT>  // 0: none, 1: leaky_relu(0.01)
__global__ __launch_bounds__(256, 2) void mma_gemm_kernel(
    const float* __restrict__ A, const float* __restrict__ B,
    const float* __restrict__ bias, float* __restrict__ C,
    int M, int N, int K)
{
    __shared__ unsigned As[2][GBM * ASTR];
    __shared__ unsigned Bs[2][GBK * BSTR];

    const int tid = threadIdx.x;
    const int warp = tid >> 5, lane = tid & 31;
    const int g = lane >> 2, tg = lane & 3;
    const int wr = (warp >> 2) * 64;   // warp row base (0 or 64)
    const int wc = (warp & 3) * 32;    // warp col base (0,32,64,96)

    const int bm = blockIdx.y, bn = blockIdx.x;

    // A staging: thread covers (row = tid>>1, cols colA..colA+7) of 128x16 tile
    const int rowS = tid >> 1;
    const int colA = (tid & 1) * 8;
    const int rowA = bm * GBM + rowS;
    const bool avalid = rowA < M;
    const float* Ap = A + (size_t)rowA * K + colA;

    // B staging: thread covers (row kb = tid>>4, cols jb..jb+7) of 16x128 tile
    const int kb = tid >> 4, jb = (tid & 15) * 8;
    const float* Bp = B + (size_t)kb * N + bn * GBN + jb;

    float acc[4][4][4];
    #pragma unroll
    for (int mt = 0; mt < 4; mt++)
        #pragma unroll
        for (int nt = 0; nt < 4; nt++)
            #pragma unroll
            for (int i = 0; i < 4; i++) acc[mt][nt][i] = 0.0f;

    float4 aR0, aR1, bR0, bR1;

    // prologue: load + stage tile 0 into buffer 0
    aR0 = avalid ? *(const float4*)(Ap)     : make_float4(0.f,0.f,0.f,0.f);
    aR1 = avalid ? *(const float4*)(Ap + 4) : make_float4(0.f,0.f,0.f,0.f);
    bR0 = *(const float4*)(Bp);
    bR1 = *(const float4*)(Bp + 4);
    {
        uint4 u;
        u.x=f2tf32(aR0.x); u.y=f2tf32(aR0.y); u.z=f2tf32(aR0.z); u.w=f2tf32(aR0.w);
        *(uint4*)&As[0][rowS * ASTR + colA] = u;
        u.x=f2tf32(aR1.x); u.y=f2tf32(aR1.y); u.z=f2tf32(aR1.z); u.w=f2tf32(aR1.w);
        *(uint4*)&As[0][rowS * ASTR + colA + 4] = u;
        u.x=f2tf32(bR0.x); u.y=f2tf32(bR0.y); u.z=f2tf32(bR0.z); u.w=f2tf32(bR0.w);
        *(uint4*)&Bs[0][kb * BSTR + jb] = u;
        u.x=f2tf32(bR1.x); u.y=f2tf32(bR1.y); u.z=f2tf32(bR1.z); u.w=f2tf32(bR1.w);
        *(uint4*)&Bs[0][kb * BSTR + jb + 4] = u;
    }
    __syncthreads();

    int buf = 0;
    for (int k0 = 0; k0 < K; k0 += GBK) {
        const int kn = k0 + GBK;
        const bool more = kn < K;

        // prefetch next tile into registers (overlaps with MMA below)
        if (more) {
            aR0 = avalid ? *(const float4*)(Ap + kn)     : make_float4(0.f,0.f,0.f,0.f);
            aR1 = avalid ? *(const float4*)(Ap + kn + 4) : make_float4(0.f,0.f,0.f,0.f);
            bR0 = *(const float4*)(Bp + (size_t)kn * N);
            bR1 = *(const float4*)(Bp + (size_t)kn * N + 4);
        }

        // compute from current buffer: 2 k-steps of 8
        #pragma unroll
        for (int kk = 0; kk < 2; kk++) {
            unsigned af[4][4];
            unsigned bf[4][2];
            #pragma unroll
            for (int mt = 0; mt < 4; mt++) {
                int r0 = wr + mt * 16 + g;
                af[mt][0] = As[buf][(r0    ) * ASTR + kk * 8 + tg];
                af[mt][1] = As[buf][(r0 + 8) * ASTR + kk * 8 + tg];
                af[mt][2] = As[buf][(r0    ) * ASTR + kk * 8 + tg + 4];
                af[mt][3] = As[buf][(r0 + 8) * ASTR + kk * 8 + tg + 4];
            }
            #pragma unroll
            for (int nt = 0; nt < 4; nt++) {
                bf[nt][0] = Bs[buf][(kk * 8 + tg    ) * BSTR + wc + nt * 8 + g];
                bf[nt][1] = Bs[buf][(kk * 8 + tg + 4) * BSTR + wc + nt * 8 + g];
            }
            #pragma unroll
            for (int mt = 0; mt < 4; mt++)
                #pragma unroll
                for (int nt = 0; nt < 4; nt++)
                    mma_tf32(acc[mt][nt], af[mt], bf[nt]);
        }

        // stage next tile into the other buffer
        if (more) {
            uint4 u;
            u.x=f2tf32(aR0.x); u.y=f2tf32(aR0.y); u.z=f2tf32(aR0.z); u.w=f2tf32(aR0.w);
            *(uint4*)&As[buf ^ 1][rowS * ASTR + colA] = u;
            u.x=f2tf32(aR1.x); u.y=f2tf32(aR1.y); u.z=f2tf32(aR1.z); u.w=f2tf32(aR1.w);
            *(uint4*)&As[buf ^ 1][rowS * ASTR + colA + 4] = u;
            u.x=f2tf32(bR0.x); u.y=f2tf32(bR0.y); u.z=f2tf32(bR0.z); u.w=f2tf32(bR0.w);
            *(uint4*)&Bs[buf ^ 1][kb * BSTR + jb] = u;
            u.x=f2tf32(bR1.x); u.y=f2tf32(bR1.y); u.z=f2tf32(bR1.z); u.w=f2tf32(bR1.w);
            *(uint4*)&Bs[buf ^ 1][kb * BSTR + jb + 4] = u;
        }
        __syncthreads();
        buf ^= 1;
    }

    // epilogue
    float bv[4][2];
    #pragma unroll
    for (int nt = 0; nt < 4; nt++) {
        int col = bn * GBN + wc + nt * 8 + 2 * tg;
        bv[nt][0] = bias ? bias[col] : 0.0f;
        bv[nt][1] = bias ? bias[col + 1] : 0.0f;
    }

    #pragma unroll
    for (int mt = 0; mt < 4; mt++) {
        #pragma unroll
        for (int i = 0; i < 2; i++) {
            int row = bm * GBM + wr + mt * 16 + g + i * 8;
            if (row >= M) continue;
            float* Crow = C + (size_t)row * N + bn * GBN + wc;
            #pragma unroll
            for (int nt = 0; nt < 4; nt++) {
                float2 v;
                v.x = acc[mt][nt][i * 2 + 0] + bv[nt][0];
                v.y = acc[mt][nt][i * 2 + 1] + bv[nt][1];
                if (ACT == 1) {
                    v.x = v.x > 0.f ? v.x : 0.01f * v.x;
                    v.y = v.y > 0.f ? v.y : 0.01f * v.y;
                }
                *(float2*)(Crow + nt * 8 + 2 * tg) = v;
            }
        }
    }
}

// ---------------- attention scores + softmax-state init ---------------------
// one warp per (node, head); also initializes emax/denom for that (node, head)
__global__ __launch_bounds__(256) void attn_scores_kernel(
    const float* __restrict__ xl,
    const float* __restrict__ att_src, const float* __restrict__ att_dst,
    float* __restrict__ asrc, float* __restrict__ adst,
    float* __restrict__ emax, float* __restrict__ denom)
{
    int task = blockIdx.x * 8 + (threadIdx.x >> 5);
    if (task >= N_NODES * 4) return;
    int lane = threadIdx.x & 31;
    int n = task >> 2, h = task & 3;

    const float* xp = xl + (size_t)n * 1024 + h * 256 + lane * 8;
    const float* sp = att_src + h * 256 + lane * 8;
    const float* dp = att_dst + h * 256 + lane * 8;

    float s1 = 0.f, s2 = 0.f;
    #pragma unroll
    for (int q = 0; q < 8; q += 4) {
        float4 v = *(const float4*)(xp + q);
        float4 a = *(const float4*)(sp + q);
        float4 b = *(const float4*)(dp + q);
        s1 += v.x * a.x + v.y * a.y + v.z * a.z + v.w * a.w;
        s2 += v.x * b.x + v.y * b.y + v.z * b.z + v.w * b.w;
    }
    #pragma unroll
    for (int off = 16; off > 0; off >>= 1) {
        s1 += __shfl_xor_sync(0xffffffffu, s1, off);
        s2 += __shfl_xor_sync(0xffffffffu, s2, off);
    }
    if (lane == 0) {
        asrc[task] = s1;
        adst[task] = s2;
        emax[task] = NEG_INF;
        denom[task] = 0.0f;
    }
}

// ---------------- pass A: edge logits + segment max -------------------------
__global__ __launch_bounds__(256) void edge_logits_kernel(
    const int* __restrict__ src, const int* __restrict__ dst,
    const float* __restrict__ asrc, const float* __restrict__ adst,
    float* __restrict__ e, float* __restrict__ emax)
{
    int i = blockIdx.x * blockDim.x + threadIdx.x;
    if (i >= N_EDGES) return;
    int s = src[i], d = dst[i];
    float4 as = *(const float4*)(asrc + s * 4);
    float4 ad = *(const float4*)(adst + d * 4);
    float4 ev;
    ev.x = as.x + ad.x; ev.x = ev.x > 0.f ? ev.x : 0.2f * ev.x;
    ev.y = as.y + ad.y; ev.y = ev.y > 0.f ? ev.y : 0.2f * ev.y;
    ev.z = as.z + ad.z; ev.z = ev.z > 0.f ? ev.z : 0.2f * ev.z;
    ev.w = as.w + ad.w; ev.w = ev.w > 0.f ? ev.w : 0.2f * ev.w;
    *(float4*)(e + (size_t)i * 4) = ev;
    atomicMaxFloat(&emax[d * 4 + 0], ev.x);
    atomicMaxFloat(&emax[d * 4 + 1], ev.y);
    atomicMaxFloat(&emax[d * 4 + 2], ev.z);
    atomicMaxFloat(&emax[d * 4 + 3], ev.w);
}

// ---------------- pass B: exp + segment sum ---------------------------------
__global__ __launch_bounds__(256) void edge_exp_kernel(
    const int* __restrict__ dst,
    float* __restrict__ e, const float* __restrict__ emax,
    float* __restrict__ denom)
{
    int i = blockIdx.x * blockDim.x + threadIdx.x;
    if (i >= N_EDGES) return;
    int d = dst[i];
    float4 ev = *(const float4*)(e + (size_t)i * 4);
    float4 mx = *(const float4*)(emax + d * 4);
    float4 ex;
    ex.x = __expf(ev.x - mx.x);
    ex.y = __expf(ev.y - mx.y);
    ex.z = __expf(ev.z - mx.z);
    ex.w = __expf(ev.w - mx.w);
    *(float4*)(e + (size_t)i * 4) = ex;
    redAdd4(denom + d * 4, ex);
}

// ---------------- pass C (layer1, concat): weighted message scatter ----------
// one warp per (edge, head); lane handles 8 contiguous channels
__global__ __launch_bounds__(256) void edge_aggregate_kernel(
    const int* __restrict__ src, const int* __restrict__ dst,
    const float* __restrict__ xl, const float* __restrict__ ex,
    const float* __restrict__ denom, float* __restrict__ out)
{
    long long task = (long long)blockIdx.x * 8 + (threadIdx.x >> 5);
    if (task >= (long long)N_EDGES * 4) return;
    int lane = threadIdx.x & 31;
    int e = (int)(task >> 2), h = (int)(task & 3);
    int s = src[e], d = dst[e];
    float alpha = ex[e * 4 + h] / (denom[d * 4 + h] + 1e-16f);

    const float* sp = xl + (size_t)s * 1024 + h * 256 + lane * 8;
    float* dp = out + (size_t)d * 1024 + h * 256 + lane * 8;
    float4 v0 = *(const float4*)(sp);
    float4 v1 = *(const float4*)(sp + 4);
    v0.x *= alpha; v0.y *= alpha; v0.z *= alpha; v0.w *= alpha;
    v1.x *= alpha; v1.y *= alpha; v1.z *= alpha; v1.w *= alpha;
    redAdd4(dp, v0);
    redAdd4(dp + 4, v1);
}

// ---------------- pass C (layer2, head-mean): fused combine + scatter --------
// one warp per edge; lane handles 8 channels of the 256-dim mean; combines the
// 4 heads in registers before a single vectorized atomic into h2[d, 256].
__global__ __launch_bounds__(256) void edge_aggregate_mean_kernel(
    const int* __restrict__ src, const int* __restrict__ dst,
    const float* __restrict__ xl, const float* __restrict__ ex,
    const float* __restrict__ denom, float* __restrict__ out)
{
    int e = blockIdx.x * 8 + (threadIdx.x >> 5);
    if (e >= N_EDGES) return;
    int lane = threadIdx.x & 31;
    int s = src[e], d = dst[e];

    float4 al = *(const float4*)(ex + (size_t)e * 4);
    float4 dn = *(const float4*)(denom + (size_t)d * 4);
    float a0 = 0.25f * al.x / (dn.x + 1e-16f);
    float a1 = 0.25f * al.y / (dn.y + 1e-16f);
    float a2 = 0.25f * al.z / (dn.z + 1e-16f);
    float a3 = 0.25f * al.w / (dn.w + 1e-16f);

    const float* sp = xl + (size_t)s * 1024 + lane * 8;
    float4 h0a = *(const float4*)(sp +   0), h0b = *(const float4*)(sp +   4);
    float4 h1a = *(const float4*)(sp + 256), h1b = *(const float4*)(sp + 260);
    float4 h2a = *(const float4*)(sp + 512), h2b = *(const float4*)(sp + 516);
    float4 h3a = *(const float4*)(sp + 768), h3b = *(const float4*)(sp + 772);

    float4 v0, v1;
    v0.x = a0*h0a.x + a1*h1a.x + a2*h2a.x + a3*h3a.x;
    v0.y = a0*h0a.y + a1*h1a.y + a2*h2a.y + a3*h3a.y;
    v0.z = a0*h0a.z + a1*h1a.z + a2*h2a.z + a3*h3a.z;
    v0.w = a0*h0a.w + a1*h1a.w + a2*h2a.w + a3*h3a.w;
    v1.x = a0*h0b.x + a1*h1b.x + a2*h2b.x + a3*h3b.x;
    v1.y = a0*h0b.y + a1*h1b.y + a2*h2b.y + a3*h3b.y;
    v1.z = a0*h0b.z + a1*h1b.z + a2*h2b.z + a3*h3b.z;
    v1.w = a0*h0b.w + a1*h1b.w + a2*h2b.w + a3*h3b.w;

    float* dp = out + (size_t)d * 256 + lane * 8;
    redAdd4(dp, v0);
    redAdd4(dp + 4, v1);
}

// ---------------- output heads ----------------------------------------------
__global__ __launch_bounds__(256) void heads_kernel(
    const float* __restrict__ fc,
    const float* __restrict__ Wb, const float* __restrict__ bb,
    const float* __restrict__ Ws, const float* __restrict__ bs,
    float* __restrict__ out)
{
    int n = blockIdx.x * 8 + (threadIdx.x >> 5);
    if (n >= N_NODES) return;
    int lane = threadIdx.x & 31;

    float acc[7] = {0.f, 0.f, 0.f, 0.f, 0.f, 0.f, 0.f};
    #pragma unroll
    for (int i = 0; i < 8; i++) {
        int k = i * 32 + lane;
        float v = fc[(size_t)n * 256 + k];
        acc[0] += v * Wb[k * 2 + 0];
        acc[1] += v * Wb[k * 2 + 1];
        #pragma unroll
        for (int j = 0; j < 5; j++) acc[2 + j] += v * Ws[k * 5 + j];
    }
    #pragma unroll
    for (int off = 16; off > 0; off >>= 1) {
        #pragma unroll
        for (int j = 0; j < 7; j++) acc[j] += __shfl_xor_sync(0xffffffffu, acc[j], off);
    }
    if (lane == 0) {
        out[(size_t)n * 2 + 0] = acc[0] + bb[0];
        out[(size_t)n * 2 + 1] = acc[1] + bb[1];
        float* sev = out + (size_t)N_NODES * 2 + (size_t)n * 5;
        #pragma unroll
        for (int j = 0; j < 5; j++) sev[j] = acc[2 + j] + bs[j];
    }
}

// ---------------- launch ------------------------------------------------------
extern "C" void kernel_launch(void* const* d_in, const int* in_sizes, int n_in,
                              void* d_out, int out_size)
{
    const float* x        = (const float*)d_in[0];
    const int*   ei       = (const int*)d_in[1];
    const float* W1       = (const float*)d_in[2];
    const float* att_src1 = (const float*)d_in[3];
    const float* att_dst1 = (const float*)d_in[4];
    const float* Wres1    = (const float*)d_in[5];
    const float* b1       = (const float*)d_in[6];
    const float* W2       = (const float*)d_in[7];
    const float* att_src2 = (const float*)d_in[8];
    const float* att_dst2 = (const float*)d_in[9];
    const float* Wres2    = (const float*)d_in[10];
    const float* b2       = (const float*)d_in[11];
    const float* Wfc      = (const float*)d_in[12];
    const float* bfc      = (const float*)d_in[13];
    const float* Wb       = (const float*)d_in[14];
    const float* bb       = (const float*)d_in[15];
    const float* Ws       = (const float*)d_in[16];
    const float* bs       = (const float*)d_in[17];
    float* out = (float*)d_out;

    const int* src = ei;
    const int* dst = ei + N_EDGES;

    float *xl, *h1, *h2, *fc1, *fc2, *asrc, *adst, *ebuf, *emax, *denom;
    cudaGetSymbolAddress((void**)&xl,    g_xl);
    cudaGetSymbolAddress((void**)&h1,    g_h1);
    cudaGetSymbolAddress((void**)&h2,    g_h2);
    cudaGetSymbolAddress((void**)&fc1,   g_fc1);
    cudaGetSymbolAddress((void**)&fc2,   g_fc2);
    cudaGetSymbolAddress((void**)&asrc,  g_asrc);
    cudaGetSymbolAddress((void**)&adst,  g_adst);
    cudaGetSymbolAddress((void**)&ebuf,  g_e);
    cudaGetSymbolAddress((void**)&emax,  g_emax);
    cudaGetSymbolAddress((void**)&denom, g_denom);

    const int mRows = (N_NODES + GBM - 1) / GBM;
    const int attnBlocks = (N_NODES * 4 + 7) / 8;
    const int edgeBlocks = (N_EDGES + 255) / 256;

    // ===== layer 1 (concat=true): h1 = agg + x@Wres1 + b1 =====
    {
        dim3 grid(1024 / GBN, mRows);
        mma_gemm_kernel<0><<<grid, 256>>>(x, Wres1, b1, h1, N_NODES, 1024, 768);
        mma_gemm_kernel<0><<<grid, 256>>>(x, W1, nullptr, xl, N_NODES, 1024, 768);
    }
    attn_scores_kernel<<<attnBlocks, 256>>>(xl, att_src1, att_dst1, asrc, adst, emax, denom);
    edge_logits_kernel<<<edgeBlocks, 256>>>(src, dst, asrc, adst, ebuf, emax);
    edge_exp_kernel<<<edgeBlocks, 256>>>(dst, ebuf, emax, denom);
    edge_aggregate_kernel<<<(N_EDGES * 4 + 7) / 8, 256>>>(src, dst, xl, ebuf, denom, h1);

    // ===== layer 2 (concat=false): h2 = mean_heads(agg) + h1@Wres2 + b2 =====
    {
        dim3 grid(256 / GBN, mRows);
        mma_gemm_kernel<0><<<grid, 256>>>(h1, Wres2, b2, h2, N_NODES, 256, 1024);
    }
    {
        dim3 grid(1024 / GBN, mRows);
        mma_gemm_kernel<0><<<grid, 256>>>(h1, W2, nullptr, xl, N_NODES, 1024, 1024);
    }
    attn_scores_kernel<<<attnBlocks, 256>>>(xl, att_src2, att_dst2, asrc, adst, emax, denom);
    edge_logits_kernel<<<edgeBlocks, 256>>>(src, dst, asrc, adst, ebuf, emax);
    edge_exp_kernel<<<edgeBlocks, 256>>>(dst, ebuf, emax, denom);
    edge_aggregate_mean_kernel<<<(N_EDGES + 7) / 8, 256>>>(src, dst, xl, ebuf, denom, h2);

    // ===== shared FC twice =====
    {
        dim3 grid(256 / GBN, mRows);
        mma_gemm_kernel<1><<<grid, 256>>>(h2, Wfc, bfc, fc1, N_NODES, 256, 256);
        mma_gemm_kernel<0><<<grid, 256>>>(fc1, Wfc, bfc, fc2, N_NODES, 256, 256);
    }

    // ===== heads =====
    heads_kernel<<<(N_NODES + 7) / 8, 256>>>(fc2, Wb, bb, Ws, bs, out);
}

// round 4
// speedup vs baseline: 3.1939x; 1.0418x over previous
#include <cuda_runtime.h>
#include <cstdint>

#define N_NODES 20000
#define N_EDGES 320000
#define NEG_INF __int_as_float(0xff800000)

// ---------------- scratch (device globals; no allocation allowed) ----------
__device__ float g_xl[N_NODES * 1024];
__device__ float g_h1[N_NODES * 1024];
__device__ float g_h2[N_NODES * 256];
__device__ float g_fc1[N_NODES * 256];
__device__ float g_fc2[N_NODES * 256];
__device__ float g_at[N_NODES * 1024];   // tf32-rounded activations (A operand)
__device__ float g_wt[1024 * 1024];      // tf32-rounded weights (B operand)
__device__ float g_asrc[N_NODES * 4];
__device__ float g_adst[N_NODES * 4];
__device__ float g_e[N_EDGES * 4];
__device__ float g_emax[N_NODES * 4];
__device__ float g_denom[N_NODES * 4];

// ---------------- helpers ---------------------------------------------------
__device__ __forceinline__ void redAdd4(float* addr, float4 v) {
    asm volatile("red.global.add.v4.f32 [%0], {%1, %2, %3, %4};"
                 :: "l"(addr), "f"(v.x), "f"(v.y), "f"(v.z), "f"(v.w) : "memory");
}

__device__ __forceinline__ void atomicMaxFloat(float* addr, float v) {
    if (v >= 0.0f) {
        atomicMax((int*)addr, __float_as_int(v));
    } else {
        atomicMin((unsigned int*)addr, (unsigned int)__float_as_int(v));
    }
}

__device__ __forceinline__ unsigned f2tf32(float x) {
    unsigned r;
    asm("cvt.rna.tf32.f32 %0, %1;" : "=r"(r) : "f"(x));
    return r;
}

__device__ __forceinline__ void mma_tf32(float* d, const unsigned* a, const unsigned* b) {
    asm volatile(
        "mma.sync.aligned.m16n8k8.row.col.f32.tf32.tf32.f32 "
        "{%0,%1,%2,%3}, {%4,%5,%6,%7}, {%8,%9}, {%0,%1,%2,%3};"
        : "+f"(d[0]), "+f"(d[1]), "+f"(d[2]), "+f"(d[3])
        : "r"(a[0]), "r"(a[1]), "r"(a[2]), "r"(a[3]), "r"(b[0]), "r"(b[1]));
}

__device__ __forceinline__ void cp16(void* smem, const void* gmem, bool pred) {
    unsigned sa = (unsigned)__cvta_generic_to_shared(smem);
    int sz = pred ? 16 : 0;
    asm volatile("cp.async.cg.shared.global [%0], [%1], 16, %2;"
                 :: "r"(sa), "l"(gmem), "r"(sz));
}

// ---------------- tf32 conversion pass ---------------------------------------
// rounds fp32 -> tf32 (rna) stored as fp32 bit pattern; n % 4 == 0
__global__ void cvt_tf32_kernel(const float* __restrict__ in, float* __restrict__ out, int n) {
    int i = (blockIdx.x * blockDim.x + threadIdx.x) * 4;
    if (i >= n) return;
    float4 v = *(const float4*)(in + i);
    uint4 u;
    u.x = f2tf32(v.x); u.y = f2tf32(v.y); u.z = f2tf32(v.z); u.w = f2tf32(v.w);
    *(uint4*)(out + i) = u;
}

// ---------------- tf32 tensor-core GEMM, cp.async 4-stage pipeline -----------
// C[M,N] = A[M,K] @ B[K,N] (+bias, +act). A,B are tf32-pre-rounded fp32.
// CTA tile 128x128, BK=16, 256 threads = 8 warps (2x4), warp tile 64x32.
// Requires N % 128 == 0, K % 16 == 0; M guarded.
#define GBM 128
#define GBN 128
#define GBK 16
#define ASTR 20           // floats per A row  -> conflict-free fragment reads
#define BSTR 136          // floats per B row  -> conflict-free fragment reads
#define ASZ (GBM * ASTR)  // 2560
#define BSZ (GBK * BSTR)  // 2176
#define STAGES 4
#define GEMM_SMEM (STAGES * (ASZ + BSZ) * 4)  // 75776 bytes

template <int ACT>  // 0: none, 1: leaky_relu(0.01)
__global__ __launch_bounds__(256, 2) void mma_gemm_kernel(
    const float* __restrict__ A, const float* __restrict__ B,
    const float* __restrict__ bias, float* __restrict__ C,
    int M, int N, int K)
{
    extern __shared__ unsigned smem[];
    unsigned* As = smem;                  // [STAGES][ASZ]
    unsigned* Bs = smem + STAGES * ASZ;   // [STAGES][BSZ]

    const int tid = threadIdx.x;
    const int warp = tid >> 5, lane = tid & 31;
    const int g = lane >> 2, tg = lane & 3;
    const int wr = (warp >> 2) * 64;
    const int wc = (warp & 3) * 32;

    const int bm = blockIdx.y, bn = blockIdx.x;

    // A staging: thread covers (row rowS, cols colA..colA+7) of 128x16 tile
    const int rowS = tid >> 1;
    const int colA = (tid & 1) * 8;
    const int rowA = bm * GBM + rowS;
    const bool avalid = rowA < M;
    const float* Ap = avalid ? (A + (size_t)rowA * K + colA) : A;

    // B staging: thread covers (row kb, cols jb..jb+7) of 16x128 tile
    const int kb = tid >> 4, jb = (tid & 15) * 8;
    const float* Bp = B + (size_t)kb * N + bn * GBN + jb;

    const int KT = K / GBK;

    float acc[4][4][4];
    #pragma unroll
    for (int mt = 0; mt < 4; mt++)
        #pragma unroll
        for (int nt = 0; nt < 4; nt++)
            #pragma unroll
            for (int i = 0; i < 4; i++) acc[mt][nt][i] = 0.0f;

    // prologue: issue first STAGES-1 tiles
    #pragma unroll
    for (int kt = 0; kt < STAGES - 1; kt++) {
        if (kt < KT) {
            unsigned* as = As + (kt % STAGES) * ASZ;
            unsigned* bs = Bs + (kt % STAGES) * BSZ;
            const float* ap = Ap + (avalid ? kt * GBK : 0);
            const float* bp = Bp + (size_t)kt * GBK * N;
            cp16(&as[rowS * ASTR + colA],     ap,     avalid);
            cp16(&as[rowS * ASTR + colA + 4], ap + 4, avalid);
            cp16(&bs[kb * BSTR + jb],     bp,     true);
            cp16(&bs[kb * BSTR + jb + 4], bp + 4, true);
        }
        asm volatile("cp.async.commit_group;");
    }

    for (int kt = 0; kt < KT; kt++) {
        // issue tile kt+STAGES-1 (or empty group to keep the count moving)
        int kf = kt + STAGES - 1;
        if (kf < KT) {
            unsigned* as = As + (kf % STAGES) * ASZ;
            unsigned* bs = Bs + (kf % STAGES) * BSZ;
            const float* ap = Ap + (avalid ? kf * GBK : 0);
            const float* bp = Bp + (size_t)kf * GBK * N;
            cp16(&as[rowS * ASTR + colA],     ap,     avalid);
            cp16(&as[rowS * ASTR + colA + 4], ap + 4, avalid);
            cp16(&bs[kb * BSTR + jb],     bp,     true);
            cp16(&bs[kb * BSTR + jb + 4], bp + 4, true);
        }
        asm volatile("cp.async.commit_group;");

        asm volatile("cp.async.wait_group %0;" :: "n"(STAGES - 2));
        __syncthreads();

        const unsigned* as = As + (kt % STAGES) * ASZ;
        const unsigned* bs = Bs + (kt % STAGES) * BSZ;

        #pragma unroll
        for (int kk = 0; kk < 2; kk++) {
            unsigned af[4][4];
            unsigned bf[4][2];
            #pragma unroll
            for (int mt = 0; mt < 4; mt++) {
                int r0 = wr + mt * 16 + g;
                af[mt][0] = as[(r0    ) * ASTR + kk * 8 + tg];
                af[mt][1] = as[(r0 + 8) * ASTR + kk * 8 + tg];
                af[mt][2] = as[(r0    ) * ASTR + kk * 8 + tg + 4];
                af[mt][3] = as[(r0 + 8) * ASTR + kk * 8 + tg + 4];
            }
            #pragma unroll
            for (int nt = 0; nt < 4; nt++) {
                bf[nt][0] = bs[(kk * 8 + tg    ) * BSTR + wc + nt * 8 + g];
                bf[nt][1] = bs[(kk * 8 + tg + 4) * BSTR + wc + nt * 8 + g];
            }
            #pragma unroll
            for (int mt = 0; mt < 4; mt++)
                #pragma unroll
                for (int nt = 0; nt < 4; nt++)
                    mma_tf32(acc[mt][nt], af[mt], bf[nt]);
        }
        __syncthreads();  // all warps done with buffer kt%STAGES before reuse
    }

    // epilogue
    float bv[4][2];
    #pragma unroll
    for (int nt = 0; nt < 4; nt++) {
        int col = bn * GBN + wc + nt * 8 + 2 * tg;
        bv[nt][0] = bias ? bias[col] : 0.0f;
        bv[nt][1] = bias ? bias[col + 1] : 0.0f;
    }

    #pragma unroll
    for (int mt = 0; mt < 4; mt++) {
        #pragma unroll
        for (int i = 0; i < 2; i++) {
            int row = bm * GBM + wr + mt * 16 + g + i * 8;
            if (row >= M) continue;
            float* Crow = C + (size_t)row * N + bn * GBN + wc;
            #pragma unroll
            for (int nt = 0; nt < 4; nt++) {
                float2 v;
                v.x = acc[mt][nt][i * 2 + 0] + bv[nt][0];
                v.y = acc[mt][nt][i * 2 + 1] + bv[nt][1];
                if (ACT == 1) {
                    v.x = v.x > 0.f ? v.x : 0.01f * v.x;
                    v.y = v.y > 0.f ? v.y : 0.01f * v.y;
                }
                *(float2*)(Crow + nt * 8 + 2 * tg) = v;
            }
        }
    }
}

// ---------------- attention scores + softmax-state init ---------------------
__global__ __launch_bounds__(256) void attn_scores_kernel(
    const float* __restrict__ xl,
    const float* __restrict__ att_src, const float* __restrict__ att_dst,
    float* __restrict__ asrc, float* __restrict__ adst,
    float* __restrict__ emax, float* __restrict__ denom)
{
    int task = blockIdx.x * 8 + (threadIdx.x >> 5);
    if (task >= N_NODES * 4) return;
    int lane = threadIdx.x & 31;
    int n = task >> 2, h = task & 3;

    const float* xp = xl + (size_t)n * 1024 + h * 256 + lane * 8;
    const float* sp = att_src + h * 256 + lane * 8;
    const float* dp = att_dst + h * 256 + lane * 8;

    float s1 = 0.f, s2 = 0.f;
    #pragma unroll
    for (int q = 0; q < 8; q += 4) {
        float4 v = *(const float4*)(xp + q);
        float4 a = *(const float4*)(sp + q);
        float4 b = *(const float4*)(dp + q);
        s1 += v.x * a.x + v.y * a.y + v.z * a.z + v.w * a.w;
        s2 += v.x * b.x + v.y * b.y + v.z * b.z + v.w * b.w;
    }
    #pragma unroll
    for (int off = 16; off > 0; off >>= 1) {
        s1 += __shfl_xor_sync(0xffffffffu, s1, off);
        s2 += __shfl_xor_sync(0xffffffffu, s2, off);
    }
    if (lane == 0) {
        asrc[task] = s1;
        adst[task] = s2;
        emax[task] = NEG_INF;
        denom[task] = 0.0f;
    }
}

// ---------------- pass A: edge logits + segment max -------------------------
__global__ __launch_bounds__(256) void edge_logits_kernel(
    const int* __restrict__ src, const int* __restrict__ dst,
    const float* __restrict__ asrc, const float* __restrict__ adst,
    float* __restrict__ e, float* __restrict__ emax)
{
    int i = blockIdx.x * blockDim.x + threadIdx.x;
    if (i >= N_EDGES) return;
    int s = src[i], d = dst[i];
    float4 as = *(const float4*)(asrc + s * 4);
    float4 ad = *(const float4*)(adst + d * 4);
    float4 ev;
    ev.x = as.x + ad.x; ev.x = ev.x > 0.f ? ev.x : 0.2f * ev.x;
    ev.y = as.y + ad.y; ev.y = ev.y > 0.f ? ev.y : 0.2f * ev.y;
    ev.z = as.z + ad.z; ev.z = ev.z > 0.f ? ev.z : 0.2f * ev.z;
    ev.w = as.w + ad.w; ev.w = ev.w > 0.f ? ev.w : 0.2f * ev.w;
    *(float4*)(e + (size_t)i * 4) = ev;
    atomicMaxFloat(&emax[d * 4 + 0], ev.x);
    atomicMaxFloat(&emax[d * 4 + 1], ev.y);
    atomicMaxFloat(&emax[d * 4 + 2], ev.z);
    atomicMaxFloat(&emax[d * 4 + 3], ev.w);
}

// ---------------- pass B: exp + segment sum ---------------------------------
__global__ __launch_bounds__(256) void edge_exp_kernel(
    const int* __restrict__ dst,
    float* __restrict__ e, const float* __restrict__ emax,
    float* __restrict__ denom)
{
    int i = blockIdx.x * blockDim.x + threadIdx.x;
    if (i >= N_EDGES) return;
    int d = dst[i];
    float4 ev = *(const float4*)(e + (size_t)i * 4);
    float4 mx = *(const float4*)(emax + d * 4);
    float4 ex;
    ex.x = __expf(ev.x - mx.x);
    ex.y = __expf(ev.y - mx.y);
    ex.z = __expf(ev.z - mx.z);
    ex.w = __expf(ev.w - mx.w);
    *(float4*)(e + (size_t)i * 4) = ex;
    redAdd4(denom + d * 4, ex);
}

// ---------------- pass C (layer1, concat): weighted message scatter ----------
__global__ __launch_bounds__(256) void edge_aggregate_kernel(
    const int* __restrict__ src, const int* __restrict__ dst,
    const float* __restrict__ xl, const float* __restrict__ ex,
    const float* __restrict__ denom, float* __restrict__ out)
{
    long long task = (long long)blockIdx.x * 8 + (threadIdx.x >> 5);
    if (task >= (long long)N_EDGES * 4) return;
    int lane = threadIdx.x & 31;
    int e = (int)(task >> 2), h = (int)(task & 3);
    int s = src[e], d = dst[e];
    float alpha = ex[e * 4 + h] / (denom[d * 4 + h] + 1e-16f);

    const float* sp = xl + (size_t)s * 1024 + h * 256 + lane * 8;
    float* dp = out + (size_t)d * 1024 + h * 256 + lane * 8;
    float4 v0 = *(const float4*)(sp);
    float4 v1 = *(const float4*)(sp + 4);
    v0.x *= alpha; v0.y *= alpha; v0.z *= alpha; v0.w *= alpha;
    v1.x *= alpha; v1.y *= alpha; v1.z *= alpha; v1.w *= alpha;
    redAdd4(dp, v0);
    redAdd4(dp + 4, v1);
}

// ---------------- pass C (layer2, head-mean): fused combine + scatter --------
__global__ __launch_bounds__(256) void edge_aggregate_mean_kernel(
    const int* __restrict__ src, const int* __restrict__ dst,
    const float* __restrict__ xl, const float* __restrict__ ex,
    const float* __restrict__ denom, float* __restrict__ out)
{
    int e = blockIdx.x * 8 + (threadIdx.x >> 5);
    if (e >= N_EDGES) return;
    int lane = threadIdx.x & 31;
    int s = src[e], d = dst[e];

    float4 al = *(const float4*)(ex + (size_t)e * 4);
    float4 dn = *(const float4*)(denom + (size_t)d * 4);
    float a0 = 0.25f * al.x / (dn.x + 1e-16f);
    float a1 = 0.25f * al.y / (dn.y + 1e-16f);
    float a2 = 0.25f * al.z / (dn.z + 1e-16f);
    float a3 = 0.25f * al.w / (dn.w + 1e-16f);

    const float* sp = xl + (size_t)s * 1024 + lane * 8;
    float4 h0a = *(const float4*)(sp +   0), h0b = *(const float4*)(sp +   4);
    float4 h1a = *(const float4*)(sp + 256), h1b = *(const float4*)(sp + 260);
    float4 h2a = *(const float4*)(sp + 512), h2b = *(const float4*)(sp + 516);
    float4 h3a = *(const float4*)(sp + 768), h3b = *(const float4*)(sp + 772);

    float4 v0, v1;
    v0.x = a0*h0a.x + a1*h1a.x + a2*h2a.x + a3*h3a.x;
    v0.y = a0*h0a.y + a1*h1a.y + a2*h2a.y + a3*h3a.y;
    v0.z = a0*h0a.z + a1*h1a.z + a2*h2a.z + a3*h3a.z;
    v0.w = a0*h0a.w + a1*h1a.w + a2*h2a.w + a3*h3a.w;
    v1.x = a0*h0b.x + a1*h1b.x + a2*h2b.x + a3*h3b.x;
    v1.y = a0*h0b.y + a1*h1b.y + a2*h2b.y + a3*h3b.y;
    v1.z = a0*h0b.z + a1*h1b.z + a2*h2b.z + a3*h3b.z;
    v1.w = a0*h0b.w + a1*h1b.w + a2*h2b.w + a3*h3b.w;

    float* dp = out + (size_t)d * 256 + lane * 8;
    redAdd4(dp, v0);
    redAdd4(dp + 4, v1);
}

// ---------------- output heads ----------------------------------------------
__global__ __launch_bounds__(256) void heads_kernel(
    const float* __restrict__ fc,
    const float* __restrict__ Wb, const float* __restrict__ bb,
    const float* __restrict__ Ws, const float* __restrict__ bs,
    float* __restrict__ out)
{
    int n = blockIdx.x * 8 + (threadIdx.x >> 5);
    if (n >= N_NODES) return;
    int lane = threadIdx.x & 31;

    float acc[7] = {0.f, 0.f, 0.f, 0.f, 0.f, 0.f, 0.f};
    #pragma unroll
    for (int i = 0; i < 8; i++) {
        int k = i * 32 + lane;
        float v = fc[(size_t)n * 256 + k];
        acc[0] += v * Wb[k * 2 + 0];
        acc[1] += v * Wb[k * 2 + 1];
        #pragma unroll
        for (int j = 0; j < 5; j++) acc[2 + j] += v * Ws[k * 5 + j];
    }
    #pragma unroll
    for (int off = 16; off > 0; off >>= 1) {
        #pragma unroll
        for (int j = 0; j < 7; j++) acc[j] += __shfl_xor_sync(0xffffffffu, acc[j], off);
    }
    if (lane == 0) {
        out[(size_t)n * 2 + 0] = acc[0] + bb[0];
        out[(size_t)n * 2 + 1] = acc[1] + bb[1];
        float* sev = out + (size_t)N_NODES * 2 + (size_t)n * 5;
        #pragma unroll
        for (int j = 0; j < 5; j++) sev[j] = acc[2 + j] + bs[j];
    }
}

// ---------------- launch ------------------------------------------------------
static inline void cvt(const float* in, float* out, int n) {
    cvt_tf32_kernel<<<(n / 4 + 255) / 256, 256>>>(in, out, n);
}

extern "C" void kernel_launch(void* const* d_in, const int* in_sizes, int n_in,
                              void* d_out, int out_size)
{
    const float* x        = (const float*)d_in[0];
    const int*   ei       = (const int*)d_in[1];
    const float* W1       = (const float*)d_in[2];
    const float* att_src1 = (const float*)d_in[3];
    const float* att_dst1 = (const float*)d_in[4];
    const float* Wres1    = (const float*)d_in[5];
    const float* b1       = (const float*)d_in[6];
    const float* W2       = (const float*)d_in[7];
    const float* att_src2 = (const float*)d_in[8];
    const float* att_dst2 = (const float*)d_in[9];
    const float* Wres2    = (const float*)d_in[10];
    const float* b2       = (const float*)d_in[11];
    const float* Wfc      = (const float*)d_in[12];
    const float* bfc      = (const float*)d_in[13];
    const float* Wb       = (const float*)d_in[14];
    const float* bb       = (const float*)d_in[15];
    const float* Ws       = (const float*)d_in[16];
    const float* bs       = (const float*)d_in[17];
    float* out = (float*)d_out;

    const int* src = ei;
    const int* dst = ei + N_EDGES;

    float *xl, *h1, *h2, *fc1, *fc2, *at, *wt, *asrc, *adst, *ebuf, *emax, *denom;
    cudaGetSymbolAddress((void**)&xl,    g_xl);
    cudaGetSymbolAddress((void**)&h1,    g_h1);
    cudaGetSymbolAddress((void**)&h2,    g_h2);
    cudaGetSymbolAddress((void**)&fc1,   g_fc1);
    cudaGetSymbolAddress((void**)&fc2,   g_fc2);
    cudaGetSymbolAddress((void**)&at,    g_at);
    cudaGetSymbolAddress((void**)&wt,    g_wt);
    cudaGetSymbolAddress((void**)&asrc,  g_asrc);
    cudaGetSymbolAddress((void**)&adst,  g_adst);
    cudaGetSymbolAddress((void**)&ebuf,  g_e);
    cudaGetSymbolAddress((void**)&emax,  g_emax);
    cudaGetSymbolAddress((void**)&denom, g_denom);

    static bool attr_done = false;
    if (!attr_done) {
        cudaFuncSetAttribute(mma_gemm_kernel<0>,
                             cudaFuncAttributeMaxDynamicSharedMemorySize, GEMM_SMEM);
        cudaFuncSetAttribute(mma_gemm_kernel<1>,
                             cudaFuncAttributeMaxDynamicSharedMemorySize, GEMM_SMEM);
        attr_done = true;
    }

    const int mRows = (N_NODES + GBM - 1) / GBM;
    const int attnBlocks = (N_NODES * 4 + 7) / 8;
    const int edgeBlocks = (N_EDGES + 255) / 256;

    // ===== layer 1 (concat=true): h1 = agg + x@Wres1 + b1 =====
    cvt(x, at, N_NODES * 768);
    {
        dim3 grid(1024 / GBN, mRows);
        cvt(Wres1, wt, 768 * 1024);
        mma_gemm_kernel<0><<<grid, 256, GEMM_SMEM>>>(at, wt, b1, h1, N_NODES, 1024, 768);
        cvt(W1, wt, 768 * 1024);
        mma_gemm_kernel<0><<<grid, 256, GEMM_SMEM>>>(at, wt, nullptr, xl, N_NODES, 1024, 768);
    }
    attn_scores_kernel<<<attnBlocks, 256>>>(xl, att_src1, att_dst1, asrc, adst, emax, denom);
    edge_logits_kernel<<<edgeBlocks, 256>>>(src, dst, asrc, adst, ebuf, emax);
    edge_exp_kernel<<<edgeBlocks, 256>>>(dst, ebuf, emax, denom);
    edge_aggregate_kernel<<<(N_EDGES * 4 + 7) / 8, 256>>>(src, dst, xl, ebuf, denom, h1);

    // ===== layer 2 (concat=false): h2 = mean_heads(agg) + h1@Wres2 + b2 =====
    cvt(h1, at, N_NODES * 1024);
    {
        dim3 grid(256 / GBN, mRows);
        cvt(Wres2, wt, 1024 * 256);
        mma_gemm_kernel<0><<<grid, 256, GEMM_SMEM>>>(at, wt, b2, h2, N_NODES, 256, 1024);
    }
    {
        dim3 grid(1024 / GBN, mRows);
        cvt(W2, wt, 1024 * 1024);
        mma_gemm_kernel<0><<<grid, 256, GEMM_SMEM>>>(at, wt, nullptr, xl, N_NODES, 1024, 1024);
    }
    attn_scores_kernel<<<attnBlocks, 256>>>(xl, att_src2, att_dst2, asrc, adst, emax, denom);
    edge_logits_kernel<<<edgeBlocks, 256>>>(src, dst, asrc, adst, ebuf, emax);
    edge_exp_kernel<<<edgeBlocks, 256>>>(dst, ebuf, emax, denom);
    edge_aggregate_mean_kernel<<<(N_EDGES + 7) / 8, 256>>>(src, dst, xl, ebuf, denom, h2);

    // ===== shared FC twice =====
    {
        dim3 grid(256 / GBN, mRows);
        cvt(h2, at, N_NODES * 256);
        cvt(Wfc, wt, 256 * 256);
        mma_gemm_kernel<1><<<grid, 256, GEMM_SMEM>>>(at, wt, bfc, fc1, N_NODES, 256, 256);
        cvt(fc1, at, N_NODES * 256);
        mma_gemm_kernel<0><<<grid, 256, GEMM_SMEM>>>(at, wt, bfc, fc2, N_NODES, 256, 256);
    }

    // ===== heads =====
    heads_kernel<<<(N_NODES + 7) / 8, 256>>>(fc2, Wb, bb, Ws, bs, out);
}

// round 6
// speedup vs baseline: 3.9163x; 1.2262x over previous
#include <cuda_runtime.h>
#include <cstdint>

#define N_NODES 20000
#define N_EDGES 320000

// ---------------- scratch (device globals; no allocation allowed) ----------
__device__ float g_xl[N_NODES * 1024];
__device__ float g_h1[N_NODES * 1024];
__device__ float g_h2[N_NODES * 256];
__device__ float g_fc1[N_NODES * 256];
__device__ float g_fc2[N_NODES * 256];
__device__ float g_at[N_NODES * 1024];   // tf32-rounded activations (A operand)
__device__ float g_wt[1024 * 1024];      // tf32-rounded weights buffer A
__device__ float g_wt2[1024 * 1024];     // tf32-rounded weights buffer B
__device__ float g_asrc[N_NODES * 4];
__device__ float g_adst[N_NODES * 4];
__device__ int   g_deg[N_NODES];
__device__ int   g_off[N_NODES + 1];
__device__ int   g_cur[N_NODES];
__device__ int   g_esrc[N_EDGES];        // src node of each edge, sorted by dst

// ---------------- helpers ---------------------------------------------------
__device__ __forceinline__ unsigned f2tf32(float x) {
    unsigned r;
    asm("cvt.rna.tf32.f32 %0, %1;" : "=r"(r) : "f"(x));
    return r;
}

__device__ __forceinline__ void mma_tf32(float* d, const unsigned* a, const unsigned* b) {
    asm volatile(
        "mma.sync.aligned.m16n8k8.row.col.f32.tf32.tf32.f32 "
        "{%0,%1,%2,%3}, {%4,%5,%6,%7}, {%8,%9}, {%0,%1,%2,%3};"
        : "+f"(d[0]), "+f"(d[1]), "+f"(d[2]), "+f"(d[3])
        : "r"(a[0]), "r"(a[1]), "r"(a[2]), "r"(a[3]), "r"(b[0]), "r"(b[1]));
}

__device__ __forceinline__ void cp16(void* smem, const void* gmem, bool pred) {
    unsigned sa = (unsigned)__cvta_generic_to_shared(smem);
    int sz = pred ? 16 : 0;
    asm volatile("cp.async.cg.shared.global [%0], [%1], 16, %2;"
                 :: "r"(sa), "l"(gmem), "r"(sz));
}

// ---------------- tf32 conversion pass ---------------------------------------
__global__ void cvt_tf32_kernel(const float* __restrict__ in, float* __restrict__ out, int n) {
    int i = (blockIdx.x * blockDim.x + threadIdx.x) * 4;
    if (i >= n) return;
    float4 v = *(const float4*)(in + i);
    uint4 u;
    u.x = f2tf32(v.x); u.y = f2tf32(v.y); u.z = f2tf32(v.z); u.w = f2tf32(v.w);
    *(uint4*)(out + i) = u;
}

// ---------------- CSR build ---------------------------------------------------
__global__ void zero_deg_kernel(int* __restrict__ deg) {
    int i = blockIdx.x * blockDim.x + threadIdx.x;
    if (i < N_NODES) deg[i] = 0;
}

__global__ void hist_kernel(const int* __restrict__ dst, int* __restrict__ deg) {
    int e = blockIdx.x * blockDim.x + threadIdx.x;
    if (e < N_EDGES) atomicAdd(&deg[dst[e]], 1);
}

// single-block exclusive scan over degrees -> offsets (and cursor copy)
__global__ __launch_bounds__(256) void scan_kernel(
    const int* __restrict__ deg, int* __restrict__ off, int* __restrict__ cur)
{
    __shared__ int partial[256];
    const int tid = threadIdx.x;
    const int CH = (N_NODES + 255) / 256;
    const int base = tid * CH;

    int s = 0;
    for (int j = 0; j < CH; j++) {
        int i = base + j;
        if (i < N_NODES) s += deg[i];
    }
    partial[tid] = s;
    __syncthreads();
    // inclusive scan over partials
    for (int o = 1; o < 256; o <<= 1) {
        int v = (tid >= o) ? partial[tid - o] : 0;
        __syncthreads();
        partial[tid] += v;
        __syncthreads();
    }
    int run = partial[tid] - s;  // exclusive
    for (int j = 0; j < CH; j++) {
        int i = base + j;
        if (i < N_NODES) {
            off[i] = run;
            cur[i] = run;
            run += deg[i];
        }
    }
    if (tid == 255) off[N_NODES] = run;
}

__global__ void scatter_kernel(const int* __restrict__ src, const int* __restrict__ dst,
                               int* __restrict__ cur, int* __restrict__ esrc) {
    int e = blockIdx.x * blockDim.x + threadIdx.x;
    if (e >= N_EDGES) return;
    int pos = atomicAdd(&cur[dst[e]], 1);
    esrc[pos] = src[e];
}

// ---------------- tf32 tensor-core GEMM, cp.async 4-stage pipeline -----------
#define GBM 128
#define GBN 128
#define GBK 16
#define ASTR 20
#define BSTR 136
#define ASZ (GBM * ASTR)
#define BSZ (GBK * BSTR)
#define STAGES 4
#define GEMM_SMEM (STAGES * (ASZ + BSZ) * 4)

template <int ACT>  // 0: none, 1: leaky_relu(0.01)
__global__ __launch_bounds__(256, 2) void mma_gemm_kernel(
    const float* __restrict__ A, const float* __restrict__ B,
    const float* __restrict__ bias, float* __restrict__ C,
    int M, int N, int K)
{
    extern __shared__ unsigned smem[];
    unsigned* As = smem;
    unsigned* Bs = smem + STAGES * ASZ;

    const int tid = threadIdx.x;
    const int warp = tid >> 5, lane = tid & 31;
    const int g = lane >> 2, tg = lane & 3;
    const int wr = (warp >> 2) * 64;
    const int wc = (warp & 3) * 32;

    const int bm = blockIdx.y, bn = blockIdx.x;

    const int rowS = tid >> 1;
    const int colA = (tid & 1) * 8;
    const int rowA = bm * GBM + rowS;
    const bool avalid = rowA < M;
    const float* Ap = avalid ? (A + (size_t)rowA * K + colA) : A;

    const int kb = tid >> 4, jb = (tid & 15) * 8;
    const float* Bp = B + (size_t)kb * N + bn * GBN + jb;

    const int KT = K / GBK;

    float acc[4][4][4];
    #pragma unroll
    for (int mt = 0; mt < 4; mt++)
        #pragma unroll
        for (int nt = 0; nt < 4; nt++)
            #pragma unroll
            for (int i = 0; i < 4; i++) acc[mt][nt][i] = 0.0f;

    #pragma unroll
    for (int kt = 0; kt < STAGES - 1; kt++) {
        if (kt < KT) {
            unsigned* as = As + (kt % STAGES) * ASZ;
            unsigned* bs = Bs + (kt % STAGES) * BSZ;
            const float* ap = Ap + (avalid ? kt * GBK : 0);
            const float* bp = Bp + (size_t)kt * GBK * N;
            cp16(&as[rowS * ASTR + colA],     ap,     avalid);
            cp16(&as[rowS * ASTR + colA + 4], ap + 4, avalid);
            cp16(&bs[kb * BSTR + jb],     bp,     true);
            cp16(&bs[kb * BSTR + jb + 4], bp + 4, true);
        }
        asm volatile("cp.async.commit_group;");
    }

    for (int kt = 0; kt < KT; kt++) {
        int kf = kt + STAGES - 1;
        if (kf < KT) {
            unsigned* as = As + (kf % STAGES) * ASZ;
            unsigned* bs = Bs + (kf % STAGES) * BSZ;
            const float* ap = Ap + (avalid ? kf * GBK : 0);
            const float* bp = Bp + (size_t)kf * GBK * N;
            cp16(&as[rowS * ASTR + colA],     ap,     avalid);
            cp16(&as[rowS * ASTR + colA + 4], ap + 4, avalid);
            cp16(&bs[kb * BSTR + jb],     bp,     true);
            cp16(&bs[kb * BSTR + jb + 4], bp + 4, true);
        }
        asm volatile("cp.async.commit_group;");

        asm volatile("cp.async.wait_group %0;" :: "n"(STAGES - 2));
        __syncthreads();

        const unsigned* as = As + (kt % STAGES) * ASZ;
        const unsigned* bs = Bs + (kt % STAGES) * BSZ;

        #pragma unroll
        for (int kk = 0; kk < 2; kk++) {
            unsigned af[4][4];
            unsigned bf[4][2];
            #pragma unroll
            for (int mt = 0; mt < 4; mt++) {
                int r0 = wr + mt * 16 + g;
                af[mt][0] = as[(r0    ) * ASTR + kk * 8 + tg];
                af[mt][1] = as[(r0 + 8) * ASTR + kk * 8 + tg];
                af[mt][2] = as[(r0    ) * ASTR + kk * 8 + tg + 4];
                af[mt][3] = as[(r0 + 8) * ASTR + kk * 8 + tg + 4];
            }
            #pragma unroll
            for (int nt = 0; nt < 4; nt++) {
                bf[nt][0] = bs[(kk * 8 + tg    ) * BSTR + wc + nt * 8 + g];
                bf[nt][1] = bs[(kk * 8 + tg + 4) * BSTR + wc + nt * 8 + g];
            }
            #pragma unroll
            for (int mt = 0; mt < 4; mt++)
                #pragma unroll
                for (int nt = 0; nt < 4; nt++)
                    mma_tf32(acc[mt][nt], af[mt], bf[nt]);
        }
        __syncthreads();
    }

    float bv[4][2];
    #pragma unroll
    for (int nt = 0; nt < 4; nt++) {
        int col = bn * GBN + wc + nt * 8 + 2 * tg;
        bv[nt][0] = bias ? bias[col] : 0.0f;
        bv[nt][1] = bias ? bias[col + 1] : 0.0f;
    }

    #pragma unroll
    for (int mt = 0; mt < 4; mt++) {
        #pragma unroll
        for (int i = 0; i < 2; i++) {
            int row = bm * GBM + wr + mt * 16 + g + i * 8;
            if (row >= M) continue;
            float* Crow = C + (size_t)row * N + bn * GBN + wc;
            #pragma unroll
            for (int nt = 0; nt < 4; nt++) {
                float2 v;
                v.x = acc[mt][nt][i * 2 + 0] + bv[nt][0];
                v.y = acc[mt][nt][i * 2 + 1] + bv[nt][1];
                if (ACT == 1) {
                    v.x = v.x > 0.f ? v.x : 0.01f * v.x;
                    v.y = v.y > 0.f ? v.y : 0.01f * v.y;
                }
                *(float2*)(Crow + nt * 8 + 2 * tg) = v;
            }
        }
    }
}

// ---------------- attention scores -------------------------------------------
__global__ __launch_bounds__(256) void attn_scores_kernel(
    const float* __restrict__ xl,
    const float* __restrict__ att_src, const float* __restrict__ att_dst,
    float* __restrict__ asrc, float* __restrict__ adst)
{
    int task = blockIdx.x * 8 + (threadIdx.x >> 5);
    if (task >= N_NODES * 4) return;
    int lane = threadIdx.x & 31;
    int n = task >> 2, h = task & 3;

    const float* xp = xl + (size_t)n * 1024 + h * 256 + lane * 8;
    const float* sp = att_src + h * 256 + lane * 8;
    const float* dp = att_dst + h * 256 + lane * 8;

    float s1 = 0.f, s2 = 0.f;
    #pragma unroll
    for (int q = 0; q < 8; q += 4) {
        float4 v = *(const float4*)(xp + q);
        float4 a = *(const float4*)(sp + q);
        float4 b = *(const float4*)(dp + q);
        s1 += v.x * a.x + v.y * a.y + v.z * a.z + v.w * a.w;
        s2 += v.x * b.x + v.y * b.y + v.z * b.z + v.w * b.w;
    }
    #pragma unroll
    for (int off = 16; off > 0; off >>= 1) {
        s1 += __shfl_xor_sync(0xffffffffu, s1, off);
        s2 += __shfl_xor_sync(0xffffffffu, s2, off);
    }
    if (lane == 0) {
        asrc[task] = s1;
        adst[task] = s2;
    }
}

// ---------------- layer1 aggregation (concat): gather, no atomics -------------
// one warp per (dst node, head); softmax computed inline over incident edges
__global__ __launch_bounds__(256) void gat_aggregate1_kernel(
    const int* __restrict__ off, const int* __restrict__ esrc,
    const float* __restrict__ xl, const float* __restrict__ asrc,
    const float* __restrict__ adst, float* __restrict__ h1)
{
    int task = blockIdx.x * 8 + (threadIdx.x >> 5);
    if (task >= N_NODES * 4) return;
    int lane = threadIdx.x & 31;
    int n = task >> 2, h = task & 3;

    const float ad = adst[n * 4 + h];
    const int j0 = off[n], j1 = off[n + 1];

    float4 u0 = make_float4(0.f, 0.f, 0.f, 0.f);
    float4 u1 = make_float4(0.f, 0.f, 0.f, 0.f);
    float ssum = 0.f;

    for (int j = j0; j < j1; j++) {
        int s = esrc[j];
        float a = asrc[s * 4 + h] + ad;
        a = a > 0.f ? a : 0.2f * a;
        float w = __expf(a);
        ssum += w;
        const float* sp = xl + (size_t)s * 1024 + h * 256 + lane * 8;
        float4 v0 = *(const float4*)(sp);
        float4 v1 = *(const float4*)(sp + 4);
        u0.x += w * v0.x; u0.y += w * v0.y; u0.z += w * v0.z; u0.w += w * v0.w;
        u1.x += w * v1.x; u1.y += w * v1.y; u1.z += w * v1.z; u1.w += w * v1.w;
    }

    float inv = 1.0f / (ssum + 1e-16f);
    float* dp = h1 + (size_t)n * 1024 + h * 256 + lane * 8;
    float4 o0 = *(const float4*)(dp);
    float4 o1 = *(const float4*)(dp + 4);
    o0.x += u0.x * inv; o0.y += u0.y * inv; o0.z += u0.z * inv; o0.w += u0.w * inv;
    o1.x += u1.x * inv; o1.y += u1.y * inv; o1.z += u1.z * inv; o1.w += u1.w * inv;
    *(float4*)(dp) = o0;
    *(float4*)(dp + 4) = o1;
}

// ---------------- layer2 aggregation (head-mean): gather, no atomics ----------
// one warp per dst node; all 4 heads combined in registers
__global__ __launch_bounds__(256) void gat_aggregate2_kernel(
    const int* __restrict__ off, const int* __restrict__ esrc,
    const float* __restrict__ xl, const float* __restrict__ asrc,
    const float* __restrict__ adst, float* __restrict__ h2)
{
    int n = blockIdx.x * 8 + (threadIdx.x >> 5);
    if (n >= N_NODES) return;
    int lane = threadIdx.x & 31;

    float4 ad = *(const float4*)(adst + n * 4);
    const int j0 = off[n], j1 = off[n + 1];

    float4 u[4][2];
    #pragma unroll
    for (int h = 0; h < 4; h++) {
        u[h][0] = make_float4(0.f, 0.f, 0.f, 0.f);
        u[h][1] = make_float4(0.f, 0.f, 0.f, 0.f);
    }
    float4 ssum = make_float4(0.f, 0.f, 0.f, 0.f);

    for (int j = j0; j < j1; j++) {
        int s = esrc[j];
        float4 as = *(const float4*)(asrc + s * 4);
        float4 e;
        e.x = as.x + ad.x; e.x = e.x > 0.f ? e.x : 0.2f * e.x;
        e.y = as.y + ad.y; e.y = e.y > 0.f ? e.y : 0.2f * e.y;
        e.z = as.z + ad.z; e.z = e.z > 0.f ? e.z : 0.2f * e.z;
        e.w = as.w + ad.w; e.w = e.w > 0.f ? e.w : 0.2f * e.w;
        float w0 = __expf(e.x), w1 = __expf(e.y), w2 = __expf(e.z), w3 = __expf(e.w);
        ssum.x += w0; ssum.y += w1; ssum.z += w2; ssum.w += w3;

        const float* sp = xl + (size_t)s * 1024 + lane * 8;
        float w[4] = {w0, w1, w2, w3};
        #pragma unroll
        for (int h = 0; h < 4; h++) {
            float4 v0 = *(const float4*)(sp + h * 256);
            float4 v1 = *(const float4*)(sp + h * 256 + 4);
            u[h][0].x += w[h] * v0.x; u[h][0].y += w[h] * v0.y;
            u[h][0].z += w[h] * v0.z; u[h][0].w += w[h] * v0.w;
            u[h][1].x += w[h] * v1.x; u[h][1].y += w[h] * v1.y;
            u[h][1].z += w[h] * v1.z; u[h][1].w += w[h] * v1.w;
        }
    }

    float i0 = 0.25f / (ssum.x + 1e-16f);
    float i1 = 0.25f / (ssum.y + 1e-16f);
    float i2 = 0.25f / (ssum.z + 1e-16f);
    float i3 = 0.25f / (ssum.w + 1e-16f);

    float* dp = h2 + (size_t)n * 256 + lane * 8;
    float4 o0 = *(const float4*)(dp);
    float4 o1 = *(const float4*)(dp + 4);
    o0.x += i0*u[0][0].x + i1*u[1][0].x + i2*u[2][0].x + i3*u[3][0].x;
    o0.y += i0*u[0][0].y + i1*u[1][0].y + i2*u[2][0].y + i3*u[3][0].y;
    o0.z += i0*u[0][0].z + i1*u[1][0].z + i2*u[2][0].z + i3*u[3][0].z;
    o0.w += i0*u[0][0].w + i1*u[1][0].w + i2*u[2][0].w + i3*u[3][0].w;
    o1.x += i0*u[0][1].x + i1*u[1][1].x + i2*u[2][1].x + i3*u[3][1].x;
    o1.y += i0*u[0][1].y + i1*u[1][1].y + i2*u[2][1].y + i3*u[3][1].y;
    o1.z += i0*u[0][1].z + i1*u[1][1].z + i2*u[2][1].z + i3*u[3][1].z;
    o1.w += i0*u[0][1].w + i1*u[1][1].w + i2*u[2][1].w + i3*u[3][1].w;
    *(float4*)(dp) = o0;
    *(float4*)(dp + 4) = o1;
}

// ---------------- output heads ----------------------------------------------
__global__ __launch_bounds__(256) void heads_kernel(
    const float* __restrict__ fc,
    const float* __restrict__ Wb, const float* __restrict__ bb,
    const float* __restrict__ Ws, const float* __restrict__ bs,
    float* __restrict__ out)
{
    int n = blockIdx.x * 8 + (threadIdx.x >> 5);
    if (n >= N_NODES) return;
    int lane = threadIdx.x & 31;

    float acc[7] = {0.f, 0.f, 0.f, 0.f, 0.f, 0.f, 0.f};
    #pragma unroll
    for (int i = 0; i < 8; i++) {
        int k = i * 32 + lane;
        float v = fc[(size_t)n * 256 + k];
        acc[0] += v * Wb[k * 2 + 0];
        acc[1] += v * Wb[k * 2 + 1];
        #pragma unroll
        for (int j = 0; j < 5; j++) acc[2 + j] += v * Ws[k * 5 + j];
    }
    #pragma unroll
    for (int off = 16; off > 0; off >>= 1) {
        #pragma unroll
        for (int j = 0; j < 7; j++) acc[j] += __shfl_xor_sync(0xffffffffu, acc[j], off);
    }
    if (lane == 0) {
        out[(size_t)n * 2 + 0] = acc[0] + bb[0];
        out[(size_t)n * 2 + 1] = acc[1] + bb[1];
        float* sev = out + (size_t)N_NODES * 2 + (size_t)n * 5;
        #pragma unroll
        for (int j = 0; j < 5; j++) sev[j] = acc[2 + j] + bs[j];
    }
}

// ---------------- launch ------------------------------------------------------
static inline void cvt(const float* in, float* out, int n) {
    cvt_tf32_kernel<<<(n / 4 + 255) / 256, 256>>>(in, out, n);
}

extern "C" void kernel_launch(void* const* d_in, const int* in_sizes, int n_in,
                              void* d_out, int out_size)
{
    const float* x        = (const float*)d_in[0];
    const int*   ei       = (const int*)d_in[1];
    const float* W1       = (const float*)d_in[2];
    const float* att_src1 = (const float*)d_in[3];
    const float* att_dst1 = (const float*)d_in[4];
    const float* Wres1    = (const float*)d_in[5];
    const float* b1       = (const float*)d_in[6];
    const float* W2       = (const float*)d_in[7];
    const float* att_src2 = (const float*)d_in[8];
    const float* att_dst2 = (const float*)d_in[9];
    const float* Wres2    = (const float*)d_in[10];
    const float* b2       = (const float*)d_in[11];
    const float* Wfc      = (const float*)d_in[12];
    const float* bfc      = (const float*)d_in[13];
    const float* Wb       = (const float*)d_in[14];
    const float* bb       = (const float*)d_in[15];
    const float* Ws       = (const float*)d_in[16];
    const float* bs       = (const float*)d_in[17];
    float* out = (float*)d_out;

    const int* src = ei;
    const int* dst = ei + N_EDGES;

    float *xl, *h1, *h2, *fc1, *fc2, *at, *wt, *wt2, *asrc, *adst;
    int *deg, *off, *cur, *esrc;
    cudaGetSymbolAddress((void**)&xl,   g_xl);
    cudaGetSymbolAddress((void**)&h1,   g_h1);
    cudaGetSymbolAddress((void**)&h2,   g_h2);
    cudaGetSymbolAddress((void**)&fc1,  g_fc1);
    cudaGetSymbolAddress((void**)&fc2,  g_fc2);
    cudaGetSymbolAddress((void**)&at,   g_at);
    cudaGetSymbolAddress((void**)&wt,   g_wt);
    cudaGetSymbolAddress((void**)&wt2,  g_wt2);
    cudaGetSymbolAddress((void**)&asrc, g_asrc);
    cudaGetSymbolAddress((void**)&adst, g_adst);
    cudaGetSymbolAddress((void**)&deg,  g_deg);
    cudaGetSymbolAddress((void**)&off,  g_off);
    cudaGetSymbolAddress((void**)&cur,  g_cur);
    cudaGetSymbolAddress((void**)&esrc, g_esrc);

    static bool attr_done = false;
    if (!attr_done) {
        cudaFuncSetAttribute(mma_gemm_kernel<0>,
                             cudaFuncAttributeMaxDynamicSharedMemorySize, GEMM_SMEM);
        cudaFuncSetAttribute(mma_gemm_kernel<1>,
                             cudaFuncAttributeMaxDynamicSharedMemorySize, GEMM_SMEM);
        attr_done = true;
    }

    const int mRows = (N_NODES + GBM - 1) / GBM;
    const int attnBlocks = (N_NODES * 4 + 7) / 8;
    const int nodeBlocks = (N_NODES + 7) / 8;
    const int edgeBlocks = (N_EDGES + 255) / 256;

    // launches 1-2: conversions for first GEMM
    cvt(x, at, N_NODES * 768);
    cvt(Wres1, wt, 768 * 1024);

    // launches 3-5: CSR build (graph constant across layers; built once)
    zero_deg_kernel<<<(N_NODES + 255) / 256, 256>>>(deg);
    hist_kernel<<<edgeBlocks, 256>>>(dst, deg);
    scan_kernel<<<1, 256>>>(deg, off, cur);

    // launch 6: big GEMM (profiled by ncu -s 5 -c 1)
    {
        dim3 grid(1024 / GBN, mRows);
        mma_gemm_kernel<0><<<grid, 256, GEMM_SMEM>>>(at, wt, b1, h1, N_NODES, 1024, 768);
        cvt(W1, wt2, 768 * 1024);
        mma_gemm_kernel<0><<<grid, 256, GEMM_SMEM>>>(at, wt2, nullptr, xl, N_NODES, 1024, 768);
    }
    scatter_kernel<<<edgeBlocks, 256>>>(src, dst, cur, esrc);

    // ===== layer 1 aggregation =====
    attn_scores_kernel<<<attnBlocks, 256>>>(xl, att_src1, att_dst1, asrc, adst);
    gat_aggregate1_kernel<<<attnBlocks, 256>>>(off, esrc, xl, asrc, adst, h1);

    // ===== layer 2: h2 = mean_heads(agg) + h1@Wres2 + b2 =====
    cvt(h1, at, N_NODES * 1024);
    {
        dim3 grid(256 / GBN, mRows);
        cvt(Wres2, wt, 1024 * 256);
        mma_gemm_kernel<0><<<grid, 256, GEMM_SMEM>>>(at, wt, b2, h2, N_NODES, 256, 1024);
    }
    {
        dim3 grid(1024 / GBN, mRows);
        cvt(W2, wt2, 1024 * 1024);
        mma_gemm_kernel<0><<<grid, 256, GEMM_SMEM>>>(at, wt2, nullptr, xl, N_NODES, 1024, 1024);
    }
    attn_scores_kernel<<<attnBlocks, 256>>>(xl, att_src2, att_dst2, asrc, adst);
    gat_aggregate2_kernel<<<nodeBlocks, 256>>>(off, esrc, xl, asrc, adst, h2);

    // ===== shared FC twice =====
    {
        dim3 grid(256 / GBN, mRows);
        cvt(h2, at, N_NODES * 256);
        cvt(Wfc, wt, 256 * 256);
        mma_gemm_kernel<1><<<grid, 256, GEMM_SMEM>>>(at, wt, bfc, fc1, N_NODES, 256, 256);
        cvt(fc1, at, N_NODES * 256);
        mma_gemm_kernel<0><<<grid, 256, GEMM_SMEM>>>(at, wt, bfc, fc2, N_NODES, 256, 256);
    }

    // ===== heads =====
    heads_kernel<<<nodeBlocks, 256>>>(fc2, Wb, bb, Ws, bs, out);
}

// round 7
// speedup vs baseline: 5.7659x; 1.4723x over previous
#include <cuda_runtime.h>
#include <cuda_fp16.h>
#include <cstdint>

#define N_NODES 20000
#define N_EDGES 320000

// ---------------- scratch (device globals; no allocation allowed) ----------
__device__ float  g_xl[N_NODES * 1024];
__device__ float  g_h1[N_NODES * 1024];
__device__ float  g_h2[N_NODES * 256];
__device__ float  g_fc1[N_NODES * 256];
__device__ float  g_fc2[N_NODES * 256];
__device__ __half g_at[N_NODES * 1024];   // fp16 activations (A operand)
__device__ __half g_wt[1024 * 1024];      // fp16 transposed weights [N,K] buf A
__device__ __half g_wt2[1024 * 1024];     // fp16 transposed weights [N,K] buf B
__device__ float  g_asrc[N_NODES * 4];
__device__ float  g_adst[N_NODES * 4];
__device__ int    g_deg[N_NODES];
__device__ int    g_off[N_NODES + 1];
__device__ int    g_cur[N_NODES];
__device__ int    g_esrc[N_EDGES];        // src node of each edge, grouped by dst

// ---------------- helpers ---------------------------------------------------
__device__ __forceinline__ void mma_f16(float* d, const unsigned* a, const unsigned* b) {
    asm volatile(
        "mma.sync.aligned.m16n8k16.row.col.f32.f16.f16.f32 "
        "{%0,%1,%2,%3}, {%4,%5,%6,%7}, {%8,%9}, {%0,%1,%2,%3};"
        : "+f"(d[0]), "+f"(d[1]), "+f"(d[2]), "+f"(d[3])
        : "r"(a[0]), "r"(a[1]), "r"(a[2]), "r"(a[3]), "r"(b[0]), "r"(b[1]));
}

__device__ __forceinline__ void cp16(void* smem, const void* gmem, bool pred) {
    unsigned sa = (unsigned)__cvta_generic_to_shared(smem);
    int sz = pred ? 16 : 0;
    asm volatile("cp.async.cg.shared.global [%0], [%1], 16, %2;"
                 :: "r"(sa), "l"(gmem), "r"(sz));
}

// ---------------- fp16 conversion passes -------------------------------------
// activations: fp32 [M,K] -> fp16 [M,K]; n % 8 == 0
__global__ void cvt_fp16_kernel(const float* __restrict__ in, __half* __restrict__ out, int n) {
    int i = (blockIdx.x * blockDim.x + threadIdx.x) * 8;
    if (i >= n) return;
    float4 v0 = *(const float4*)(in + i);
    float4 v1 = *(const float4*)(in + i + 4);
    __half2 h[4];
    h[0] = __floats2half2_rn(v0.x, v0.y);
    h[1] = __floats2half2_rn(v0.z, v0.w);
    h[2] = __floats2half2_rn(v1.x, v1.y);
    h[3] = __floats2half2_rn(v1.z, v1.w);
    *(uint4*)(out + i) = *(uint4*)h;
}

// weights: W[K,N] fp32 -> Wt[N,K] fp16. K,N multiples of 32.
__global__ void cvt_fp16_transpose_kernel(const float* __restrict__ in, __half* __restrict__ out,
                                          int K, int N) {
    __shared__ float t[32][33];
    int k0 = blockIdx.y * 32, n0 = blockIdx.x * 32;
    int tx = threadIdx.x, ty = threadIdx.y;  // 32 x 8
    #pragma unroll
    for (int j = 0; j < 32; j += 8)
        t[ty + j][tx] = in[(size_t)(k0 + ty + j) * N + n0 + tx];
    __syncthreads();
    #pragma unroll
    for (int j = 0; j < 32; j += 8)
        out[(size_t)(n0 + ty + j) * K + k0 + tx] = __float2half_rn(t[tx][ty + j]);
}

// ---------------- CSR build ---------------------------------------------------
__global__ void zero_deg_kernel(int* __restrict__ deg) {
    int i = blockIdx.x * blockDim.x + threadIdx.x;
    if (i < N_NODES) deg[i] = 0;
}

__global__ void hist_kernel(const int* __restrict__ dst, int* __restrict__ deg) {
    int e = blockIdx.x * blockDim.x + threadIdx.x;
    if (e < N_EDGES) atomicAdd(&deg[dst[e]], 1);
}

__global__ __launch_bounds__(256) void scan_kernel(
    const int* __restrict__ deg, int* __restrict__ off, int* __restrict__ cur)
{
    __shared__ int partial[256];
    const int tid = threadIdx.x;
    const int CH = (N_NODES + 255) / 256;
    const int base = tid * CH;

    int s = 0;
    for (int j = 0; j < CH; j++) {
        int i = base + j;
        if (i < N_NODES) s += deg[i];
    }
    partial[tid] = s;
    __syncthreads();
    for (int o = 1; o < 256; o <<= 1) {
        int v = (tid >= o) ? partial[tid - o] : 0;
        __syncthreads();
        partial[tid] += v;
        __syncthreads();
    }
    int run = partial[tid] - s;
    for (int j = 0; j < CH; j++) {
        int i = base + j;
        if (i < N_NODES) {
            off[i] = run;
            cur[i] = run;
            run += deg[i];
        }
    }
    if (tid == 255) off[N_NODES] = run;
}

__global__ void scatter_kernel(const int* __restrict__ src, const int* __restrict__ dst,
                               int* __restrict__ cur, int* __restrict__ esrc) {
    int e = blockIdx.x * blockDim.x + threadIdx.x;
    if (e >= N_EDGES) return;
    int pos = atomicAdd(&cur[dst[e]], 1);
    esrc[pos] = src[e];
}

// ---------------- fp16 tensor-core GEMM, cp.async 4-stage pipeline -----------
// C[M,N] = A[M,K] @ Bt[N,K]^T (+bias, +act). A fp16 [M,K] row-major,
// Bt fp16 [N,K] (pre-transposed). CTA tile 128x128, K-tile = 32 halves.
// 256 threads = 8 warps (2x4), warp tile 64x32, mma m16n8k16.
// Requires N % 128 == 0, K % 32 == 0; M guarded.
#define GBM 128
#define GBN 128
#define HK 32                   // halves per K-tile
#define ROWW 20                 // words per smem row (32 halves + 8 pad)
#define TSZW (128 * ROWW)       // words per (A or B) tile = 2560
#define STAGES 4
#define GEMM_SMEM (STAGES * 2 * TSZW * 4)   // 81920 bytes

template <int ACT>  // 0: none, 1: leaky_relu(0.01)
__global__ __launch_bounds__(256, 2) void mma_gemm_kernel(
    const __half* __restrict__ A, const __half* __restrict__ Bt,
    const float* __restrict__ bias, float* __restrict__ C,
    int M, int N, int K)
{
    extern __shared__ unsigned smem[];
    unsigned* As = smem;                       // [STAGES][TSZW]
    unsigned* Bs = smem + STAGES * TSZW;       // [STAGES][TSZW]

    const int tid = threadIdx.x;
    const int warp = tid >> 5, lane = tid & 31;
    const int g = lane >> 2, tg = lane & 3;
    const int wr = (warp >> 2) * 64;
    const int wc = (warp & 3) * 32;

    const int bm = blockIdx.y, bn = blockIdx.x;

    // staging: thread covers (row = tid>>1, halves colH..colH+15) of 128x32 tile
    const int rowS = tid >> 1;
    const int colH = (tid & 1) * 16;
    const int rowA = bm * GBM + rowS;
    const bool avalid = rowA < M;
    const __half* Ap = avalid ? (A + (size_t)rowA * K + colH) : A;
    const __half* Bp = Bt + (size_t)(bn * GBN + rowS) * K + colH;
    const int sOff = rowS * ROWW + (tid & 1) * 8;   // words

    const int KT = K / HK;

    float acc[4][4][4];
    #pragma unroll
    for (int mt = 0; mt < 4; mt++)
        #pragma unroll
        for (int nt = 0; nt < 4; nt++)
            #pragma unroll
            for (int i = 0; i < 4; i++) acc[mt][nt][i] = 0.0f;

    #pragma unroll
    for (int kt = 0; kt < STAGES - 1; kt++) {
        if (kt < KT) {
            unsigned* as = As + (kt % STAGES) * TSZW;
            unsigned* bs = Bs + (kt % STAGES) * TSZW;
            const __half* ap = Ap + (avalid ? kt * HK : 0);
            const __half* bp = Bp + kt * HK;
            cp16(&as[sOff],     ap,     avalid);
            cp16(&as[sOff + 4], ap + 8, avalid);
            cp16(&bs[sOff],     bp,     true);
            cp16(&bs[sOff + 4], bp + 8, true);
        }
        asm volatile("cp.async.commit_group;");
    }

    for (int kt = 0; kt < KT; kt++) {
        int kf = kt + STAGES - 1;
        if (kf < KT) {
            unsigned* as = As + (kf % STAGES) * TSZW;
            unsigned* bs = Bs + (kf % STAGES) * TSZW;
            const __half* ap = Ap + (avalid ? kf * HK : 0);
            const __half* bp = Bp + kf * HK;
            cp16(&as[sOff],     ap,     avalid);
            cp16(&as[sOff + 4], ap + 8, avalid);
            cp16(&bs[sOff],     bp,     true);
            cp16(&bs[sOff + 4], bp + 8, true);
        }
        asm volatile("cp.async.commit_group;");

        asm volatile("cp.async.wait_group %0;" :: "n"(STAGES - 2));
        __syncthreads();

        const unsigned* as = As + (kt % STAGES) * TSZW;
        const unsigned* bs = Bs + (kt % STAGES) * TSZW;

        // 2 k-steps of 16 halves
        #pragma unroll
        for (int kk = 0; kk < 2; kk++) {
            unsigned af[4][4];
            unsigned bf[4][2];
            #pragma unroll
            for (int mt = 0; mt < 4; mt++) {
                int r0 = wr + mt * 16 + g;
                af[mt][0] = as[(r0    ) * ROWW + kk * 8 + tg];
                af[mt][1] = as[(r0 + 8) * ROWW + kk * 8 + tg];
                af[mt][2] = as[(r0    ) * ROWW + kk * 8 + tg + 4];
                af[mt][3] = as[(r0 + 8) * ROWW + kk * 8 + tg + 4];
            }
            #pragma unroll
            for (int nt = 0; nt < 4; nt++) {
                int rb = wc + nt * 8 + g;
                bf[nt][0] = bs[rb * ROWW + kk * 8 + tg];
                bf[nt][1] = bs[rb * ROWW + kk * 8 + tg + 4];
            }
            #pragma unroll
            for (int mt = 0; mt < 4; mt++)
                #pragma unroll
                for (int nt = 0; nt < 4; nt++)
                    mma_f16(acc[mt][nt], af[mt], bf[nt]);
        }
        __syncthreads();
    }

    float bv[4][2];
    #pragma unroll
    for (int nt = 0; nt < 4; nt++) {
        int col = bn * GBN + wc + nt * 8 + 2 * tg;
        bv[nt][0] = bias ? bias[col] : 0.0f;
        bv[nt][1] = bias ? bias[col + 1] : 0.0f;
    }

    #pragma unroll
    for (int mt = 0; mt < 4; mt++) {
        #pragma unroll
        for (int i = 0; i < 2; i++) {
            int row = bm * GBM + wr + mt * 16 + g + i * 8;
            if (row >= M) continue;
            float* Crow = C + (size_t)row * N + bn * GBN + wc;
            #pragma unroll
            for (int nt = 0; nt < 4; nt++) {
                float2 v;
                v.x = acc[mt][nt][i * 2 + 0] + bv[nt][0];
                v.y = acc[mt][nt][i * 2 + 1] + bv[nt][1];
                if (ACT == 1) {
                    v.x = v.x > 0.f ? v.x : 0.01f * v.x;
                    v.y = v.y > 0.f ? v.y : 0.01f * v.y;
                }
                *(float2*)(Crow + nt * 8 + 2 * tg) = v;
            }
        }
    }
}

// ---------------- attention scores -------------------------------------------
__global__ __launch_bounds__(256) void attn_scores_kernel(
    const float* __restrict__ xl,
    const float* __restrict__ att_src, const float* __restrict__ att_dst,
    float* __restrict__ asrc, float* __restrict__ adst)
{
    int task = blockIdx.x * 8 + (threadIdx.x >> 5);
    if (task >= N_NODES * 4) return;
    int lane = threadIdx.x & 31;
    int n = task >> 2, h = task & 3;

    const float* xp = xl + (size_t)n * 1024 + h * 256 + lane * 8;
    const float* sp = att_src + h * 256 + lane * 8;
    const float* dp = att_dst + h * 256 + lane * 8;

    float s1 = 0.f, s2 = 0.f;
    #pragma unroll
    for (int q = 0; q < 8; q += 4) {
        float4 v = *(const float4*)(xp + q);
        float4 a = *(const float4*)(sp + q);
        float4 b = *(const float4*)(dp + q);
        s1 += v.x * a.x + v.y * a.y + v.z * a.z + v.w * a.w;
        s2 += v.x * b.x + v.y * b.y + v.z * b.z + v.w * b.w;
    }
    #pragma unroll
    for (int off = 16; off > 0; off >>= 1) {
        s1 += __shfl_xor_sync(0xffffffffu, s1, off);
        s2 += __shfl_xor_sync(0xffffffffu, s2, off);
    }
    if (lane == 0) {
        asrc[task] = s1;
        adst[task] = s2;
    }
}

// ---------------- layer1 aggregation (concat): gather, no atomics -------------
__global__ __launch_bounds__(256) void gat_aggregate1_kernel(
    const int* __restrict__ off, const int* __restrict__ esrc,
    const float* __restrict__ xl, const float* __restrict__ asrc,
    const float* __restrict__ adst, float* __restrict__ h1)
{
    int task = blockIdx.x * 8 + (threadIdx.x >> 5);
    if (task >= N_NODES * 4) return;
    int lane = threadIdx.x & 31;
    int n = task >> 2, h = task & 3;

    const float ad = adst[n * 4 + h];
    const int j0 = off[n], j1 = off[n + 1];

    float4 u0 = make_float4(0.f, 0.f, 0.f, 0.f);
    float4 u1 = make_float4(0.f, 0.f, 0.f, 0.f);
    float ssum = 0.f;

    for (int j = j0; j < j1; j++) {
        int s = esrc[j];
        float a = asrc[s * 4 + h] + ad;
        a = a > 0.f ? a : 0.2f * a;
        float w = __expf(a);
        ssum += w;
        const float* sp = xl + (size_t)s * 1024 + h * 256 + lane * 8;
        float4 v0 = *(const float4*)(sp);
        float4 v1 = *(const float4*)(sp + 4);
        u0.x += w * v0.x; u0.y += w * v0.y; u0.z += w * v0.z; u0.w += w * v0.w;
        u1.x += w * v1.x; u1.y += w * v1.y; u1.z += w * v1.z; u1.w += w * v1.w;
    }

    float inv = 1.0f / (ssum + 1e-16f);
    float* dp = h1 + (size_t)n * 1024 + h * 256 + lane * 8;
    float4 o0 = *(const float4*)(dp);
    float4 o1 = *(const float4*)(dp + 4);
    o0.x += u0.x * inv; o0.y += u0.y * inv; o0.z += u0.z * inv; o0.w += u0.w * inv;
    o1.x += u1.x * inv; o1.y += u1.y * inv; o1.z += u1.z * inv; o1.w += u1.w * inv;
    *(float4*)(dp) = o0;
    *(float4*)(dp + 4) = o1;
}

// ---------------- layer2 aggregation (head-mean): gather, no atomics ----------
__global__ __launch_bounds__(256) void gat_aggregate2_kernel(
    const int* __restrict__ off, const int* __restrict__ esrc,
    const float* __restrict__ xl, const float* __restrict__ asrc,
    const float* __restrict__ adst, float* __restrict__ h2)
{
    int n = blockIdx.x * 8 + (threadIdx.x >> 5);
    if (n >= N_NODES) return;
    int lane = threadIdx.x & 31;

    float4 ad = *(const float4*)(adst + n * 4);
    const int j0 = off[n], j1 = off[n + 1];

    float4 u[4][2];
    #pragma unroll
    for (int h = 0; h < 4; h++) {
        u[h][0] = make_float4(0.f, 0.f, 0.f, 0.f);
        u[h][1] = make_float4(0.f, 0.f, 0.f, 0.f);
    }
    float4 ssum = make_float4(0.f, 0.f, 0.f, 0.f);

    for (int j = j0; j < j1; j++) {
        int s = esrc[j];
        float4 as = *(const float4*)(asrc + s * 4);
        float4 e;
        e.x = as.x + ad.x; e.x = e.x > 0.f ? e.x : 0.2f * e.x;
        e.y = as.y + ad.y; e.y = e.y > 0.f ? e.y : 0.2f * e.y;
        e.z = as.z + ad.z; e.z = e.z > 0.f ? e.z : 0.2f * e.z;
        e.w = as.w + ad.w; e.w = e.w > 0.f ? e.w : 0.2f * e.w;
        float w0 = __expf(e.x), w1 = __expf(e.y), w2 = __expf(e.z), w3 = __expf(e.w);
        ssum.x += w0; ssum.y += w1; ssum.z += w2; ssum.w += w3;

        const float* sp = xl + (size_t)s * 1024 + lane * 8;
        float w[4] = {w0, w1, w2, w3};
        #pragma unroll
        for (int h = 0; h < 4; h++) {
            float4 v0 = *(const float4*)(sp + h * 256);
            float4 v1 = *(const float4*)(sp + h * 256 + 4);
            u[h][0].x += w[h] * v0.x; u[h][0].y += w[h] * v0.y;
            u[h][0].z += w[h] * v0.z; u[h][0].w += w[h] * v0.w;
            u[h][1].x += w[h] * v1.x; u[h][1].y += w[h] * v1.y;
            u[h][1].z += w[h] * v1.z; u[h][1].w += w[h] * v1.w;
        }
    }

    float i0 = 0.25f / (ssum.x + 1e-16f);
    float i1 = 0.25f / (ssum.y + 1e-16f);
    float i2 = 0.25f / (ssum.z + 1e-16f);
    float i3 = 0.25f / (ssum.w + 1e-16f);

    float* dp = h2 + (size_t)n * 256 + lane * 8;
    float4 o0 = *(const float4*)(dp);
    float4 o1 = *(const float4*)(dp + 4);
    o0.x += i0*u[0][0].x + i1*u[1][0].x + i2*u[2][0].x + i3*u[3][0].x;
    o0.y += i0*u[0][0].y + i1*u[1][0].y + i2*u[2][0].y + i3*u[3][0].y;
    o0.z += i0*u[0][0].z + i1*u[1][0].z + i2*u[2][0].z + i3*u[3][0].z;
    o0.w += i0*u[0][0].w + i1*u[1][0].w + i2*u[2][0].w + i3*u[3][0].w;
    o1.x += i0*u[0][1].x + i1*u[1][1].x + i2*u[2][1].x + i3*u[3][1].x;
    o1.y += i0*u[0][1].y + i1*u[1][1].y + i2*u[2][1].y + i3*u[3][1].y;
    o1.z += i0*u[0][1].z + i1*u[1][1].z + i2*u[2][1].z + i3*u[3][1].z;
    o1.w += i0*u[0][1].w + i1*u[1][1].w + i2*u[2][1].w + i3*u[3][1].w;
    *(float4*)(dp) = o0;
    *(float4*)(dp + 4) = o1;
}

// ---------------- output heads ----------------------------------------------
__global__ __launch_bounds__(256) void heads_kernel(
    const float* __restrict__ fc,
    const float* __restrict__ Wb, const float* __restrict__ bb,
    const float* __restrict__ Ws, const float* __restrict__ bs,
    float* __restrict__ out)
{
    int n = blockIdx.x * 8 + (threadIdx.x >> 5);
    if (n >= N_NODES) return;
    int lane = threadIdx.x & 31;

    float acc[7] = {0.f, 0.f, 0.f, 0.f, 0.f, 0.f, 0.f};
    #pragma unroll
    for (int i = 0; i < 8; i++) {
        int k = i * 32 + lane;
        float v = fc[(size_t)n * 256 + k];
        acc[0] += v * Wb[k * 2 + 0];
        acc[1] += v * Wb[k * 2 + 1];
        #pragma unroll
        for (int j = 0; j < 5; j++) acc[2 + j] += v * Ws[k * 5 + j];
    }
    #pragma unroll
    for (int off = 16; off > 0; off >>= 1) {
        #pragma unroll
        for (int j = 0; j < 7; j++) acc[j] += __shfl_xor_sync(0xffffffffu, acc[j], off);
    }
    if (lane == 0) {
        out[(size_t)n * 2 + 0] = acc[0] + bb[0];
        out[(size_t)n * 2 + 1] = acc[1] + bb[1];
        float* sev = out + (size_t)N_NODES * 2 + (size_t)n * 5;
        #pragma unroll
        for (int j = 0; j < 5; j++) sev[j] = acc[2 + j] + bs[j];
    }
}

// ---------------- launch ------------------------------------------------------
static inline void cvt(const float* in, __half* out, int n) {
    cvt_fp16_kernel<<<(n / 8 + 255) / 256, 256>>>(in, out, n);
}
static inline void cvtT(const float* W, __half* out, int K, int N) {
    dim3 grid(N / 32, K / 32);
    cvt_fp16_transpose_kernel<<<grid, dim3(32, 8)>>>(W, out, K, N);
}

extern "C" void kernel_launch(void* const* d_in, const int* in_sizes, int n_in,
                              void* d_out, int out_size)
{
    const float* x        = (const float*)d_in[0];
    const int*   ei       = (const int*)d_in[1];
    const float* W1       = (const float*)d_in[2];
    const float* att_src1 = (const float*)d_in[3];
    const float* att_dst1 = (const float*)d_in[4];
    const float* Wres1    = (const float*)d_in[5];
    const float* b1       = (const float*)d_in[6];
    const float* W2       = (const float*)d_in[7];
    const float* att_src2 = (const float*)d_in[8];
    const float* att_dst2 = (const float*)d_in[9];
    const float* Wres2    = (const float*)d_in[10];
    const float* b2       = (const float*)d_in[11];
    const float* Wfc      = (const float*)d_in[12];
    const float* bfc      = (const float*)d_in[13];
    const float* Wb       = (const float*)d_in[14];
    const float* bb       = (const float*)d_in[15];
    const float* Ws       = (const float*)d_in[16];
    const float* bs       = (const float*)d_in[17];
    float* out = (float*)d_out;

    const int* src = ei;
    const int* dst = ei + N_EDGES;

    float *xl, *h1, *h2, *fc1, *fc2, *asrc, *adst;
    __half *at, *wt, *wt2;
    int *deg, *off, *cur, *esrc;
    cudaGetSymbolAddress((void**)&xl,   g_xl);
    cudaGetSymbolAddress((void**)&h1,   g_h1);
    cudaGetSymbolAddress((void**)&h2,   g_h2);
    cudaGetSymbolAddress((void**)&fc1,  g_fc1);
    cudaGetSymbolAddress((void**)&fc2,  g_fc2);
    cudaGetSymbolAddress((void**)&at,   g_at);
    cudaGetSymbolAddress((void**)&wt,   g_wt);
    cudaGetSymbolAddress((void**)&wt2,  g_wt2);
    cudaGetSymbolAddress((void**)&asrc, g_asrc);
    cudaGetSymbolAddress((void**)&adst, g_adst);
    cudaGetSymbolAddress((void**)&deg,  g_deg);
    cudaGetSymbolAddress((void**)&off,  g_off);
    cudaGetSymbolAddress((void**)&cur,  g_cur);
    cudaGetSymbolAddress((void**)&esrc, g_esrc);

    static bool attr_done = false;
    if (!attr_done) {
        cudaFuncSetAttribute(mma_gemm_kernel<0>,
                             cudaFuncAttributeMaxDynamicSharedMemorySize, GEMM_SMEM);
        cudaFuncSetAttribute(mma_gemm_kernel<1>,
                             cudaFuncAttributeMaxDynamicSharedMemorySize, GEMM_SMEM);
        attr_done = true;
    }

    const int mRows = (N_NODES + GBM - 1) / GBM;
    const int attnBlocks = (N_NODES * 4 + 7) / 8;
    const int nodeBlocks = (N_NODES + 7) / 8;
    const int edgeBlocks = (N_EDGES + 255) / 256;

    // conversions + CSR build
    cvt(x, at, N_NODES * 768);
    cvtT(Wres1, wt, 768, 1024);
    zero_deg_kernel<<<(N_NODES + 255) / 256, 256>>>(deg);
    hist_kernel<<<edgeBlocks, 256>>>(dst, deg);
    scan_kernel<<<1, 256>>>(deg, off, cur);

    // ===== layer 1 (concat=true): h1 = agg + x@Wres1 + b1 =====
    {
        dim3 grid(1024 / GBN, mRows);
        mma_gemm_kernel<0><<<grid, 256, GEMM_SMEM>>>(at, wt, b1, h1, N_NODES, 1024, 768);
        cvtT(W1, wt2, 768, 1024);
        mma_gemm_kernel<0><<<grid, 256, GEMM_SMEM>>>(at, wt2, nullptr, xl, N_NODES, 1024, 768);
    }
    scatter_kernel<<<edgeBlocks, 256>>>(src, dst, cur, esrc);

    attn_scores_kernel<<<attnBlocks, 256>>>(xl, att_src1, att_dst1, asrc, adst);
    gat_aggregate1_kernel<<<attnBlocks, 256>>>(off, esrc, xl, asrc, adst, h1);

    // ===== layer 2 (concat=false): h2 = mean_heads(agg) + h1@Wres2 + b2 =====
    cvt(h1, at, N_NODES * 1024);
    {
        dim3 grid(256 / GBN, mRows);
        cvtT(Wres2, wt, 1024, 256);
        mma_gemm_kernel<0><<<grid, 256, GEMM_SMEM>>>(at, wt, b2, h2, N_NODES, 256, 1024);
    }
    {
        dim3 grid(1024 / GBN, mRows);
        cvtT(W2, wt2, 1024, 1024);
        mma_gemm_kernel<0><<<grid, 256, GEMM_SMEM>>>(at, wt2, nullptr, xl, N_NODES, 1024, 1024);
    }
    attn_scores_kernel<<<attnBlocks, 256>>>(xl, att_src2, att_dst2, asrc, adst);
    gat_aggregate2_kernel<<<nodeBlocks, 256>>>(off, esrc, xl, asrc, adst, h2);

    // ===== shared FC twice =====
    {
        dim3 grid(256 / GBN, mRows);
        cvt(h2, at, N_NODES * 256);
        cvtT(Wfc, wt, 256, 256);
        mma_gemm_kernel<1><<<grid, 256, GEMM_SMEM>>>(at, wt, bfc, fc1, N_NODES, 256, 256);
        cvt(fc1, at, N_NODES * 256);
        mma_gemm_kernel<0><<<grid, 256, GEMM_SMEM>>>(at, wt, bfc, fc2, N_NODES, 256, 256);
    }

    // ===== heads =====
    heads_kernel<<<nodeBlocks, 256>>>(fc2, Wb, bb, Ws, bs, out);
}

// round 8
// speedup vs baseline: 6.5615x; 1.1380x over previous
#include <cuda_runtime.h>
#include <cuda_fp16.h>
#include <cstdint>

#define N_NODES 20000
#define N_EDGES 320000

// ---------------- scratch (device globals; no allocation allowed) ----------
__device__ __half g_xl16[N_NODES * 1024];  // fp16 per-head features (gather source)
__device__ float  g_h1[N_NODES * 1024];    // layer1 residual GEMM output (read once)
__device__ float  g_h2[N_NODES * 256];     // layer2 residual GEMM output (read once)
__device__ __half g_fc1h[N_NODES * 256];   // fp16 fc1 output
__device__ float  g_fc2[N_NODES * 256];
__device__ __half g_at[N_NODES * 1024];    // fp16 A operand (x, then h1, then h2)
__device__ __half g_wt[1024 * 1024];       // fp16 transposed weights buf A
__device__ __half g_wt2[1024 * 1024];      // fp16 transposed weights buf B
__device__ float  g_asrc[N_NODES * 4];
__device__ float  g_adst[N_NODES * 4];
__device__ int    g_deg[N_NODES];
__device__ int    g_off[N_NODES + 1];
__device__ int    g_cur[N_NODES];
__device__ int    g_esrc[N_EDGES];         // src node of each edge, grouped by dst

// ---------------- helpers ---------------------------------------------------
__device__ __forceinline__ void mma_f16(float* d, const unsigned* a, const unsigned* b) {
    asm volatile(
        "mma.sync.aligned.m16n8k16.row.col.f32.f16.f16.f32 "
        "{%0,%1,%2,%3}, {%4,%5,%6,%7}, {%8,%9}, {%0,%1,%2,%3};"
        : "+f"(d[0]), "+f"(d[1]), "+f"(d[2]), "+f"(d[3])
        : "r"(a[0]), "r"(a[1]), "r"(a[2]), "r"(a[3]), "r"(b[0]), "r"(b[1]));
}

__device__ __forceinline__ void cp16(void* smem, const void* gmem, bool pred) {
    unsigned sa = (unsigned)__cvta_generic_to_shared(smem);
    int sz = pred ? 16 : 0;
    asm volatile("cp.async.cg.shared.global [%0], [%1], 16, %2;"
                 :: "r"(sa), "l"(gmem), "r"(sz));
}

// ---------------- fp16 conversion passes -------------------------------------
__global__ void cvt_fp16_kernel(const float* __restrict__ in, __half* __restrict__ out, int n) {
    int i = (blockIdx.x * blockDim.x + threadIdx.x) * 8;
    if (i >= n) return;
    float4 v0 = *(const float4*)(in + i);
    float4 v1 = *(const float4*)(in + i + 4);
    __half2 h[4];
    h[0] = __floats2half2_rn(v0.x, v0.y);
    h[1] = __floats2half2_rn(v0.z, v0.w);
    h[2] = __floats2half2_rn(v1.x, v1.y);
    h[3] = __floats2half2_rn(v1.z, v1.w);
    *(uint4*)(out + i) = *(uint4*)h;
}

// weights: W[K,N] fp32 -> Wt[N,K] fp16. K,N multiples of 32.
__global__ void cvt_fp16_transpose_kernel(const float* __restrict__ in, __half* __restrict__ out,
                                          int K, int N) {
    __shared__ float t[32][33];
    int k0 = blockIdx.y * 32, n0 = blockIdx.x * 32;
    int tx = threadIdx.x, ty = threadIdx.y;  // 32 x 8
    #pragma unroll
    for (int j = 0; j < 32; j += 8)
        t[ty + j][tx] = in[(size_t)(k0 + ty + j) * N + n0 + tx];
    __syncthreads();
    #pragma unroll
    for (int j = 0; j < 32; j += 8)
        out[(size_t)(n0 + ty + j) * K + k0 + tx] = __float2half_rn(t[tx][ty + j]);
}

// ---------------- CSR build ---------------------------------------------------
__global__ void zero_deg_kernel(int* __restrict__ deg) {
    int i = blockIdx.x * blockDim.x + threadIdx.x;
    if (i < N_NODES) deg[i] = 0;
}

__global__ void hist_kernel(const int* __restrict__ dst, int* __restrict__ deg) {
    int e = blockIdx.x * blockDim.x + threadIdx.x;
    if (e < N_EDGES) atomicAdd(&deg[dst[e]], 1);
}

__global__ __launch_bounds__(256) void scan_kernel(
    const int* __restrict__ deg, int* __restrict__ off, int* __restrict__ cur)
{
    __shared__ int partial[256];
    const int tid = threadIdx.x;
    const int CH = (N_NODES + 255) / 256;
    const int base = tid * CH;

    int s = 0;
    for (int j = 0; j < CH; j++) {
        int i = base + j;
        if (i < N_NODES) s += deg[i];
    }
    partial[tid] = s;
    __syncthreads();
    for (int o = 1; o < 256; o <<= 1) {
        int v = (tid >= o) ? partial[tid - o] : 0;
        __syncthreads();
        partial[tid] += v;
        __syncthreads();
    }
    int run = partial[tid] - s;
    for (int j = 0; j < CH; j++) {
        int i = base + j;
        if (i < N_NODES) {
            off[i] = run;
            cur[i] = run;
            run += deg[i];
        }
    }
    if (tid == 255) off[N_NODES] = run;
}

__global__ void scatter_kernel(const int* __restrict__ src, const int* __restrict__ dst,
                               int* __restrict__ cur, int* __restrict__ esrc) {
    int e = blockIdx.x * blockDim.x + threadIdx.x;
    if (e >= N_EDGES) return;
    int pos = atomicAdd(&cur[dst[e]], 1);
    esrc[pos] = src[e];
}

// ---------------- fp16 tensor-core GEMM, cp.async 4-stage pipeline -----------
// C[M,N] = A[M,K] @ Bt[N,K]^T (+bias, +act). Outputs: C (fp32) and/or C16 (fp16),
// either may be null. CTA tile 128x128, K-tile 32 halves, 8 warps (2x4) 64x32,
// mma m16n8k16. Requires N % 128 == 0, K % 32 == 0; M guarded.
#define GBM 128
#define GBN 128
#define HK 32
#define ROWW 20
#define TSZW (128 * ROWW)
#define STAGES 4
#define GEMM_SMEM (STAGES * 2 * TSZW * 4)

template <int ACT>  // 0: none, 1: leaky_relu(0.01)
__global__ __launch_bounds__(256, 2) void mma_gemm_kernel(
    const __half* __restrict__ A, const __half* __restrict__ Bt,
    const float* __restrict__ bias, float* __restrict__ C,
    __half* __restrict__ C16, int M, int N, int K)
{
    extern __shared__ unsigned smem[];
    unsigned* As = smem;
    unsigned* Bs = smem + STAGES * TSZW;

    const int tid = threadIdx.x;
    const int warp = tid >> 5, lane = tid & 31;
    const int g = lane >> 2, tg = lane & 3;
    const int wr = (warp >> 2) * 64;
    const int wc = (warp & 3) * 32;

    const int bm = blockIdx.y, bn = blockIdx.x;

    const int rowS = tid >> 1;
    const int rowA = bm * GBM + rowS;
    const bool avalid = rowA < M;
    const __half* Ap = avalid ? (A + (size_t)rowA * K + (tid & 1) * 16) : A;
    const __half* Bp = Bt + (size_t)(bn * GBN + rowS) * K + (tid & 1) * 16;
    const int sOff = rowS * ROWW + (tid & 1) * 8;

    const int KT = K / HK;

    float acc[4][4][4];
    #pragma unroll
    for (int mt = 0; mt < 4; mt++)
        #pragma unroll
        for (int nt = 0; nt < 4; nt++)
            #pragma unroll
            for (int i = 0; i < 4; i++) acc[mt][nt][i] = 0.0f;

    #pragma unroll
    for (int kt = 0; kt < STAGES - 1; kt++) {
        if (kt < KT) {
            unsigned* as = As + (kt % STAGES) * TSZW;
            unsigned* bs = Bs + (kt % STAGES) * TSZW;
            const __half* ap = Ap + (avalid ? kt * HK : 0);
            const __half* bp = Bp + kt * HK;
            cp16(&as[sOff],     ap,     avalid);
            cp16(&as[sOff + 4], ap + 8, avalid);
            cp16(&bs[sOff],     bp,     true);
            cp16(&bs[sOff + 4], bp + 8, true);
        }
        asm volatile("cp.async.commit_group;");
    }

    for (int kt = 0; kt < KT; kt++) {
        int kf = kt + STAGES - 1;
        if (kf < KT) {
            unsigned* as = As + (kf % STAGES) * TSZW;
            unsigned* bs = Bs + (kf % STAGES) * TSZW;
            const __half* ap = Ap + (avalid ? kf * HK : 0);
            const __half* bp = Bp + kf * HK;
            cp16(&as[sOff],     ap,     avalid);
            cp16(&as[sOff + 4], ap + 8, avalid);
            cp16(&bs[sOff],     bp,     true);
            cp16(&bs[sOff + 4], bp + 8, true);
        }
        asm volatile("cp.async.commit_group;");

        asm volatile("cp.async.wait_group %0;" :: "n"(STAGES - 2));
        __syncthreads();

        const unsigned* as = As + (kt % STAGES) * TSZW;
        const unsigned* bs = Bs + (kt % STAGES) * TSZW;

        #pragma unroll
        for (int kk = 0; kk < 2; kk++) {
            unsigned af[4][4];
            unsigned bf[4][2];
            #pragma unroll
            for (int mt = 0; mt < 4; mt++) {
                int r0 = wr + mt * 16 + g;
                af[mt][0] = as[(r0    ) * ROWW + kk * 8 + tg];
                af[mt][1] = as[(r0 + 8) * ROWW + kk * 8 + tg];
                af[mt][2] = as[(r0    ) * ROWW + kk * 8 + tg + 4];
                af[mt][3] = as[(r0 + 8) * ROWW + kk * 8 + tg + 4];
            }
            #pragma unroll
            for (int nt = 0; nt < 4; nt++) {
                int rb = wc + nt * 8 + g;
                bf[nt][0] = bs[rb * ROWW + kk * 8 + tg];
                bf[nt][1] = bs[rb * ROWW + kk * 8 + tg + 4];
            }
            #pragma unroll
            for (int mt = 0; mt < 4; mt++)
                #pragma unroll
                for (int nt = 0; nt < 4; nt++)
                    mma_f16(acc[mt][nt], af[mt], bf[nt]);
        }
        __syncthreads();
    }

    float bv[4][2];
    #pragma unroll
    for (int nt = 0; nt < 4; nt++) {
        int col = bn * GBN + wc + nt * 8 + 2 * tg;
        bv[nt][0] = bias ? bias[col] : 0.0f;
        bv[nt][1] = bias ? bias[col + 1] : 0.0f;
    }

    #pragma unroll
    for (int mt = 0; mt < 4; mt++) {
        #pragma unroll
        for (int i = 0; i < 2; i++) {
            int row = bm * GBM + wr + mt * 16 + g + i * 8;
            if (row >= M) continue;
            size_t rb = (size_t)row * N + bn * GBN + wc;
            #pragma unroll
            for (int nt = 0; nt < 4; nt++) {
                float2 v;
                v.x = acc[mt][nt][i * 2 + 0] + bv[nt][0];
                v.y = acc[mt][nt][i * 2 + 1] + bv[nt][1];
                if (ACT == 1) {
                    v.x = v.x > 0.f ? v.x : 0.01f * v.x;
                    v.y = v.y > 0.f ? v.y : 0.01f * v.y;
                }
                if (C)   *(float2*)(C + rb + nt * 8 + 2 * tg) = v;
                if (C16) *(__half2*)(C16 + rb + nt * 8 + 2 * tg) = __floats2half2_rn(v.x, v.y);
            }
        }
    }
}

// ---------------- attention scores (fp16 xl) ---------------------------------
__global__ __launch_bounds__(256) void attn_scores_kernel(
    const __half* __restrict__ xl,
    const float* __restrict__ att_src, const float* __restrict__ att_dst,
    float* __restrict__ asrc, float* __restrict__ adst)
{
    int task = blockIdx.x * 8 + (threadIdx.x >> 5);
    if (task >= N_NODES * 4) return;
    int lane = threadIdx.x & 31;
    int n = task >> 2, h = task & 3;

    const __half* xp = xl + (size_t)n * 1024 + h * 256 + lane * 8;
    const float* sp = att_src + h * 256 + lane * 8;
    const float* dp = att_dst + h * 256 + lane * 8;

    uint4 raw = *(const uint4*)xp;
    __half2* hh = (__half2*)&raw;
    float2 p0 = __half22float2(hh[0]);
    float2 p1 = __half22float2(hh[1]);
    float2 p2 = __half22float2(hh[2]);
    float2 p3 = __half22float2(hh[3]);
    float4 a0 = *(const float4*)(sp), a1 = *(const float4*)(sp + 4);
    float4 b0 = *(const float4*)(dp), b1 = *(const float4*)(dp + 4);

    float s1 = p0.x*a0.x + p0.y*a0.y + p1.x*a0.z + p1.y*a0.w
             + p2.x*a1.x + p2.y*a1.y + p3.x*a1.z + p3.y*a1.w;
    float s2 = p0.x*b0.x + p0.y*b0.y + p1.x*b0.z + p1.y*b0.w
             + p2.x*b1.x + p2.y*b1.y + p3.x*b1.z + p3.y*b1.w;

    #pragma unroll
    for (int off = 16; off > 0; off >>= 1) {
        s1 += __shfl_xor_sync(0xffffffffu, s1, off);
        s2 += __shfl_xor_sync(0xffffffffu, s2, off);
    }
    if (lane == 0) {
        asrc[task] = s1;
        adst[task] = s2;
    }
}

// ---------------- layer1 aggregation: fp16 gather, fp16 'at' output ----------
// one warp per (dst node, head); out_at = half(h1_res + softmax-weighted sum)
__global__ __launch_bounds__(256) void gat_aggregate1_kernel(
    const int* __restrict__ off, const int* __restrict__ esrc,
    const __half* __restrict__ xl, const float* __restrict__ asrc,
    const float* __restrict__ adst, const float* __restrict__ h1,
    __half* __restrict__ out_at)
{
    int task = blockIdx.x * 8 + (threadIdx.x >> 5);
    if (task >= N_NODES * 4) return;
    int lane = threadIdx.x & 31;
    int n = task >> 2, h = task & 3;

    const float ad = adst[n * 4 + h];
    const int j0 = off[n], j1 = off[n + 1];

    float u[8] = {0.f, 0.f, 0.f, 0.f, 0.f, 0.f, 0.f, 0.f};
    float ssum = 0.f;

    for (int j = j0; j < j1; j++) {
        int s = esrc[j];
        float a = asrc[s * 4 + h] + ad;
        a = a > 0.f ? a : 0.2f * a;
        float w = __expf(a);
        ssum += w;
        uint4 raw = *(const uint4*)(xl + (size_t)s * 1024 + h * 256 + lane * 8);
        __half2* hh = (__half2*)&raw;
        float2 p0 = __half22float2(hh[0]);
        float2 p1 = __half22float2(hh[1]);
        float2 p2 = __half22float2(hh[2]);
        float2 p3 = __half22float2(hh[3]);
        u[0] += w * p0.x; u[1] += w * p0.y; u[2] += w * p1.x; u[3] += w * p1.y;
        u[4] += w * p2.x; u[5] += w * p2.y; u[6] += w * p3.x; u[7] += w * p3.y;
    }

    float inv = 1.0f / (ssum + 1e-16f);
    size_t base = (size_t)n * 1024 + h * 256 + lane * 8;
    float4 r0 = *(const float4*)(h1 + base);
    float4 r1 = *(const float4*)(h1 + base + 4);
    __half2 o[4];
    o[0] = __floats2half2_rn(r0.x + u[0] * inv, r0.y + u[1] * inv);
    o[1] = __floats2half2_rn(r0.z + u[2] * inv, r0.w + u[3] * inv);
    o[2] = __floats2half2_rn(r1.x + u[4] * inv, r1.y + u[5] * inv);
    o[3] = __floats2half2_rn(r1.z + u[6] * inv, r1.w + u[7] * inv);
    *(uint4*)(out_at + base) = *(uint4*)o;
}

// ---------------- layer2 aggregation: head-mean, fp16 gather/out -------------
// one warp per dst node; out_at[n,256] = half(h2_res + mean-head agg)
__global__ __launch_bounds__(256) void gat_aggregate2_kernel(
    const int* __restrict__ off, const int* __restrict__ esrc,
    const __half* __restrict__ xl, const float* __restrict__ asrc,
    const float* __restrict__ adst, const float* __restrict__ h2,
    __half* __restrict__ out_at)
{
    int n = blockIdx.x * 8 + (threadIdx.x >> 5);
    if (n >= N_NODES) return;
    int lane = threadIdx.x & 31;

    float4 ad = *(const float4*)(adst + n * 4);
    const int j0 = off[n], j1 = off[n + 1];

    float u[4][8];
    #pragma unroll
    for (int h = 0; h < 4; h++)
        #pragma unroll
        for (int q = 0; q < 8; q++) u[h][q] = 0.f;
    float4 ssum = make_float4(0.f, 0.f, 0.f, 0.f);

    for (int j = j0; j < j1; j++) {
        int s = esrc[j];
        float4 as = *(const float4*)(asrc + s * 4);
        float4 e;
        e.x = as.x + ad.x; e.x = e.x > 0.f ? e.x : 0.2f * e.x;
        e.y = as.y + ad.y; e.y = e.y > 0.f ? e.y : 0.2f * e.y;
        e.z = as.z + ad.z; e.z = e.z > 0.f ? e.z : 0.2f * e.z;
        e.w = as.w + ad.w; e.w = e.w > 0.f ? e.w : 0.2f * e.w;
        float w[4];
        w[0] = __expf(e.x); w[1] = __expf(e.y); w[2] = __expf(e.z); w[3] = __expf(e.w);
        ssum.x += w[0]; ssum.y += w[1]; ssum.z += w[2]; ssum.w += w[3];

        const __half* sp = xl + (size_t)s * 1024 + lane * 8;
        #pragma unroll
        for (int h = 0; h < 4; h++) {
            uint4 raw = *(const uint4*)(sp + h * 256);
            __half2* hh = (__half2*)&raw;
            float2 p0 = __half22float2(hh[0]);
            float2 p1 = __half22float2(hh[1]);
            float2 p2 = __half22float2(hh[2]);
            float2 p3 = __half22float2(hh[3]);
            u[h][0] += w[h] * p0.x; u[h][1] += w[h] * p0.y;
            u[h][2] += w[h] * p1.x; u[h][3] += w[h] * p1.y;
            u[h][4] += w[h] * p2.x; u[h][5] += w[h] * p2.y;
            u[h][6] += w[h] * p3.x; u[h][7] += w[h] * p3.y;
        }
    }

    float i0 = 0.25f / (ssum.x + 1e-16f);
    float i1 = 0.25f / (ssum.y + 1e-16f);
    float i2 = 0.25f / (ssum.z + 1e-16f);
    float i3 = 0.25f / (ssum.w + 1e-16f);

    size_t base = (size_t)n * 256 + lane * 8;
    float4 r0 = *(const float4*)(h2 + base);
    float4 r1 = *(const float4*)(h2 + base + 4);
    float o[8];
    o[0] = r0.x + i0*u[0][0] + i1*u[1][0] + i2*u[2][0] + i3*u[3][0];
    o[1] = r0.y + i0*u[0][1] + i1*u[1][1] + i2*u[2][1] + i3*u[3][1];
    o[2] = r0.z + i0*u[0][2] + i1*u[1][2] + i2*u[2][2] + i3*u[3][2];
    o[3] = r0.w + i0*u[0][3] + i1*u[1][3] + i2*u[2][3] + i3*u[3][3];
    o[4] = r1.x + i0*u[0][4] + i1*u[1][4] + i2*u[2][4] + i3*u[3][4];
    o[5] = r1.y + i0*u[0][5] + i1*u[1][5] + i2*u[2][5] + i3*u[3][5];
    o[6] = r1.z + i0*u[0][6] + i1*u[1][6] + i2*u[2][6] + i3*u[3][6];
    o[7] = r1.w + i0*u[0][7] + i1*u[1][7] + i2*u[2][7] + i3*u[3][7];
    __half2 ho[4];
    ho[0] = __floats2half2_rn(o[0], o[1]);
    ho[1] = __floats2half2_rn(o[2], o[3]);
    ho[2] = __floats2half2_rn(o[4], o[5]);
    ho[3] = __floats2half2_rn(o[6], o[7]);
    *(uint4*)(out_at + base) = *(uint4*)ho;
}

// ---------------- output heads ----------------------------------------------
__global__ __launch_bounds__(256) void heads_kernel(
    const float* __restrict__ fc,
    const float* __restrict__ Wb, const float* __restrict__ bb,
    const float* __restrict__ Ws, const float* __restrict__ bs,
    float* __restrict__ out)
{
    int n = blockIdx.x * 8 + (threadIdx.x >> 5);
    if (n >= N_NODES) return;
    int lane = threadIdx.x & 31;

    float acc[7] = {0.f, 0.f, 0.f, 0.f, 0.f, 0.f, 0.f};
    #pragma unroll
    for (int i = 0; i < 8; i++) {
        int k = i * 32 + lane;
        float v = fc[(size_t)n * 256 + k];
        acc[0] += v * Wb[k * 2 + 0];
        acc[1] += v * Wb[k * 2 + 1];
        #pragma unroll
        for (int j = 0; j < 5; j++) acc[2 + j] += v * Ws[k * 5 + j];
    }
    #pragma unroll
    for (int off = 16; off > 0; off >>= 1) {
        #pragma unroll
        for (int j = 0; j < 7; j++) acc[j] += __shfl_xor_sync(0xffffffffu, acc[j], off);
    }
    if (lane == 0) {
        out[(size_t)n * 2 + 0] = acc[0] + bb[0];
        out[(size_t)n * 2 + 1] = acc[1] + bb[1];
        float* sev = out + (size_t)N_NODES * 2 + (size_t)n * 5;
        #pragma unroll
        for (int j = 0; j < 5; j++) sev[j] = acc[2 + j] + bs[j];
    }
}

// ---------------- launch ------------------------------------------------------
static inline void cvt(const float* in, __half* out, int n) {
    cvt_fp16_kernel<<<(n / 8 + 255) / 256, 256>>>(in, out, n);
}
static inline void cvtT(const float* W, __half* out, int K, int N) {
    dim3 grid(N / 32, K / 32);
    cvt_fp16_transpose_kernel<<<grid, dim3(32, 8)>>>(W, out, K, N);
}

extern "C" void kernel_launch(void* const* d_in, const int* in_sizes, int n_in,
                              void* d_out, int out_size)
{
    const float* x        = (const float*)d_in[0];
    const int*   ei       = (const int*)d_in[1];
    const float* W1       = (const float*)d_in[2];
    const float* att_src1 = (const float*)d_in[3];
    const float* att_dst1 = (const float*)d_in[4];
    const float* Wres1    = (const float*)d_in[5];
    const float* b1       = (const float*)d_in[6];
    const float* W2       = (const float*)d_in[7];
    const float* att_src2 = (const float*)d_in[8];
    const float* att_dst2 = (const float*)d_in[9];
    const float* Wres2    = (const float*)d_in[10];
    const float* b2       = (const float*)d_in[11];
    const float* Wfc      = (const float*)d_in[12];
    const float* bfc      = (const float*)d_in[13];
    const float* Wb       = (const float*)d_in[14];
    const float* bb       = (const float*)d_in[15];
    const float* Ws       = (const float*)d_in[16];
    const float* bs       = (const float*)d_in[17];
    float* out = (float*)d_out;

    const int* src = ei;
    const int* dst = ei + N_EDGES;

    float *h1, *h2, *fc2, *asrc, *adst;
    __half *xl16, *at, *wt, *wt2, *fc1h;
    int *deg, *off, *cur, *esrc;
    cudaGetSymbolAddress((void**)&xl16, g_xl16);
    cudaGetSymbolAddress((void**)&h1,   g_h1);
    cudaGetSymbolAddress((void**)&h2,   g_h2);
    cudaGetSymbolAddress((void**)&fc1h, g_fc1h);
    cudaGetSymbolAddress((void**)&fc2,  g_fc2);
    cudaGetSymbolAddress((void**)&at,   g_at);
    cudaGetSymbolAddress((void**)&wt,   g_wt);
    cudaGetSymbolAddress((void**)&wt2,  g_wt2);
    cudaGetSymbolAddress((void**)&asrc, g_asrc);
    cudaGetSymbolAddress((void**)&adst, g_adst);
    cudaGetSymbolAddress((void**)&deg,  g_deg);
    cudaGetSymbolAddress((void**)&off,  g_off);
    cudaGetSymbolAddress((void**)&cur,  g_cur);
    cudaGetSymbolAddress((void**)&esrc, g_esrc);

    static bool attr_done = false;
    if (!attr_done) {
        cudaFuncSetAttribute(mma_gemm_kernel<0>,
                             cudaFuncAttributeMaxDynamicSharedMemorySize, GEMM_SMEM);
        cudaFuncSetAttribute(mma_gemm_kernel<1>,
                             cudaFuncAttributeMaxDynamicSharedMemorySize, GEMM_SMEM);
        attr_done = true;
    }

    const int mRows = (N_NODES + GBM - 1) / GBM;
    const int attnBlocks = (N_NODES * 4 + 7) / 8;
    const int nodeBlocks = (N_NODES + 7) / 8;
    const int edgeBlocks = (N_EDGES + 255) / 256;

    // launches 1-3
    cvt(x, at, N_NODES * 768);
    cvtT(Wres1, wt, 768, 1024);
    zero_deg_kernel<<<(N_NODES + 255) / 256, 256>>>(deg);

    // launch 4: big GEMM (ncu window)
    {
        dim3 grid(1024 / GBN, mRows);
        mma_gemm_kernel<0><<<grid, 256, GEMM_SMEM>>>(at, wt, b1, h1, nullptr,
                                                     N_NODES, 1024, 768);
        cvtT(W1, wt2, 768, 1024);
        mma_gemm_kernel<0><<<grid, 256, GEMM_SMEM>>>(at, wt2, nullptr, nullptr, xl16,
                                                     N_NODES, 1024, 768);
    }
    hist_kernel<<<edgeBlocks, 256>>>(dst, deg);
    scan_kernel<<<1, 256>>>(deg, off, cur);
    scatter_kernel<<<edgeBlocks, 256>>>(src, dst, cur, esrc);

    // ===== layer 1 aggregation -> fp16 'at' =====
    attn_scores_kernel<<<attnBlocks, 256>>>(xl16, att_src1, att_dst1, asrc, adst);
    gat_aggregate1_kernel<<<attnBlocks, 256>>>(off, esrc, xl16, asrc, adst, h1, at);

    // ===== layer 2 =====
    {
        dim3 grid(256 / GBN, mRows);
        cvtT(Wres2, wt, 1024, 256);
        mma_gemm_kernel<0><<<grid, 256, GEMM_SMEM>>>(at, wt, b2, h2, nullptr,
                                                     N_NODES, 256, 1024);
    }
    {
        dim3 grid(1024 / GBN, mRows);
        cvtT(W2, wt2, 1024, 1024);
        mma_gemm_kernel<0><<<grid, 256, GEMM_SMEM>>>(at, wt2, nullptr, nullptr, xl16,
                                                     N_NODES, 1024, 1024);
    }
    attn_scores_kernel<<<attnBlocks, 256>>>(xl16, att_src2, att_dst2, asrc, adst);
    gat_aggregate2_kernel<<<nodeBlocks, 256>>>(off, esrc, xl16, asrc, adst, h2, at);

    // ===== shared FC twice =====
    {
        dim3 grid(256 / GBN, mRows);
        cvtT(Wfc, wt, 256, 256);
        mma_gemm_kernel<1><<<grid, 256, GEMM_SMEM>>>(at, wt, bfc, nullptr, fc1h,
                                                     N_NODES, 256, 256);
        mma_gemm_kernel<0><<<grid, 256, GEMM_SMEM>>>(fc1h, wt, bfc, fc2, nullptr,
                                                     N_NODES, 256, 256);
    }

    // ===== heads =====
    heads_kernel<<<nodeBlocks, 256>>>(fc2, Wb, bb, Ws, bs, out);
}

// round 9
// speedup vs baseline: 7.0839x; 1.0796x over previous
#include <cuda_runtime.h>
#include <cuda_fp16.h>
#include <cstdint>

#define N_NODES 20000
#define N_EDGES 320000

// ---------------- scratch (device globals; no allocation allowed) ----------
__device__ __half g_xl16[N_NODES * 1024];  // fp16 per-head features (gather source)
__device__ float  g_h1[N_NODES * 1024];    // layer1 residual GEMM output (read once)
__device__ float  g_h2[N_NODES * 256];     // layer2 residual GEMM output (read once)
__device__ __half g_fc1h[N_NODES * 256];   // fp16 fc1 output
__device__ float  g_fc2[N_NODES * 256];
__device__ __half g_at[N_NODES * 1024];    // fp16 A operand (x, then h1, then h2)
__device__ __half g_wt[2048 * 1024];       // fp16 transposed packed weights [N,K]
__device__ float  g_asrc[N_NODES * 4];
__device__ float  g_adst[N_NODES * 4];
__device__ int    g_deg[N_NODES];
__device__ int    g_off[N_NODES + 1];
__device__ int    g_cur[N_NODES];
__device__ int    g_esrc[N_EDGES];         // src node of each edge, grouped by dst

// ---------------- helpers ---------------------------------------------------
__device__ __forceinline__ void mma_f16(float* d, const unsigned* a, const unsigned* b) {
    asm volatile(
        "mma.sync.aligned.m16n8k16.row.col.f32.f16.f16.f32 "
        "{%0,%1,%2,%3}, {%4,%5,%6,%7}, {%8,%9}, {%0,%1,%2,%3};"
        : "+f"(d[0]), "+f"(d[1]), "+f"(d[2]), "+f"(d[3])
        : "r"(a[0]), "r"(a[1]), "r"(a[2]), "r"(a[3]), "r"(b[0]), "r"(b[1]));
}

__device__ __forceinline__ void cp16(void* smem, const void* gmem, bool pred) {
    unsigned sa = (unsigned)__cvta_generic_to_shared(smem);
    int sz = pred ? 16 : 0;
    asm volatile("cp.async.cg.shared.global [%0], [%1], 16, %2;"
                 :: "r"(sa), "l"(gmem), "r"(sz));
}

// ---------------- fp16 conversion passes -------------------------------------
__global__ void cvt_fp16_kernel(const float* __restrict__ in, __half* __restrict__ out, int n) {
    int i = (blockIdx.x * blockDim.x + threadIdx.x) * 8;
    if (i >= n) return;
    float4 v0 = *(const float4*)(in + i);
    float4 v1 = *(const float4*)(in + i + 4);
    __half2 h[4];
    h[0] = __floats2half2_rn(v0.x, v0.y);
    h[1] = __floats2half2_rn(v0.z, v0.w);
    h[2] = __floats2half2_rn(v1.x, v1.y);
    h[3] = __floats2half2_rn(v1.z, v1.w);
    *(uint4*)(out + i) = *(uint4*)h;
}

// weights: W[K,N] fp32 -> out[N,K] fp16 (transposed). K,N multiples of 32.
__global__ void cvt_fp16_transpose_kernel(const float* __restrict__ in, __half* __restrict__ out,
                                          int K, int N) {
    __shared__ float t[32][33];
    int k0 = blockIdx.y * 32, n0 = blockIdx.x * 32;
    int tx = threadIdx.x, ty = threadIdx.y;  // 32 x 8
    #pragma unroll
    for (int j = 0; j < 32; j += 8)
        t[ty + j][tx] = in[(size_t)(k0 + ty + j) * N + n0 + tx];
    __syncthreads();
    #pragma unroll
    for (int j = 0; j < 32; j += 8)
        out[(size_t)(n0 + ty + j) * K + k0 + tx] = __float2half_rn(t[tx][ty + j]);
}

// ---------------- CSR build ---------------------------------------------------
__global__ void zero_deg_kernel(int* __restrict__ deg) {
    int i = blockIdx.x * blockDim.x + threadIdx.x;
    if (i < N_NODES) deg[i] = 0;
}

__global__ void hist_kernel(const int* __restrict__ dst, int* __restrict__ deg) {
    int e = blockIdx.x * blockDim.x + threadIdx.x;
    if (e < N_EDGES) atomicAdd(&deg[dst[e]], 1);
}

__global__ __launch_bounds__(256) void scan_kernel(
    const int* __restrict__ deg, int* __restrict__ off, int* __restrict__ cur)
{
    __shared__ int partial[256];
    const int tid = threadIdx.x;
    const int CH = (N_NODES + 255) / 256;
    const int base = tid * CH;

    int s = 0;
    for (int j = 0; j < CH; j++) {
        int i = base + j;
        if (i < N_NODES) s += deg[i];
    }
    partial[tid] = s;
    __syncthreads();
    for (int o = 1; o < 256; o <<= 1) {
        int v = (tid >= o) ? partial[tid - o] : 0;
        __syncthreads();
        partial[tid] += v;
        __syncthreads();
    }
    int run = partial[tid] - s;
    for (int j = 0; j < CH; j++) {
        int i = base + j;
        if (i < N_NODES) {
            off[i] = run;
            cur[i] = run;
            run += deg[i];
        }
    }
    if (tid == 255) off[N_NODES] = run;
}

__global__ void scatter_kernel(const int* __restrict__ src, const int* __restrict__ dst,
                               int* __restrict__ cur, int* __restrict__ esrc) {
    int e = blockIdx.x * blockDim.x + threadIdx.x;
    if (e >= N_EDGES) return;
    int pos = atomicAdd(&cur[dst[e]], 1);
    esrc[pos] = src[e];
}

// ---------------- fp16 tensor-core GEMM, cp.async 4-stage, single-sync -------
// C_all[M,N] = A[M,K] @ Bt[N,K]^T. Split output: columns [0,Nsplit) go fp32 to
// C (row stride Nsplit, bias biasA); columns [Nsplit,N) go fp16 to C16 (row
// stride N-Nsplit, bias biasB). Nsplit % 128 == 0 so each CTA is in one region.
// CTA tile 128x128, K-tile 32 halves, 8 warps (2x4) 64x32, mma m16n8k16.
// Requires N % 128 == 0, K % 32 == 0; M guarded.
#define GBM 128
#define GBN 128
#define HK 32
#define ROWW 20
#define TSZW (128 * ROWW)
#define STAGES 4
#define GEMM_SMEM (STAGES * 2 * TSZW * 4)

template <int ACT>  // 0: none, 1: leaky_relu(0.01)
__global__ __launch_bounds__(256, 2) void mma_gemm_kernel(
    const __half* __restrict__ A, const __half* __restrict__ Bt,
    const float* __restrict__ biasA, const float* __restrict__ biasB,
    float* __restrict__ C, __half* __restrict__ C16,
    int M, int N, int K, int Nsplit)
{
    extern __shared__ unsigned smem[];
    unsigned* As = smem;
    unsigned* Bs = smem + STAGES * TSZW;

    const int tid = threadIdx.x;
    const int warp = tid >> 5, lane = tid & 31;
    const int g = lane >> 2, tg = lane & 3;
    const int wr = (warp >> 2) * 64;
    const int wc = (warp & 3) * 32;

    const int bm = blockIdx.y, bn = blockIdx.x;

    const int rowS = tid >> 1;
    const int rowA = bm * GBM + rowS;
    const bool avalid = rowA < M;
    const __half* Ap = avalid ? (A + (size_t)rowA * K + (tid & 1) * 16) : A;
    const __half* Bp = Bt + (size_t)(bn * GBN + rowS) * K + (tid & 1) * 16;
    const int sOff = rowS * ROWW + (tid & 1) * 8;

    const int KT = K / HK;

    float acc[4][4][4];
    #pragma unroll
    for (int mt = 0; mt < 4; mt++)
        #pragma unroll
        for (int nt = 0; nt < 4; nt++)
            #pragma unroll
            for (int i = 0; i < 4; i++) acc[mt][nt][i] = 0.0f;

    // prologue: stage tiles 0..2
    #pragma unroll
    for (int kt = 0; kt < STAGES - 1; kt++) {
        if (kt < KT) {
            unsigned* as = As + (kt % STAGES) * TSZW;
            unsigned* bs = Bs + (kt % STAGES) * TSZW;
            const __half* ap = Ap + (avalid ? kt * HK : 0);
            const __half* bp = Bp + kt * HK;
            cp16(&as[sOff],     ap,     avalid);
            cp16(&as[sOff + 4], ap + 8, avalid);
            cp16(&bs[sOff],     bp,     true);
            cp16(&bs[sOff + 4], bp + 8, true);
        }
        asm volatile("cp.async.commit_group;");
    }

    for (int kt = 0; kt < KT; kt++) {
        // tile kt resident
        asm volatile("cp.async.wait_group %0;" :: "n"(STAGES - 2));
        // single barrier: also proves all warps finished reading buffer
        // (kt-1)%STAGES == (kt+3)%STAGES before we overwrite it below
        __syncthreads();

        int kf = kt + STAGES - 1;
        if (kf < KT) {
            unsigned* as = As + (kf % STAGES) * TSZW;
            unsigned* bs = Bs + (kf % STAGES) * TSZW;
            const __half* ap = Ap + (avalid ? kf * HK : 0);
            const __half* bp = Bp + kf * HK;
            cp16(&as[sOff],     ap,     avalid);
            cp16(&as[sOff + 4], ap + 8, avalid);
            cp16(&bs[sOff],     bp,     true);
            cp16(&bs[sOff + 4], bp + 8, true);
        }
        asm volatile("cp.async.commit_group;");

        const unsigned* as = As + (kt % STAGES) * TSZW;
        const unsigned* bs = Bs + (kt % STAGES) * TSZW;

        #pragma unroll
        for (int kk = 0; kk < 2; kk++) {
            unsigned af[4][4];
            unsigned bf[4][2];
            #pragma unroll
            for (int mt = 0; mt < 4; mt++) {
                int r0 = wr + mt * 16 + g;
                af[mt][0] = as[(r0    ) * ROWW + kk * 8 + tg];
                af[mt][1] = as[(r0 + 8) * ROWW + kk * 8 + tg];
                af[mt][2] = as[(r0    ) * ROWW + kk * 8 + tg + 4];
                af[mt][3] = as[(r0 + 8) * ROWW + kk * 8 + tg + 4];
            }
            #pragma unroll
            for (int nt = 0; nt < 4; nt++) {
                int rb = wc + nt * 8 + g;
                bf[nt][0] = bs[rb * ROWW + kk * 8 + tg];
                bf[nt][1] = bs[rb * ROWW + kk * 8 + tg + 4];
            }
            #pragma unroll
            for (int mt = 0; mt < 4; mt++)
                #pragma unroll
                for (int nt = 0; nt < 4; nt++)
                    mma_f16(acc[mt][nt], af[mt], bf[nt]);
        }
    }

    // epilogue: whole CTA tile lies in one output region
    const int colBase = bn * GBN;
    const bool rA = colBase < Nsplit;
    const int Wd = rA ? Nsplit : (N - Nsplit);
    const int cb = (rA ? colBase : colBase - Nsplit) + wc;
    const float* bias = rA ? biasA : biasB;

    float bv[4][2];
    #pragma unroll
    for (int nt = 0; nt < 4; nt++) {
        int col = cb + nt * 8 + 2 * tg;
        bv[nt][0] = bias ? bias[col] : 0.0f;
        bv[nt][1] = bias ? bias[col + 1] : 0.0f;
    }

    #pragma unroll
    for (int mt = 0; mt < 4; mt++) {
        #pragma unroll
        for (int i = 0; i < 2; i++) {
            int row = bm * GBM + wr + mt * 16 + g + i * 8;
            if (row >= M) continue;
            size_t rb = (size_t)row * Wd + cb;
            #pragma unroll
            for (int nt = 0; nt < 4; nt++) {
                float2 v;
                v.x = acc[mt][nt][i * 2 + 0] + bv[nt][0];
                v.y = acc[mt][nt][i * 2 + 1] + bv[nt][1];
                if (ACT == 1) {
                    v.x = v.x > 0.f ? v.x : 0.01f * v.x;
                    v.y = v.y > 0.f ? v.y : 0.01f * v.y;
                }
                if (rA) *(float2*)(C + rb + nt * 8 + 2 * tg) = v;
                else    *(__half2*)(C16 + rb + nt * 8 + 2 * tg) = __floats2half2_rn(v.x, v.y);
            }
        }
    }
}

// ---------------- attention scores (fp16 xl) ---------------------------------
__global__ __launch_bounds__(256) void attn_scores_kernel(
    const __half* __restrict__ xl,
    const float* __restrict__ att_src, const float* __restrict__ att_dst,
    float* __restrict__ asrc, float* __restrict__ adst)
{
    int task = blockIdx.x * 8 + (threadIdx.x >> 5);
    if (task >= N_NODES * 4) return;
    int lane = threadIdx.x & 31;
    int n = task >> 2, h = task & 3;

    const __half* xp = xl + (size_t)n * 1024 + h * 256 + lane * 8;
    const float* sp = att_src + h * 256 + lane * 8;
    const float* dp = att_dst + h * 256 + lane * 8;

    uint4 raw = *(const uint4*)xp;
    __half2* hh = (__half2*)&raw;
    float2 p0 = __half22float2(hh[0]);
    float2 p1 = __half22float2(hh[1]);
    float2 p2 = __half22float2(hh[2]);
    float2 p3 = __half22float2(hh[3]);
    float4 a0 = *(const float4*)(sp), a1 = *(const float4*)(sp + 4);
    float4 b0 = *(const float4*)(dp), b1 = *(const float4*)(dp + 4);

    float s1 = p0.x*a0.x + p0.y*a0.y + p1.x*a0.z + p1.y*a0.w
             + p2.x*a1.x + p2.y*a1.y + p3.x*a1.z + p3.y*a1.w;
    float s2 = p0.x*b0.x + p0.y*b0.y + p1.x*b0.z + p1.y*b0.w
             + p2.x*b1.x + p2.y*b1.y + p3.x*b1.z + p3.y*b1.w;

    #pragma unroll
    for (int off = 16; off > 0; off >>= 1) {
        s1 += __shfl_xor_sync(0xffffffffu, s1, off);
        s2 += __shfl_xor_sync(0xffffffffu, s2, off);
    }
    if (lane == 0) {
        asrc[task] = s1;
        adst[task] = s2;
    }
}

// ---------------- layer1 aggregation: fp16 gather, fp16 'at' output ----------
__global__ __launch_bounds__(256) void gat_aggregate1_kernel(
    const int* __restrict__ off, const int* __restrict__ esrc,
    const __half* __restrict__ xl, const float* __restrict__ asrc,
    const float* __restrict__ adst, const float* __restrict__ h1,
    __half* __restrict__ out_at)
{
    int task = blockIdx.x * 8 + (threadIdx.x >> 5);
    if (task >= N_NODES * 4) return;
    int lane = threadIdx.x & 31;
    int n = task >> 2, h = task & 3;

    const float ad = adst[n * 4 + h];
    const int j0 = off[n], j1 = off[n + 1];

    float u[8] = {0.f, 0.f, 0.f, 0.f, 0.f, 0.f, 0.f, 0.f};
    float ssum = 0.f;

    for (int j = j0; j < j1; j++) {
        int s = esrc[j];
        float a = asrc[s * 4 + h] + ad;
        a = a > 0.f ? a : 0.2f * a;
        float w = __expf(a);
        ssum += w;
        uint4 raw = *(const uint4*)(xl + (size_t)s * 1024 + h * 256 + lane * 8);
        __half2* hh = (__half2*)&raw;
        float2 p0 = __half22float2(hh[0]);
        float2 p1 = __half22float2(hh[1]);
        float2 p2 = __half22float2(hh[2]);
        float2 p3 = __half22float2(hh[3]);
        u[0] += w * p0.x; u[1] += w * p0.y; u[2] += w * p1.x; u[3] += w * p1.y;
        u[4] += w * p2.x; u[5] += w * p2.y; u[6] += w * p3.x; u[7] += w * p3.y;
    }

    float inv = 1.0f / (ssum + 1e-16f);
    size_t base = (size_t)n * 1024 + h * 256 + lane * 8;
    float4 r0 = *(const float4*)(h1 + base);
    float4 r1 = *(const float4*)(h1 + base + 4);
    __half2 o[4];
    o[0] = __floats2half2_rn(r0.x + u[0] * inv, r0.y + u[1] * inv);
    o[1] = __floats2half2_rn(r0.z + u[2] * inv, r0.w + u[3] * inv);
    o[2] = __floats2half2_rn(r1.x + u[4] * inv, r1.y + u[5] * inv);
    o[3] = __floats2half2_rn(r1.z + u[6] * inv, r1.w + u[7] * inv);
    *(uint4*)(out_at + base) = *(uint4*)o;
}

// ---------------- layer2 aggregation: head-mean, fp16 gather/out -------------
__global__ __launch_bounds__(256) void gat_aggregate2_kernel(
    const int* __restrict__ off, const int* __restrict__ esrc,
    const __half* __restrict__ xl, const float* __restrict__ asrc,
    const float* __restrict__ adst, const float* __restrict__ h2,
    __half* __restrict__ out_at)
{
    int n = blockIdx.x * 8 + (threadIdx.x >> 5);
    if (n >= N_NODES) return;
    int lane = threadIdx.x & 31;

    float4 ad = *(const float4*)(adst + n * 4);
    const int j0 = off[n], j1 = off[n + 1];

    float u[4][8];
    #pragma unroll
    for (int h = 0; h < 4; h++)
        #pragma unroll
        for (int q = 0; q < 8; q++) u[h][q] = 0.f;
    float4 ssum = make_float4(0.f, 0.f, 0.f, 0.f);

    for (int j = j0; j < j1; j++) {
        int s = esrc[j];
        float4 as = *(const float4*)(asrc + s * 4);
        float4 e;
        e.x = as.x + ad.x; e.x = e.x > 0.f ? e.x : 0.2f * e.x;
        e.y = as.y + ad.y; e.y = e.y > 0.f ? e.y : 0.2f * e.y;
        e.z = as.z + ad.z; e.z = e.z > 0.f ? e.z : 0.2f * e.z;
        e.w = as.w + ad.w; e.w = e.w > 0.f ? e.w : 0.2f * e.w;
        float w[4];
        w[0] = __expf(e.x); w[1] = __expf(e.y); w[2] = __expf(e.z); w[3] = __expf(e.w);
        ssum.x += w[0]; ssum.y += w[1]; ssum.z += w[2]; ssum.w += w[3];

        const __half* sp = xl + (size_t)s * 1024 + lane * 8;
        #pragma unroll
        for (int h = 0; h < 4; h++) {
            uint4 raw = *(const uint4*)(sp + h * 256);
            __half2* hh = (__half2*)&raw;
            float2 p0 = __half22float2(hh[0]);
            float2 p1 = __half22float2(hh[1]);
            float2 p2 = __half22float2(hh[2]);
            float2 p3 = __half22float2(hh[3]);
            u[h][0] += w[h] * p0.x; u[h][1] += w[h] * p0.y;
            u[h][2] += w[h] * p1.x; u[h][3] += w[h] * p1.y;
            u[h][4] += w[h] * p2.x; u[h][5] += w[h] * p2.y;
            u[h][6] += w[h] * p3.x; u[h][7] += w[h] * p3.y;
        }
    }

    float i0 = 0.25f / (ssum.x + 1e-16f);
    float i1 = 0.25f / (ssum.y + 1e-16f);
    float i2 = 0.25f / (ssum.z + 1e-16f);
    float i3 = 0.25f / (ssum.w + 1e-16f);

    size_t base = (size_t)n * 256 + lane * 8;
    float4 r0 = *(const float4*)(h2 + base);
    float4 r1 = *(const float4*)(h2 + base + 4);
    float o[8];
    o[0] = r0.x + i0*u[0][0] + i1*u[1][0] + i2*u[2][0] + i3*u[3][0];
    o[1] = r0.y + i0*u[0][1] + i1*u[1][1] + i2*u[2][1] + i3*u[3][1];
    o[2] = r0.z + i0*u[0][2] + i1*u[1][2] + i2*u[2][2] + i3*u[3][2];
    o[3] = r0.w + i0*u[0][3] + i1*u[1][3] + i2*u[2][3] + i3*u[3][3];
    o[4] = r1.x + i0*u[0][4] + i1*u[1][4] + i2*u[2][4] + i3*u[3][4];
    o[5] = r1.y + i0*u[0][5] + i1*u[1][5] + i2*u[2][5] + i3*u[3][5];
    o[6] = r1.z + i0*u[0][6] + i1*u[1][6] + i2*u[2][6] + i3*u[3][6];
    o[7] = r1.w + i0*u[0][7] + i1*u[1][7] + i2*u[2][7] + i3*u[3][7];
    __half2 ho[4];
    ho[0] = __floats2half2_rn(o[0], o[1]);
    ho[1] = __floats2half2_rn(o[2], o[3]);
    ho[2] = __floats2half2_rn(o[4], o[5]);
    ho[3] = __floats2half2_rn(o[6], o[7]);
    *(uint4*)(out_at + base) = *(uint4*)ho;
}

// ---------------- output heads ----------------------------------------------
__global__ __launch_bounds__(256) void heads_kernel(
    const float* __restrict__ fc,
    const float* __restrict__ Wb, const float* __restrict__ bb,
    const float* __restrict__ Ws, const float* __restrict__ bs,
    float* __restrict__ out)
{
    int n = blockIdx.x * 8 + (threadIdx.x >> 5);
    if (n >= N_NODES) return;
    int lane = threadIdx.x & 31;

    float acc[7] = {0.f, 0.f, 0.f, 0.f, 0.f, 0.f, 0.f};
    #pragma unroll
    for (int i = 0; i < 8; i++) {
        int k = i * 32 + lane;
        float v = fc[(size_t)n * 256 + k];
        acc[0] += v * Wb[k * 2 + 0];
        acc[1] += v * Wb[k * 2 + 1];
        #pragma unroll
        for (int j = 0; j < 5; j++) acc[2 + j] += v * Ws[k * 5 + j];
    }
    #pragma unroll
    for (int off = 16; off > 0; off >>= 1) {
        #pragma unroll
        for (int j = 0; j < 7; j++) acc[j] += __shfl_xor_sync(0xffffffffu, acc[j], off);
    }
    if (lane == 0) {
        out[(size_t)n * 2 + 0] = acc[0] + bb[0];
        out[(size_t)n * 2 + 1] = acc[1] + bb[1];
        float* sev = out + (size_t)N_NODES * 2 + (size_t)n * 5;
        #pragma unroll
        for (int j = 0; j < 5; j++) sev[j] = acc[2 + j] + bs[j];
    }
}

// ---------------- launch ------------------------------------------------------
static inline void cvt(const float* in, __half* out, int n) {
    cvt_fp16_kernel<<<(n / 8 + 255) / 256, 256>>>(in, out, n);
}
static inline void cvtT(const float* W, __half* out, int K, int N) {
    dim3 grid(N / 32, K / 32);
    cvt_fp16_transpose_kernel<<<grid, dim3(32, 8)>>>(W, out, K, N);
}

extern "C" void kernel_launch(void* const* d_in, const int* in_sizes, int n_in,
                              void* d_out, int out_size)
{
    const float* x        = (const float*)d_in[0];
    const int*   ei       = (const int*)d_in[1];
    const float* W1       = (const float*)d_in[2];
    const float* att_src1 = (const float*)d_in[3];
    const float* att_dst1 = (const float*)d_in[4];
    const float* Wres1    = (const float*)d_in[5];
    const float* b1       = (const float*)d_in[6];
    const float* W2       = (const float*)d_in[7];
    const float* att_src2 = (const float*)d_in[8];
    const float* att_dst2 = (const float*)d_in[9];
    const float* Wres2    = (const float*)d_in[10];
    const float* b2       = (const float*)d_in[11];
    const float* Wfc      = (const float*)d_in[12];
    const float* bfc      = (const float*)d_in[13];
    const float* Wb       = (const float*)d_in[14];
    const float* bb       = (const float*)d_in[15];
    const float* Ws       = (const float*)d_in[16];
    const float* bs       = (const float*)d_in[17];
    float* out = (float*)d_out;

    const int* src = ei;
    const int* dst = ei + N_EDGES;

    float *h1, *h2, *fc2, *asrc, *adst;
    __half *xl16, *at, *wt, *fc1h;
    int *deg, *off, *cur, *esrc;
    cudaGetSymbolAddress((void**)&xl16, g_xl16);
    cudaGetSymbolAddress((void**)&h1,   g_h1);
    cudaGetSymbolAddress((void**)&h2,   g_h2);
    cudaGetSymbolAddress((void**)&fc1h, g_fc1h);
    cudaGetSymbolAddress((void**)&fc2,  g_fc2);
    cudaGetSymbolAddress((void**)&at,   g_at);
    cudaGetSymbolAddress((void**)&wt,   g_wt);
    cudaGetSymbolAddress((void**)&asrc, g_asrc);
    cudaGetSymbolAddress((void**)&adst, g_adst);
    cudaGetSymbolAddress((void**)&deg,  g_deg);
    cudaGetSymbolAddress((void**)&off,  g_off);
    cudaGetSymbolAddress((void**)&cur,  g_cur);
    cudaGetSymbolAddress((void**)&esrc, g_esrc);

    static bool attr_done = false;
    if (!attr_done) {
        cudaFuncSetAttribute(mma_gemm_kernel<0>,
                             cudaFuncAttributeMaxDynamicSharedMemorySize, GEMM_SMEM);
        cudaFuncSetAttribute(mma_gemm_kernel<1>,
                             cudaFuncAttributeMaxDynamicSharedMemorySize, GEMM_SMEM);
        attr_done = true;
    }

    const int mRows = (N_NODES + GBM - 1) / GBM;
    const int attnBlocks = (N_NODES * 4 + 7) / 8;
    const int nodeBlocks = (N_NODES + 7) / 8;
    const int edgeBlocks = (N_EDGES + 255) / 256;

    // launches 1-3: operand prep (packed weights: [Wres1^T ; W1^T] = [2048, 768])
    cvt(x, at, N_NODES * 768);
    cvtT(Wres1, wt, 768, 1024);
    cvtT(W1, wt + (size_t)1024 * 768, 768, 1024);

    // launch 4 (ncu window): fused layer1 GEMM, N=2048
    //   cols [0,1024)    -> h1 (fp32) + b1
    //   cols [1024,2048) -> xl16 (fp16)
    {
        dim3 grid(2048 / GBN, mRows);
        mma_gemm_kernel<0><<<grid, 256, GEMM_SMEM>>>(at, wt, b1, nullptr, h1, xl16,
                                                     N_NODES, 2048, 768, 1024);
    }

    // CSR build
    zero_deg_kernel<<<(N_NODES + 255) / 256, 256>>>(deg);
    hist_kernel<<<edgeBlocks, 256>>>(dst, deg);
    scan_kernel<<<1, 256>>>(deg, off, cur);
    scatter_kernel<<<edgeBlocks, 256>>>(src, dst, cur, esrc);

    // ===== layer 1 aggregation -> fp16 'at' =====
    attn_scores_kernel<<<attnBlocks, 256>>>(xl16, att_src1, att_dst1, asrc, adst);
    gat_aggregate1_kernel<<<attnBlocks, 256>>>(off, esrc, xl16, asrc, adst, h1, at);

    // ===== fused layer2 GEMM, N=1280: cols [0,256)->h2+b2, [256,1280)->xl16 ===
    cvtT(Wres2, wt, 1024, 256);
    cvtT(W2, wt + (size_t)256 * 1024, 1024, 1024);
    {
        dim3 grid(1280 / GBN, mRows);
        mma_gemm_kernel<0><<<grid, 256, GEMM_SMEM>>>(at, wt, b2, nullptr, h2, xl16,
                                                     N_NODES, 1280, 1024, 256);
    }
    attn_scores_kernel<<<attnBlocks, 256>>>(xl16, att_src2, att_dst2, asrc, adst);
    gat_aggregate2_kernel<<<nodeBlocks, 256>>>(off, esrc, xl16, asrc, adst, h2, at);

    // ===== shared FC twice =====
    cvtT(Wfc, wt, 256, 256);
    {
        dim3 grid(256 / GBN, mRows);
        // fc1: all columns fp16 out with bias+leaky (region B, Nsplit=0)
        mma_gemm_kernel<1><<<grid, 256, GEMM_SMEM>>>(at, wt, nullptr, bfc, nullptr, fc1h,
                                                     N_NODES, 256, 256, 0);
        // fc2: all columns fp32 out with bias (region A, Nsplit=256)
        mma_gemm_kernel<0><<<grid, 256, GEMM_SMEM>>>(fc1h, wt, bfc, nullptr, fc2, nullptr,
                                                     N_NODES, 256, 256, 256);
    }

    // ===== heads =====
    heads_kernel<<<nodeBlocks, 256>>>(fc2, Wb, bb, Ws, bs, out);
}

// round 10
// speedup vs baseline: 7.9136x; 1.1171x over previous
#include <cuda_runtime.h>
#include <cuda_fp16.h>
#include <cstdint>

#define N_NODES 20000
#define N_EDGES 320000

// ---------------- scratch (device globals; no allocation allowed) ----------
__device__ __half g_xl16[N_NODES * 1024];  // fp16 per-head features (gather source)
__device__ float  g_h1[N_NODES * 1024];    // layer1 residual GEMM output (read once)
__device__ float  g_h2[N_NODES * 256];     // layer2 residual GEMM output (read once)
__device__ __half g_fc1h[N_NODES * 256];   // fp16 fc1 output
__device__ float  g_fc2[N_NODES * 256];
__device__ __half g_at[N_NODES * 1024];    // fp16 A operand (x, then h1, then h2)
__device__ __half g_wt[2048 * 1024];       // fp16 transposed packed weights [N,K]
__device__ float  g_asrc[N_NODES * 4];
__device__ float  g_adst[N_NODES * 4];
__device__ int    g_deg[N_NODES];
__device__ int    g_off[N_NODES + 1];
__device__ int    g_cur[N_NODES];
__device__ int    g_esrc[N_EDGES];         // src node of each edge, grouped by dst

// ---------------- helpers ---------------------------------------------------
__device__ __forceinline__ void mma_f16(float* d, const unsigned* a, const unsigned* b) {
    asm volatile(
        "mma.sync.aligned.m16n8k16.row.col.f32.f16.f16.f32 "
        "{%0,%1,%2,%3}, {%4,%5,%6,%7}, {%8,%9}, {%0,%1,%2,%3};"
        : "+f"(d[0]), "+f"(d[1]), "+f"(d[2]), "+f"(d[3])
        : "r"(a[0]), "r"(a[1]), "r"(a[2]), "r"(a[3]), "r"(b[0]), "r"(b[1]));
}

__device__ __forceinline__ void ldsm4(unsigned& r0, unsigned& r1, unsigned& r2, unsigned& r3,
                                      uint32_t addr) {
    asm volatile("ldmatrix.sync.aligned.m8n8.x4.shared.b16 {%0,%1,%2,%3}, [%4];"
                 : "=r"(r0), "=r"(r1), "=r"(r2), "=r"(r3) : "r"(addr));
}

__device__ __forceinline__ void cp16(void* smem, const void* gmem, bool pred) {
    unsigned sa = (unsigned)__cvta_generic_to_shared(smem);
    int sz = pred ? 16 : 0;
    asm volatile("cp.async.cg.shared.global [%0], [%1], 16, %2;"
                 :: "r"(sa), "l"(gmem), "r"(sz));
}

// ---------------- fp16 conversion passes -------------------------------------
__global__ void cvt_fp16_kernel(const float* __restrict__ in, __half* __restrict__ out, int n) {
    int i = (blockIdx.x * blockDim.x + threadIdx.x) * 8;
    if (i >= n) return;
    float4 v0 = *(const float4*)(in + i);
    float4 v1 = *(const float4*)(in + i + 4);
    __half2 h[4];
    h[0] = __floats2half2_rn(v0.x, v0.y);
    h[1] = __floats2half2_rn(v0.z, v0.w);
    h[2] = __floats2half2_rn(v1.x, v1.y);
    h[3] = __floats2half2_rn(v1.z, v1.w);
    *(uint4*)(out + i) = *(uint4*)h;
}

// weights: W[K,N] fp32 -> out[N,K] fp16 (transposed). K,N multiples of 32.
__global__ void cvt_fp16_transpose_kernel(const float* __restrict__ in, __half* __restrict__ out,
                                          int K, int N) {
    __shared__ float t[32][33];
    int k0 = blockIdx.y * 32, n0 = blockIdx.x * 32;
    int tx = threadIdx.x, ty = threadIdx.y;  // 32 x 8
    #pragma unroll
    for (int j = 0; j < 32; j += 8)
        t[ty + j][tx] = in[(size_t)(k0 + ty + j) * N + n0 + tx];
    __syncthreads();
    #pragma unroll
    for (int j = 0; j < 32; j += 8)
        out[(size_t)(n0 + ty + j) * K + k0 + tx] = __float2half_rn(t[tx][ty + j]);
}

// ---------------- CSR build ---------------------------------------------------
__global__ void zero_deg_kernel(int* __restrict__ deg) {
    int i = blockIdx.x * blockDim.x + threadIdx.x;
    if (i < N_NODES) deg[i] = 0;
}

__global__ void hist_kernel(const int* __restrict__ dst, int* __restrict__ deg) {
    int e = blockIdx.x * blockDim.x + threadIdx.x;
    if (e < N_EDGES) atomicAdd(&deg[dst[e]], 1);
}

__global__ __launch_bounds__(256) void scan_kernel(
    const int* __restrict__ deg, int* __restrict__ off, int* __restrict__ cur)
{
    __shared__ int partial[256];
    const int tid = threadIdx.x;
    const int CH = (N_NODES + 255) / 256;
    const int base = tid * CH;

    int s = 0;
    for (int j = 0; j < CH; j++) {
        int i = base + j;
        if (i < N_NODES) s += deg[i];
    }
    partial[tid] = s;
    __syncthreads();
    for (int o = 1; o < 256; o <<= 1) {
        int v = (tid >= o) ? partial[tid - o] : 0;
        __syncthreads();
        partial[tid] += v;
        __syncthreads();
    }
    int run = partial[tid] - s;
    for (int j = 0; j < CH; j++) {
        int i = base + j;
        if (i < N_NODES) {
            off[i] = run;
            cur[i] = run;
            run += deg[i];
        }
    }
    if (tid == 255) off[N_NODES] = run;
}

__global__ void scatter_kernel(const int* __restrict__ src, const int* __restrict__ dst,
                               int* __restrict__ cur, int* __restrict__ esrc) {
    int e = blockIdx.x * blockDim.x + threadIdx.x;
    if (e >= N_EDGES) return;
    int pos = atomicAdd(&cur[dst[e]], 1);
    esrc[pos] = src[e];
}

// ---------------- fp16 tensor-core GEMM, cp.async 4-stage, single-sync -------
// C_all[M,N] = A[M,K] @ Bt[N,K]^T. Split output: columns [0,Nsplit) go fp32 to
// C (row stride Nsplit, bias biasA); columns [Nsplit,N) go fp16 to C16 (row
// stride N-Nsplit, bias biasB). Nsplit % 128 == 0 so each CTA is in one region.
// CTA tile 128x128, K-tile 32 halves, 8 warps (2x4) 64x32, mma m16n8k16,
// fragment loads via ldmatrix.x4 (conflict-free with 80B row pitch).
// Requires N % 128 == 0, K % 32 == 0; M guarded.
#define GBM 128
#define GBN 128
#define HK 32
#define ROWW 20
#define TSZW (128 * ROWW)
#define STAGES 4
#define GEMM_SMEM (STAGES * 2 * TSZW * 4)

template <int ACT>  // 0: none, 1: leaky_relu(0.01)
__global__ __launch_bounds__(256, 2) void mma_gemm_kernel(
    const __half* __restrict__ A, const __half* __restrict__ Bt,
    const float* __restrict__ biasA, const float* __restrict__ biasB,
    float* __restrict__ C, __half* __restrict__ C16,
    int M, int N, int K, int Nsplit)
{
    extern __shared__ unsigned smem[];
    unsigned* As = smem;
    unsigned* Bs = smem + STAGES * TSZW;

    const int tid = threadIdx.x;
    const int warp = tid >> 5, lane = tid & 31;
    const int g = lane >> 2, tg = lane & 3;
    const int wr = (warp >> 2) * 64;
    const int wc = (warp & 3) * 32;

    const int bm = blockIdx.y, bn = blockIdx.x;

    const int rowS = tid >> 1;
    const int rowA = bm * GBM + rowS;
    const bool avalid = rowA < M;
    const __half* Ap = avalid ? (A + (size_t)rowA * K + (tid & 1) * 16) : A;
    const __half* Bp = Bt + (size_t)(bn * GBN + rowS) * K + (tid & 1) * 16;
    const int sOff = rowS * ROWW + (tid & 1) * 8;

    // ldmatrix per-lane byte offsets within a tile
    //   A (x4, one per mt): lanes 0-15 rows wr+(lane&15) @k-byte 0; lanes 16-31 same rows @+16
    //   B (x4, one per nt-pair): lanes select n-subtile via bit4, k-half via bit3
    const uint32_t sbase = (uint32_t)__cvta_generic_to_shared(smem);
    const uint32_t aLds = (uint32_t)(wr + (lane & 15)) * 80u + ((lane >> 4) & 1) * 16u;
    const uint32_t bLds = (uint32_t)(wc + ((lane >> 4) & 1) * 8 + (lane & 7)) * 80u
                        + ((lane >> 3) & 1) * 16u;

    const int KT = K / HK;

    float acc[4][4][4];
    #pragma unroll
    for (int mt = 0; mt < 4; mt++)
        #pragma unroll
        for (int nt = 0; nt < 4; nt++)
            #pragma unroll
            for (int i = 0; i < 4; i++) acc[mt][nt][i] = 0.0f;

    // prologue: stage tiles 0..2
    #pragma unroll
    for (int kt = 0; kt < STAGES - 1; kt++) {
        if (kt < KT) {
            unsigned* as = As + (kt % STAGES) * TSZW;
            unsigned* bs = Bs + (kt % STAGES) * TSZW;
            const __half* ap = Ap + (avalid ? kt * HK : 0);
            const __half* bp = Bp + kt * HK;
            cp16(&as[sOff],     ap,     avalid);
            cp16(&as[sOff + 4], ap + 8, avalid);
            cp16(&bs[sOff],     bp,     true);
            cp16(&bs[sOff + 4], bp + 8, true);
        }
        asm volatile("cp.async.commit_group;");
    }

    for (int kt = 0; kt < KT; kt++) {
        // tile kt resident
        asm volatile("cp.async.wait_group %0;" :: "n"(STAGES - 2));
        // single barrier: also proves all warps finished reading buffer
        // (kt-1)%STAGES == (kt+3)%STAGES before we overwrite it below
        __syncthreads();

        int kf = kt + STAGES - 1;
        if (kf < KT) {
            unsigned* as = As + (kf % STAGES) * TSZW;
            unsigned* bs = Bs + (kf % STAGES) * TSZW;
            const __half* ap = Ap + (avalid ? kf * HK : 0);
            const __half* bp = Bp + kf * HK;
            cp16(&as[sOff],     ap,     avalid);
            cp16(&as[sOff + 4], ap + 8, avalid);
            cp16(&bs[sOff],     bp,     true);
            cp16(&bs[sOff + 4], bp + 8, true);
        }
        asm volatile("cp.async.commit_group;");

        const uint32_t aBase = sbase + (uint32_t)((kt % STAGES) * TSZW) * 4u + aLds;
        const uint32_t bBase = sbase + (uint32_t)((STAGES + (kt % STAGES)) * TSZW) * 4u + bLds;

        #pragma unroll
        for (int kk = 0; kk < 2; kk++) {
            unsigned af[4][4];
            unsigned bf[4][2];
            #pragma unroll
            for (int mt = 0; mt < 4; mt++)
                ldsm4(af[mt][0], af[mt][1], af[mt][2], af[mt][3],
                      aBase + mt * 1280u + kk * 32u);
            #pragma unroll
            for (int p = 0; p < 2; p++)
                ldsm4(bf[p * 2][0], bf[p * 2][1], bf[p * 2 + 1][0], bf[p * 2 + 1][1],
                      bBase + p * 1280u + kk * 32u);
            #pragma unroll
            for (int mt = 0; mt < 4; mt++)
                #pragma unroll
                for (int nt = 0; nt < 4; nt++)
                    mma_f16(acc[mt][nt], af[mt], bf[nt]);
        }
    }

    // epilogue: whole CTA tile lies in one output region
    const int colBase = bn * GBN;
    const bool rA = colBase < Nsplit;
    const int Wd = rA ? Nsplit : (N - Nsplit);
    const int cb = (rA ? colBase : colBase - Nsplit) + wc;
    const float* bias = rA ? biasA : biasB;

    float bv[4][2];
    #pragma unroll
    for (int nt = 0; nt < 4; nt++) {
        int col = cb + nt * 8 + 2 * tg;
        bv[nt][0] = bias ? bias[col] : 0.0f;
        bv[nt][1] = bias ? bias[col + 1] : 0.0f;
    }

    #pragma unroll
    for (int mt = 0; mt < 4; mt++) {
        #pragma unroll
        for (int i = 0; i < 2; i++) {
            int row = bm * GBM + wr + mt * 16 + g + i * 8;
            if (row >= M) continue;
            size_t rb = (size_t)row * Wd + cb;
            #pragma unroll
            for (int nt = 0; nt < 4; nt++) {
                float2 v;
                v.x = acc[mt][nt][i * 2 + 0] + bv[nt][0];
                v.y = acc[mt][nt][i * 2 + 1] + bv[nt][1];
                if (ACT == 1) {
                    v.x = v.x > 0.f ? v.x : 0.01f * v.x;
                    v.y = v.y > 0.f ? v.y : 0.01f * v.y;
                }
                if (rA) *(float2*)(C + rb + nt * 8 + 2 * tg) = v;
                else    *(__half2*)(C16 + rb + nt * 8 + 2 * tg) = __floats2half2_rn(v.x, v.y);
            }
        }
    }
}

// ---------------- attention scores (fp16 xl) ---------------------------------
__global__ __launch_bounds__(256) void attn_scores_kernel(
    const __half* __restrict__ xl,
    const float* __restrict__ att_src, const float* __restrict__ att_dst,
    float* __restrict__ asrc, float* __restrict__ adst)
{
    int task = blockIdx.x * 8 + (threadIdx.x >> 5);
    if (task >= N_NODES * 4) return;
    int lane = threadIdx.x & 31;
    int n = task >> 2, h = task & 3;

    const __half* xp = xl + (size_t)n * 1024 + h * 256 + lane * 8;
    const float* sp = att_src + h * 256 + lane * 8;
    const float* dp = att_dst + h * 256 + lane * 8;

    uint4 raw = *(const uint4*)xp;
    __half2* hh = (__half2*)&raw;
    float2 p0 = __half22float2(hh[0]);
    float2 p1 = __half22float2(hh[1]);
    float2 p2 = __half22float2(hh[2]);
    float2 p3 = __half22float2(hh[3]);
    float4 a0 = *(const float4*)(sp), a1 = *(const float4*)(sp + 4);
    float4 b0 = *(const float4*)(dp), b1 = *(const float4*)(dp + 4);

    float s1 = p0.x*a0.x + p0.y*a0.y + p1.x*a0.z + p1.y*a0.w
             + p2.x*a1.x + p2.y*a1.y + p3.x*a1.z + p3.y*a1.w;
    float s2 = p0.x*b0.x + p0.y*b0.y + p1.x*b0.z + p1.y*b0.w
             + p2.x*b1.x + p2.y*b1.y + p3.x*b1.z + p3.y*b1.w;

    #pragma unroll
    for (int off = 16; off > 0; off >>= 1) {
        s1 += __shfl_xor_sync(0xffffffffu, s1, off);
        s2 += __shfl_xor_sync(0xffffffffu, s2, off);
    }
    if (lane == 0) {
        asrc[task] = s1;
        adst[task] = s2;
    }
}

// ---------------- layer1 aggregation: fp16 gather, fp16 'at' output ----------
__global__ __launch_bounds__(256) void gat_aggregate1_kernel(
    const int* __restrict__ off, const int* __restrict__ esrc,
    const __half* __restrict__ xl, const float* __restrict__ asrc,
    const float* __restrict__ adst, const float* __restrict__ h1,
    __half* __restrict__ out_at)
{
    int task = blockIdx.x * 8 + (threadIdx.x >> 5);
    if (task >= N_NODES * 4) return;
    int lane = threadIdx.x & 31;
    int n = task >> 2, h = task & 3;

    const float ad = adst[n * 4 + h];
    const int j0 = off[n], j1 = off[n + 1];

    float u[8] = {0.f, 0.f, 0.f, 0.f, 0.f, 0.f, 0.f, 0.f};
    float ssum = 0.f;

    for (int j = j0; j < j1; j++) {
        int s = esrc[j];
        float a = asrc[s * 4 + h] + ad;
        a = a > 0.f ? a : 0.2f * a;
        float w = __expf(a);
        ssum += w;
        uint4 raw = *(const uint4*)(xl + (size_t)s * 1024 + h * 256 + lane * 8);
        __half2* hh = (__half2*)&raw;
        float2 p0 = __half22float2(hh[0]);
        float2 p1 = __half22float2(hh[1]);
        float2 p2 = __half22float2(hh[2]);
        float2 p3 = __half22float2(hh[3]);
        u[0] += w * p0.x; u[1] += w * p0.y; u[2] += w * p1.x; u[3] += w * p1.y;
        u[4] += w * p2.x; u[5] += w * p2.y; u[6] += w * p3.x; u[7] += w * p3.y;
    }

    float inv = 1.0f / (ssum + 1e-16f);
    size_t base = (size_t)n * 1024 + h * 256 + lane * 8;
    float4 r0 = *(const float4*)(h1 + base);
    float4 r1 = *(const float4*)(h1 + base + 4);
    __half2 o[4];
    o[0] = __floats2half2_rn(r0.x + u[0] * inv, r0.y + u[1] * inv);
    o[1] = __floats2half2_rn(r0.z + u[2] * inv, r0.w + u[3] * inv);
    o[2] = __floats2half2_rn(r1.x + u[4] * inv, r1.y + u[5] * inv);
    o[3] = __floats2half2_rn(r1.z + u[6] * inv, r1.w + u[7] * inv);
    *(uint4*)(out_at + base) = *(uint4*)o;
}

// ---------------- layer2 aggregation: head-mean, fp16 gather/out -------------
__global__ __launch_bounds__(256) void gat_aggregate2_kernel(
    const int* __restrict__ off, const int* __restrict__ esrc,
    const __half* __restrict__ xl, const float* __restrict__ asrc,
    const float* __restrict__ adst, const float* __restrict__ h2,
    __half* __restrict__ out_at)
{
    int n = blockIdx.x * 8 + (threadIdx.x >> 5);
    if (n >= N_NODES) return;
    int lane = threadIdx.x & 31;

    float4 ad = *(const float4*)(adst + n * 4);
    const int j0 = off[n], j1 = off[n + 1];

    float u[4][8];
    #pragma unroll
    for (int h = 0; h < 4; h++)
        #pragma unroll
        for (int q = 0; q < 8; q++) u[h][q] = 0.f;
    float4 ssum = make_float4(0.f, 0.f, 0.f, 0.f);

    for (int j = j0; j < j1; j++) {
        int s = esrc[j];
        float4 as = *(const float4*)(asrc + s * 4);
        float4 e;
        e.x = as.x + ad.x; e.x = e.x > 0.f ? e.x : 0.2f * e.x;
        e.y = as.y + ad.y; e.y = e.y > 0.f ? e.y : 0.2f * e.y;
        e.z = as.z + ad.z; e.z = e.z > 0.f ? e.z : 0.2f * e.z;
        e.w = as.w + ad.w; e.w = e.w > 0.f ? e.w : 0.2f * e.w;
        float w[4];
        w[0] = __expf(e.x); w[1] = __expf(e.y); w[2] = __expf(e.z); w[3] = __expf(e.w);
        ssum.x += w[0]; ssum.y += w[1]; ssum.z += w[2]; ssum.w += w[3];

        const __half* sp = xl + (size_t)s * 1024 + lane * 8;
        #pragma unroll
        for (int h = 0; h < 4; h++) {
            uint4 raw = *(const uint4*)(sp + h * 256);
            __half2* hh = (__half2*)&raw;
            float2 p0 = __half22float2(hh[0]);
            float2 p1 = __half22float2(hh[1]);
            float2 p2 = __half22float2(hh[2]);
            float2 p3 = __half22float2(hh[3]);
            u[h][0] += w[h] * p0.x; u[h][1] += w[h] * p0.y;
            u[h][2] += w[h] * p1.x; u[h][3] += w[h] * p1.y;
            u[h][4] += w[h] * p2.x; u[h][5] += w[h] * p2.y;
            u[h][6] += w[h] * p3.x; u[h][7] += w[h] * p3.y;
        }
    }

    float i0 = 0.25f / (ssum.x + 1e-16f);
    float i1 = 0.25f / (ssum.y + 1e-16f);
    float i2 = 0.25f / (ssum.z + 1e-16f);
    float i3 = 0.25f / (ssum.w + 1e-16f);

    size_t base = (size_t)n * 256 + lane * 8;
    float4 r0 = *(const float4*)(h2 + base);
    float4 r1 = *(const float4*)(h2 + base + 4);
    float o[8];
    o[0] = r0.x + i0*u[0][0] + i1*u[1][0] + i2*u[2][0] + i3*u[3][0];
    o[1] = r0.y + i0*u[0][1] + i1*u[1][1] + i2*u[2][1] + i3*u[3][1];
    o[2] = r0.z + i0*u[0][2] + i1*u[1][2] + i2*u[2][2] + i3*u[3][2];
    o[3] = r0.w + i0*u[0][3] + i1*u[1][3] + i2*u[2][3] + i3*u[3][3];
    o[4] = r1.x + i0*u[0][4] + i1*u[1][4] + i2*u[2][4] + i3*u[3][4];
    o[5] = r1.y + i0*u[0][5] + i1*u[1][5] + i2*u[2][5] + i3*u[3][5];
    o[6] = r1.z + i0*u[0][6] + i1*u[1][6] + i2*u[2][6] + i3*u[3][6];
    o[7] = r1.w + i0*u[0][7] + i1*u[1][7] + i2*u[2][7] + i3*u[3][7];
    __half2 ho[4];
    ho[0] = __floats2half2_rn(o[0], o[1]);
    ho[1] = __floats2half2_rn(o[2], o[3]);
    ho[2] = __floats2half2_rn(o[4], o[5]);
    ho[3] = __floats2half2_rn(o[6], o[7]);
    *(uint4*)(out_at + base) = *(uint4*)ho;
}

// ---------------- output heads ----------------------------------------------
__global__ __launch_bounds__(256) void heads_kernel(
    const float* __restrict__ fc,
    const float* __restrict__ Wb, const float* __restrict__ bb,
    const float* __restrict__ Ws, const float* __restrict__ bs,
    float* __restrict__ out)
{
    int n = blockIdx.x * 8 + (threadIdx.x >> 5);
    if (n >= N_NODES) return;
    int lane = threadIdx.x & 31;

    float acc[7] = {0.f, 0.f, 0.f, 0.f, 0.f, 0.f, 0.f};
    #pragma unroll
    for (int i = 0; i < 8; i++) {
        int k = i * 32 + lane;
        float v = fc[(size_t)n * 256 + k];
        acc[0] += v * Wb[k * 2 + 0];
        acc[1] += v * Wb[k * 2 + 1];
        #pragma unroll
        for (int j = 0; j < 5; j++) acc[2 + j] += v * Ws[k * 5 + j];
    }
    #pragma unroll
    for (int off = 16; off > 0; off >>= 1) {
        #pragma unroll
        for (int j = 0; j < 7; j++) acc[j] += __shfl_xor_sync(0xffffffffu, acc[j], off);
    }
    if (lane == 0) {
        out[(size_t)n * 2 + 0] = acc[0] + bb[0];
        out[(size_t)n * 2 + 1] = acc[1] + bb[1];
        float* sev = out + (size_t)N_NODES * 2 + (size_t)n * 5;
        #pragma unroll
        for (int j = 0; j < 5; j++) sev[j] = acc[2 + j] + bs[j];
    }
}

// ---------------- launch ------------------------------------------------------
static inline void cvt(const float* in, __half* out, int n) {
    cvt_fp16_kernel<<<(n / 8 + 255) / 256, 256>>>(in, out, n);
}
static inline void cvtT(const float* W, __half* out, int K, int N) {
    dim3 grid(N / 32, K / 32);
    cvt_fp16_transpose_kernel<<<grid, dim3(32, 8)>>>(W, out, K, N);
}

extern "C" void kernel_launch(void* const* d_in, const int* in_sizes, int n_in,
                              void* d_out, int out_size)
{
    const float* x        = (const float*)d_in[0];
    const int*   ei       = (const int*)d_in[1];
    const float* W1       = (const float*)d_in[2];
    const float* att_src1 = (const float*)d_in[3];
    const float* att_dst1 = (const float*)d_in[4];
    const float* Wres1    = (const float*)d_in[5];
    const float* b1       = (const float*)d_in[6];
    const float* W2       = (const float*)d_in[7];
    const float* att_src2 = (const float*)d_in[8];
    const float* att_dst2 = (const float*)d_in[9];
    const float* Wres2    = (const float*)d_in[10];
    const float* b2       = (const float*)d_in[11];
    const float* Wfc      = (const float*)d_in[12];
    const float* bfc      = (const float*)d_in[13];
    const float* Wb       = (const float*)d_in[14];
    const float* bb       = (const float*)d_in[15];
    const float* Ws       = (const float*)d_in[16];
    const float* bs       = (const float*)d_in[17];
    float* out = (float*)d_out;

    const int* src = ei;
    const int* dst = ei + N_EDGES;

    float *h1, *h2, *fc2, *asrc, *adst;
    __half *xl16, *at, *wt, *fc1h;
    int *deg, *off, *cur, *esrc;
    cudaGetSymbolAddress((void**)&xl16, g_xl16);
    cudaGetSymbolAddress((void**)&h1,   g_h1);
    cudaGetSymbolAddress((void**)&h2,   g_h2);
    cudaGetSymbolAddress((void**)&fc1h, g_fc1h);
    cudaGetSymbolAddress((void**)&fc2,  g_fc2);
    cudaGetSymbolAddress((void**)&at,   g_at);
    cudaGetSymbolAddress((void**)&wt,   g_wt);
    cudaGetSymbolAddress((void**)&asrc, g_asrc);
    cudaGetSymbolAddress((void**)&adst, g_adst);
    cudaGetSymbolAddress((void**)&deg,  g_deg);
    cudaGetSymbolAddress((void**)&off,  g_off);
    cudaGetSymbolAddress((void**)&cur,  g_cur);
    cudaGetSymbolAddress((void**)&esrc, g_esrc);

    static bool attr_done = false;
    if (!attr_done) {
        cudaFuncSetAttribute(mma_gemm_kernel<0>,
                             cudaFuncAttributeMaxDynamicSharedMemorySize, GEMM_SMEM);
        cudaFuncSetAttribute(mma_gemm_kernel<1>,
                             cudaFuncAttributeMaxDynamicSharedMemorySize, GEMM_SMEM);
        attr_done = true;
    }

    const int mRows = (N_NODES + GBM - 1) / GBM;
    const int attnBlocks = (N_NODES * 4 + 7) / 8;
    const int nodeBlocks = (N_NODES + 7) / 8;
    const int edgeBlocks = (N_EDGES + 255) / 256;

    // launches 1-3: operand prep (packed weights: [Wres1^T ; W1^T] = [2048, 768])
    cvt(x, at, N_NODES * 768);
    cvtT(Wres1, wt, 768, 1024);
    cvtT(W1, wt + (size_t)1024 * 768, 768, 1024);

    // launch 4 (ncu window): fused layer1 GEMM, N=2048
    //   cols [0,1024)    -> h1 (fp32) + b1
    //   cols [1024,2048) -> xl16 (fp16)
    {
        dim3 grid(2048 / GBN, mRows);
        mma_gemm_kernel<0><<<grid, 256, GEMM_SMEM>>>(at, wt, b1, nullptr, h1, xl16,
                                                     N_NODES, 2048, 768, 1024);
    }

    // CSR build
    zero_deg_kernel<<<(N_NODES + 255) / 256, 256>>>(deg);
    hist_kernel<<<edgeBlocks, 256>>>(dst, deg);
    scan_kernel<<<1, 256>>>(deg, off, cur);
    scatter_kernel<<<edgeBlocks, 256>>>(src, dst, cur, esrc);

    // ===== layer 1 aggregation -> fp16 'at' =====
    attn_scores_kernel<<<attnBlocks, 256>>>(xl16, att_src1, att_dst1, asrc, adst);
    gat_aggregate1_kernel<<<attnBlocks, 256>>>(off, esrc, xl16, asrc, adst, h1, at);

    // ===== fused layer2 GEMM, N=1280: cols [0,256)->h2+b2, [256,1280)->xl16 ===
    cvtT(Wres2, wt, 1024, 256);
    cvtT(W2, wt + (size_t)256 * 1024, 1024, 1024);
    {
        dim3 grid(1280 / GBN, mRows);
        mma_gemm_kernel<0><<<grid, 256, GEMM_SMEM>>>(at, wt, b2, nullptr, h2, xl16,
                                                     N_NODES, 1280, 1024, 256);
    }
    attn_scores_kernel<<<attnBlocks, 256>>>(xl16, att_src2, att_dst2, asrc, adst);
    gat_aggregate2_kernel<<<nodeBlocks, 256>>>(off, esrc, xl16, asrc, adst, h2, at);

    // ===== shared FC twice =====
    cvtT(Wfc, wt, 256, 256);
    {
        dim3 grid(256 / GBN, mRows);
        // fc1: all columns fp16 out with bias+leaky (region B, Nsplit=0)
        mma_gemm_kernel<1><<<grid, 256, GEMM_SMEM>>>(at, wt, nullptr, bfc, nullptr, fc1h,
                                                     N_NODES, 256, 256, 0);
        // fc2: all columns fp32 out with bias (region A, Nsplit=256)
        mma_gemm_kernel<0><<<grid, 256, GEMM_SMEM>>>(fc1h, wt, bfc, nullptr, fc2, nullptr,
                                                     N_NODES, 256, 256, 256);
    }

    // ===== heads =====
    heads_kernel<<<nodeBlocks, 256>>>(fc2, Wb, bb, Ws, bs, out);
}